// round 5
// baseline (speedup 1.0000x reference)
#include <cuda_runtime.h>
#include <math.h>

// Problem constants
#define B_   2
#define S_   2048
#define D_   2048
#define H_   16
#define KV_  4
#define KQD_ 96
#define VD_  128
#define TOK  (B_*S_)       // 4096
#define QN   (H_*KQD_)     // 1536
#define KN   (KV_*KQD_)    // 384
#define VN   (KV_*VD_)     // 512
#define ON   (H_*VD_)      // 2048

__device__ float g_q [TOK * QN];
__device__ float g_k [TOK * KN];
__device__ float g_v [TOK * VN];
__device__ float g_ao[TOK * ON];
__device__ float g_cos[S_ * 48];
__device__ float g_sin[S_ * 48];
__device__ double g_invf[48];

// ---------------------------------------------------------------------------
// inv_freq in double, 48 threads total (fp64 cost negligible)
// ---------------------------------------------------------------------------
__global__ void invf_kernel() {
    int j = threadIdx.x;
    if (j < 48) g_invf[j] = pow(10000.0, -(double)j / 48.0);
}

// RoPE table: pure fp32 float-pair pipeline (no fp64 trig).
// angle = pos*inv computed with exact fma residual; two-term 2pi reduction.
__global__ void rope_table_kernel() {
    int i = blockIdx.x * blockDim.x + threadIdx.x;
    if (i >= S_ * 48) return;
    int pos = i / 48, j = i % 48;
    double d = g_invf[j];
    float hi = (float)d;
    float lo = (float)(d - (double)hi);
    float fp = (float)pos;
    float p  = fp * hi;
    float e  = fmaf(fp, hi, -p);            // exact product residual
    float t2 = fmaf(fp, lo, e);             // small correction term
    const float INV2PI = 0.15915494309189535f;
    const float PIH    = 6.2831854820251465f;       // float(2pi), rounded
    const float PIL    = -1.7484555314695172e-7f;   // 2pi - PIH
    float n = rintf(p * INV2PI);
    float r = fmaf(-n, PIH, p);
    r = fmaf(-n, PIL, r);
    r = r + t2;                             // |r| <= pi + eps, err ~6e-7
    float s, c;
    sincosf(r, &s, &c);
    g_cos[i] = c;
    g_sin[i] = s;
}

// ---------------------------------------------------------------------------
__device__ __forceinline__ unsigned f2tf32(float x) {
    unsigned r;
    asm("cvt.rna.tf32.f32 %0, %1;" : "=r"(r) : "f"(x));
    return r;
}
__device__ __forceinline__ void mma_tf32(float* c, const unsigned* a, const unsigned* b) {
    asm volatile(
        "mma.sync.aligned.m16n8k8.row.col.f32.tf32.tf32.f32 "
        "{%0,%1,%2,%3}, {%4,%5,%6,%7}, {%8,%9}, {%0,%1,%2,%3};\n"
        : "+f"(c[0]), "+f"(c[1]), "+f"(c[2]), "+f"(c[3])
        : "r"(a[0]), "r"(a[1]), "r"(a[2]), "r"(a[3]),
          "r"(b[0]), "r"(b[1]));
}
__device__ __forceinline__ void cp_async16(unsigned saddr, const void* g) {
    asm volatile("cp.async.cg.shared.global [%0], [%1], 16;\n" :: "r"(saddr), "l"(g));
}
#define CP_COMMIT() asm volatile("cp.async.commit_group;\n" ::: "memory")
#define CP_WAIT1()  asm volatile("cp.async.wait_group 1;\n" ::: "memory")

// ---------------------------------------------------------------------------
// TF32 GEMM-NT core (128x128 tile, BK=16, double-buffered).
// ---------------------------------------------------------------------------
#define BKT 16
#define SSTR 136

template<bool RND>
__device__ __forceinline__ void gemm_body(
    const float* __restrict__ A, const float* __restrict__ Bm,
    float* __restrict__ C, int N, int K, int bm, int bn,
    unsigned (*As)[BKT][SSTR], unsigned (*Bs)[BKT][SSTR])
{
    const int tid  = threadIdx.x;
    const int warp = tid >> 5;
    const int lane = tid & 31;
    const int g    = lane >> 2;
    const int t    = lane & 3;
    const int wm   = (warp >> 2) * 64;
    const int wn   = (warp & 3) * 32;

    const int lrow = tid >> 1;
    const int lkc  = (tid & 1) * 8;
    const float* Ap = A  + (size_t)(bm + lrow) * K + lkc;
    const float* Bp = Bm + (size_t)(bn + lrow) * K + lkc;

    float acc[4][4][4];
#pragma unroll
    for (int i = 0; i < 4; i++)
#pragma unroll
        for (int j = 0; j < 4; j++)
#pragma unroll
            for (int r = 0; r < 4; r++) acc[i][j][r] = 0.f;

    float4 pa0 = *(const float4*)(Ap + 0);
    float4 pa1 = *(const float4*)(Ap + 4);
    float4 pb0 = *(const float4*)(Bp + 0);
    float4 pb1 = *(const float4*)(Bp + 4);
    {
        As[0][lkc+0][lrow] = f2tf32(pa0.x); As[0][lkc+1][lrow] = f2tf32(pa0.y);
        As[0][lkc+2][lrow] = f2tf32(pa0.z); As[0][lkc+3][lrow] = f2tf32(pa0.w);
        As[0][lkc+4][lrow] = f2tf32(pa1.x); As[0][lkc+5][lrow] = f2tf32(pa1.y);
        As[0][lkc+6][lrow] = f2tf32(pa1.z); As[0][lkc+7][lrow] = f2tf32(pa1.w);
        Bs[0][lkc+0][lrow] = f2tf32(pb0.x); Bs[0][lkc+1][lrow] = f2tf32(pb0.y);
        Bs[0][lkc+2][lrow] = f2tf32(pb0.z); Bs[0][lkc+3][lrow] = f2tf32(pb0.w);
        Bs[0][lkc+4][lrow] = f2tf32(pb1.x); Bs[0][lkc+5][lrow] = f2tf32(pb1.y);
        Bs[0][lkc+6][lrow] = f2tf32(pb1.z); Bs[0][lkc+7][lrow] = f2tf32(pb1.w);
    }
    __syncthreads();

    int cur = 0;
    for (int k0 = BKT; k0 <= K; k0 += BKT) {
        const bool more = (k0 < K);
        if (more) {
            pa0 = *(const float4*)(Ap + k0);
            pa1 = *(const float4*)(Ap + k0 + 4);
            pb0 = *(const float4*)(Bp + k0);
            pb1 = *(const float4*)(Bp + k0 + 4);
        }
#pragma unroll
        for (int kh = 0; kh < 2; kh++) {
            const int k8 = kh * 8;
            unsigned af[4][4], bf[4][2];
#pragma unroll
            for (int i = 0; i < 4; i++) {
                int m = wm + 16 * i;
                af[i][0] = As[cur][k8 + t    ][m + g];
                af[i][1] = As[cur][k8 + t    ][m + g + 8];
                af[i][2] = As[cur][k8 + t + 4][m + g];
                af[i][3] = As[cur][k8 + t + 4][m + g + 8];
            }
#pragma unroll
            for (int j = 0; j < 4; j++) {
                int n = wn + 8 * j;
                bf[j][0] = Bs[cur][k8 + t    ][n + g];
                bf[j][1] = Bs[cur][k8 + t + 4][n + g];
            }
#pragma unroll
            for (int i = 0; i < 4; i++)
#pragma unroll
                for (int j = 0; j < 4; j++)
                    mma_tf32(acc[i][j], af[i], bf[j]);
        }
        if (more) {
            int nxt = cur ^ 1;
            As[nxt][lkc+0][lrow] = f2tf32(pa0.x); As[nxt][lkc+1][lrow] = f2tf32(pa0.y);
            As[nxt][lkc+2][lrow] = f2tf32(pa0.z); As[nxt][lkc+3][lrow] = f2tf32(pa0.w);
            As[nxt][lkc+4][lrow] = f2tf32(pa1.x); As[nxt][lkc+5][lrow] = f2tf32(pa1.y);
            As[nxt][lkc+6][lrow] = f2tf32(pa1.z); As[nxt][lkc+7][lrow] = f2tf32(pa1.w);
            Bs[nxt][lkc+0][lrow] = f2tf32(pb0.x); Bs[nxt][lkc+1][lrow] = f2tf32(pb0.y);
            Bs[nxt][lkc+2][lrow] = f2tf32(pb0.z); Bs[nxt][lkc+3][lrow] = f2tf32(pb0.w);
            Bs[nxt][lkc+4][lrow] = f2tf32(pb1.x); Bs[nxt][lkc+5][lrow] = f2tf32(pb1.y);
            Bs[nxt][lkc+6][lrow] = f2tf32(pb1.z); Bs[nxt][lkc+7][lrow] = f2tf32(pb1.w);
        }
        __syncthreads();
        cur ^= 1;
    }

#pragma unroll
    for (int i = 0; i < 4; i++) {
#pragma unroll
        for (int j = 0; j < 4; j++) {
            size_t r0 = (size_t)(bm + wm + 16 * i + g);
            size_t col = (size_t)(bn + wn + 8 * j + 2 * t);
            float v0 = acc[i][j][0], v1 = acc[i][j][1];
            float v2 = acc[i][j][2], v3 = acc[i][j][3];
            if (RND) {
                v0 = __uint_as_float(f2tf32(v0)); v1 = __uint_as_float(f2tf32(v1));
                v2 = __uint_as_float(f2tf32(v2)); v3 = __uint_as_float(f2tf32(v3));
            }
            *(float2*)&C[r0 * N + col]       = make_float2(v0, v1);
            *(float2*)&C[(r0 + 8) * N + col] = make_float2(v2, v3);
        }
    }
}

// O projection
__global__ void __launch_bounds__(256, 2) sgemm_tf32(
    const float* __restrict__ A, const float* __restrict__ Bm,
    float* __restrict__ C, int M, int N, int K)
{
    __shared__ unsigned As[2][BKT][SSTR];
    __shared__ unsigned Bs[2][BKT][SSTR];
    gemm_body<false>(A, Bm, C, N, K, blockIdx.y << 7, blockIdx.x << 7, As, Bs);
}

// Fused QKV projection, compact grid: x in [0,19): 12 Q | 3 K | 4 V
__global__ void __launch_bounds__(256, 2) sgemm_qkv(
    const float* __restrict__ A,
    const float* __restrict__ Wq, const float* __restrict__ Wk,
    const float* __restrict__ Wv,
    float* __restrict__ qb, float* __restrict__ kb, float* __restrict__ vb)
{
    __shared__ unsigned As[2][BKT][SSTR];
    __shared__ unsigned Bs[2][BKT][SSTR];
    const int bx = blockIdx.x;
    const int bm = blockIdx.y << 7;
    if (bx < 12) {
        gemm_body<false>(A, Wq, qb, QN, D_, bm, bx << 7, As, Bs);
    } else if (bx < 15) {
        gemm_body<false>(A, Wk, kb, KN, D_, bm, (bx - 12) << 7, As, Bs);
    } else {
        gemm_body<true>(A, Wv, vb, VN, D_, bm, (bx - 15) << 7, As, Bs);
    }
}

// ---------------------------------------------------------------------------
// Fused RMSNorm+RoPE over Q rows then K rows. K output rounded to tf32 bits.
// ---------------------------------------------------------------------------
#define QROWS (TOK * H_)
#define KROWS (TOK * KV_)

__global__ void rmsnorm_rope_fused(float* qb, float* kb,
                                   const float* __restrict__ qw,
                                   const float* __restrict__ kw,
                                   const int* __restrict__ pos_ids)
{
    __shared__ float sh[4][96];
    const int wid  = threadIdx.x >> 5;
    const int lane = threadIdx.x & 31;
    const int row  = blockIdx.x * 4 + wid;
    if (row >= QROWS + KROWS) return;

    const bool isK = (row >= QROWS);
    const int  r   = isK ? row - QROWS : row;
    const int  token = isK ? (r / KV_) : (r / H_);
    float* x = (isK ? kb : qb) + (size_t)r * 96;
    const float* w = isK ? kw : qw;

    float v0 = x[lane], v1 = x[lane + 32], v2 = x[lane + 64];
    float ss = v0 * v0 + v1 * v1 + v2 * v2;
#pragma unroll
    for (int o = 16; o; o >>= 1) ss += __shfl_xor_sync(0xffffffffu, ss, o);
    float inv = rsqrtf(ss * (1.0f / 96.0f) + 1e-6f);

    sh[wid][lane]      = v0 * inv * w[lane];
    sh[wid][lane + 32] = v1 * inv * w[lane + 32];
    sh[wid][lane + 64] = v2 * inv * w[lane + 64];
    __syncwarp();

    const int pos = pos_ids[token];
    const float* ct = g_cos + pos * 48;
    const float* st = g_sin + pos * 48;
#pragma unroll
    for (int q3 = 0; q3 < 3; q3++) {
        int d = lane + q3 * 32;
        int f = (d < 48) ? d : d - 48;
        float rh = (d < 48) ? -sh[wid][d + 48] : sh[wid][d - 48];
        float val = sh[wid][d] * ct[f] + rh * st[f];
        x[d] = isK ? __uint_as_float(f2tf32(val)) : val;
    }
}

// ---------------------------------------------------------------------------
// Tensor-core flash attention (tf32 MMA, pipelined via cp.async).
// CTA = (128-q tile, head, batch), 256 thr / 8 warps. qt reversed (heavy 1st).
// ---------------------------------------------------------------------------
#define QT128 128
#define KT64  64
#define QSTR 100
#define VSTR 136
#define PSTR 68
#define SM_QS   0
#define SM_KF   (128*QSTR)
#define SM_VF   (SM_KF + 2*64*QSTR)
#define SM_PS   (SM_VF + 2*64*VSTR)
#define ATTN_WORDS (SM_PS + 8*16*PSTR)

extern __shared__ unsigned ds_attn[];

__global__ void __launch_bounds__(256) attn_tc_kernel()
{
    const int qt  = (int)gridDim.x - 1 - (int)blockIdx.x;  // heavy CTAs first
    const int h   = blockIdx.y;
    const int b   = blockIdx.z;
    const int kvh = h >> 2;
    const int tid = threadIdx.x;
    const int w   = tid >> 5;
    const int lane = tid & 31;
    const int g   = lane >> 2;
    const int t   = lane & 3;
    const int wm  = w * 16;

    unsigned* Qs  = ds_attn + SM_QS;
    unsigned* Psw = ds_attn + SM_PS + w * 16 * PSTR;
    unsigned kf_s[2], vf_s[2];
    kf_s[0] = (unsigned)__cvta_generic_to_shared(ds_attn + SM_KF);
    kf_s[1] = kf_s[0] + 64 * QSTR * 4;
    vf_s[0] = (unsigned)__cvta_generic_to_shared(ds_attn + SM_VF);
    vf_s[1] = vf_s[0] + 64 * VSTR * 4;
    unsigned* Kf[2] = { ds_attn + SM_KF, ds_attn + SM_KF + 64 * QSTR };
    unsigned* Vf[2] = { ds_attn + SM_VF, ds_attn + SM_VF + 64 * VSTR };

    const float scale = 1.0f / sqrtf(96.0f);
    const float* kb0 = g_k + (size_t)(b * S_) * KN + kvh * KQD_;
    const float* vb0 = g_v + (size_t)(b * S_) * VN + kvh * VD_;

    const float* qbase = g_q + ((size_t)(b * S_ + qt * QT128)) * QN + h * KQD_;
    for (int it = tid; it < 128 * 24; it += 256) {
        int r = it / 24, c4 = (it % 24) * 4;
        float4 v = *(const float4*)(qbase + (size_t)r * QN + c4);
        uint4 u = make_uint4(f2tf32(v.x * scale), f2tf32(v.y * scale),
                             f2tf32(v.z * scale), f2tf32(v.w * scale));
        *(uint4*)&Qs[r * QSTR + c4] = u;
    }

    {
        const float* kbase = kb0;
        for (int it = tid; it < 64 * 24; it += 256) {
            int r = it / 24, c4 = (it % 24) * 4;
            cp_async16(kf_s[0] + (r * QSTR + c4) * 4, kbase + (size_t)r * KN + c4);
        }
        const float* vbase = vb0;
        for (int it = tid; it < 64 * 32; it += 256) {
            int r = it >> 5, c4 = (it & 31) * 4;
            cp_async16(vf_s[0] + (r * VSTR + c4) * 4, vbase + (size_t)r * VN + c4);
        }
        CP_COMMIT();
    }

    float o[16][4];
#pragma unroll
    for (int j = 0; j < 16; j++)
#pragma unroll
        for (int r = 0; r < 4; r++) o[j][r] = 0.f;
    float m0 = -INFINITY, m1 = -INFINITY, l0 = 0.f, l1 = 0.f;

    const int row0g = qt * QT128 + wm + g;
    const int row1g = row0g + 8;
    const int kt_max = 2 * qt + 1;

    for (int kt = 0; kt <= kt_max; kt++) {
        const int cur = kt & 1;
        if (kt < kt_max) {
            const int nb = (kt + 1) & 1;
            const float* kbase = kb0 + (size_t)(kt + 1) * KT64 * KN;
            for (int it = tid; it < 64 * 24; it += 256) {
                int r = it / 24, c4 = (it % 24) * 4;
                cp_async16(kf_s[nb] + (r * QSTR + c4) * 4, kbase + (size_t)r * KN + c4);
            }
            const float* vbase = vb0 + (size_t)(kt + 1) * KT64 * VN;
            for (int it = tid; it < 64 * 32; it += 256) {
                int r = it >> 5, c4 = (it & 31) * 4;
                cp_async16(vf_s[nb] + (r * VSTR + c4) * 4, vbase + (size_t)r * VN + c4);
            }
        }
        CP_COMMIT();
        CP_WAIT1();
        __syncthreads();

        if (KT64 * kt <= qt * QT128 + wm + 15) {
            const unsigned* Kc = Kf[cur];
            const unsigned* Vc = Vf[cur];

            float s[8][4];
#pragma unroll
            for (int j = 0; j < 8; j++)
#pragma unroll
                for (int r = 0; r < 4; r++) s[j][r] = 0.f;
#pragma unroll
            for (int k8 = 0; k8 < 96; k8 += 8) {
                unsigned af[4];
                af[0] = Qs[(wm + g    ) * QSTR + k8 + t    ];
                af[1] = Qs[(wm + g + 8) * QSTR + k8 + t    ];
                af[2] = Qs[(wm + g    ) * QSTR + k8 + t + 4];
                af[3] = Qs[(wm + g + 8) * QSTR + k8 + t + 4];
#pragma unroll
                for (int j = 0; j < 8; j++) {
                    unsigned bf[2];
                    bf[0] = Kc[(8 * j + g) * QSTR + k8 + t    ];
                    bf[1] = Kc[(8 * j + g) * QSTR + k8 + t + 4];
                    mma_tf32(s[j], af, bf);
                }
            }

            if (kt >= 2 * qt) {
#pragma unroll
                for (int j = 0; j < 8; j++) {
                    int c0 = kt * KT64 + 8 * j + 2 * t;
                    if (c0     > row0g) s[j][0] = -INFINITY;
                    if (c0 + 1 > row0g) s[j][1] = -INFINITY;
                    if (c0     > row1g) s[j][2] = -INFINITY;
                    if (c0 + 1 > row1g) s[j][3] = -INFINITY;
                }
            }

            float ml0 = -INFINITY, ml1 = -INFINITY;
#pragma unroll
            for (int j = 0; j < 8; j++) {
                ml0 = fmaxf(ml0, fmaxf(s[j][0], s[j][1]));
                ml1 = fmaxf(ml1, fmaxf(s[j][2], s[j][3]));
            }
            ml0 = fmaxf(ml0, __shfl_xor_sync(0xffffffffu, ml0, 1));
            ml0 = fmaxf(ml0, __shfl_xor_sync(0xffffffffu, ml0, 2));
            ml1 = fmaxf(ml1, __shfl_xor_sync(0xffffffffu, ml1, 1));
            ml1 = fmaxf(ml1, __shfl_xor_sync(0xffffffffu, ml1, 2));
            float mn0 = fmaxf(m0, ml0), mn1 = fmaxf(m1, ml1);
            float al0 = __expf(m0 - mn0), al1 = __expf(m1 - mn1);
            m0 = mn0; m1 = mn1;
            float sum0 = 0.f, sum1 = 0.f;
#pragma unroll
            for (int j = 0; j < 8; j++) {
                s[j][0] = __expf(s[j][0] - mn0); sum0 += s[j][0];
                s[j][1] = __expf(s[j][1] - mn0); sum0 += s[j][1];
                s[j][2] = __expf(s[j][2] - mn1); sum1 += s[j][2];
                s[j][3] = __expf(s[j][3] - mn1); sum1 += s[j][3];
            }
            sum0 += __shfl_xor_sync(0xffffffffu, sum0, 1);
            sum0 += __shfl_xor_sync(0xffffffffu, sum0, 2);
            sum1 += __shfl_xor_sync(0xffffffffu, sum1, 1);
            sum1 += __shfl_xor_sync(0xffffffffu, sum1, 2);
            l0 = l0 * al0 + sum0;
            l1 = l1 * al1 + sum1;
#pragma unroll
            for (int j = 0; j < 16; j++) {
                o[j][0] *= al0; o[j][1] *= al0;
                o[j][2] *= al1; o[j][3] *= al1;
            }

#pragma unroll
            for (int j = 0; j < 8; j++) {
                *(uint2*)&Psw[g * PSTR + 8 * j + 2 * t] =
                    make_uint2(f2tf32(s[j][0]), f2tf32(s[j][1]));
                *(uint2*)&Psw[(g + 8) * PSTR + 8 * j + 2 * t] =
                    make_uint2(f2tf32(s[j][2]), f2tf32(s[j][3]));
            }
            __syncwarp();

#pragma unroll
            for (int k8 = 0; k8 < 64; k8 += 8) {
                unsigned af[4];
                af[0] = Psw[(g    ) * PSTR + k8 + t    ];
                af[1] = Psw[(g + 8) * PSTR + k8 + t    ];
                af[2] = Psw[(g    ) * PSTR + k8 + t + 4];
                af[3] = Psw[(g + 8) * PSTR + k8 + t + 4];
#pragma unroll
                for (int jn = 0; jn < 16; jn++) {
                    unsigned bf[2];
                    bf[0] = Vc[(k8 + t    ) * VSTR + 8 * jn + g];
                    bf[1] = Vc[(k8 + t + 4) * VSTR + 8 * jn + g];
                    mma_tf32(o[jn], af, bf);
                }
            }
        }
        __syncthreads();
    }

    float inv0 = 1.0f / l0, inv1 = 1.0f / l1;
    float* ob = g_ao + ((size_t)(b * S_)) * ON + h * VD_;
    size_t r0 = (size_t)(qt * QT128 + wm + g);
    size_t r1 = r0 + 8;
#pragma unroll
    for (int jn = 0; jn < 16; jn++) {
        int col = 8 * jn + 2 * t;
        *(float2*)&ob[r0 * ON + col] = make_float2(o[jn][0] * inv0, o[jn][1] * inv0);
        *(float2*)&ob[r1 * ON + col] = make_float2(o[jn][2] * inv1, o[jn][3] * inv1);
    }
}

// ---------------------------------------------------------------------------
extern "C" void kernel_launch(void* const* d_in, const int* in_sizes, int n_in,
                              void* d_out, int out_size)
{
    const float* hidden = (const float*)d_in[0];
    const int*   pos    = (const int*)  d_in[1];
    const float* Wq     = (const float*)d_in[2];
    const float* Wk     = (const float*)d_in[3];
    const float* Wv     = (const float*)d_in[4];
    const float* Wo     = (const float*)d_in[5];
    const float* qw     = (const float*)d_in[6];
    const float* kw     = (const float*)d_in[7];
    float* out = (float*)d_out;

    void *pq, *pk, *pv, *pa;
    cudaGetSymbolAddress(&pq, g_q);
    cudaGetSymbolAddress(&pk, g_k);
    cudaGetSymbolAddress(&pv, g_v);
    cudaGetSymbolAddress(&pa, g_ao);
    float* qb = (float*)pq;
    float* kb = (float*)pk;
    float* vb = (float*)pv;
    float* ab = (float*)pa;

    static int smem_set = 0;
    if (!smem_set) {
        cudaFuncSetAttribute(attn_tc_kernel,
                             cudaFuncAttributeMaxDynamicSharedMemorySize,
                             ATTN_WORDS * 4);
        smem_set = 1;
    }

    // 1. inv_freq (tiny fp64) + RoPE table (pure fp32)
    invf_kernel<<<1, 64>>>();
    rope_table_kernel<<<(S_ * 48 + 255) / 256, 256>>>();

    // 2. Fused QKV projection, compact 19-wide grid
    sgemm_qkv<<<dim3(19, TOK / 128), 256>>>(hidden, Wq, Wk, Wv, qb, kb, vb);

    // 3. Fused RMSNorm + RoPE
    rmsnorm_rope_fused<<<(QROWS + KROWS) / 4, 128>>>(qb, kb, qw, kw, pos);

    // 4. Tensor-core flash attention (heavy-first scheduling)
    attn_tc_kernel<<<dim3(S_ / QT128, H_, B_), 256, ATTN_WORDS * 4>>>();

    // 5. Output projection
    sgemm_tf32<<<dim3(D_ / 128, TOK / 128), 256>>>(ab, Wo, out, TOK, D_, ON);
}

// round 6
// speedup vs baseline: 1.5418x; 1.5418x over previous
#include <cuda_runtime.h>
#include <math.h>

// Problem constants
#define B_   2
#define S_   2048
#define D_   2048
#define H_   16
#define KV_  4
#define KQD_ 96
#define VD_  128
#define TOK  (B_*S_)       // 4096
#define QN   (H_*KQD_)     // 1536
#define KN   (KV_*KQD_)    // 384
#define VN   (KV_*VD_)     // 512
#define ON   (H_*VD_)      // 2048

__device__ float g_q [TOK * QN];
__device__ float g_k [TOK * KN];
__device__ float g_v [TOK * VN];
__device__ float g_ao[TOK * ON];
__device__ float g_cos[S_ * 48];
__device__ float g_sin[S_ * 48];
__device__ double g_invf[48];

// ---------------------------------------------------------------------------
// inv_freq in double, 48 threads total (fp64 cost negligible)
// ---------------------------------------------------------------------------
__global__ void invf_kernel() {
    int j = threadIdx.x;
    if (j < 48) g_invf[j] = pow(10000.0, -(double)j / 48.0);
}

// RoPE table: pure fp32 float-pair pipeline (no fp64 trig).
__global__ void rope_table_kernel() {
    int i = blockIdx.x * blockDim.x + threadIdx.x;
    if (i >= S_ * 48) return;
    int pos = i / 48, j = i % 48;
    double d = g_invf[j];
    float hi = (float)d;
    float lo = (float)(d - (double)hi);
    float fp = (float)pos;
    float p  = fp * hi;
    float e  = fmaf(fp, hi, -p);            // exact product residual
    float t2 = fmaf(fp, lo, e);             // small correction term
    const float INV2PI = 0.15915494309189535f;
    const float PIH    = 6.2831854820251465f;
    const float PIL    = -1.7484555314695172e-7f;
    float n = rintf(p * INV2PI);
    float r = fmaf(-n, PIH, p);
    r = fmaf(-n, PIL, r);
    r = r + t2;
    float s, c;
    sincosf(r, &s, &c);
    g_cos[i] = c;
    g_sin[i] = s;
}

// ---------------------------------------------------------------------------
__device__ __forceinline__ unsigned f2tf32(float x) {
    unsigned r;
    asm("cvt.rna.tf32.f32 %0, %1;" : "=r"(r) : "f"(x));
    return r;
}
__device__ __forceinline__ void mma_tf32(float* c, const unsigned* a, const unsigned* b) {
    asm volatile(
        "mma.sync.aligned.m16n8k8.row.col.f32.tf32.tf32.f32 "
        "{%0,%1,%2,%3}, {%4,%5,%6,%7}, {%8,%9}, {%0,%1,%2,%3};\n"
        : "+f"(c[0]), "+f"(c[1]), "+f"(c[2]), "+f"(c[3])
        : "r"(a[0]), "r"(a[1]), "r"(a[2]), "r"(a[3]),
          "r"(b[0]), "r"(b[1]));
}
__device__ __forceinline__ void cp_async16(unsigned saddr, const void* g) {
    asm volatile("cp.async.cg.shared.global [%0], [%1], 16;\n" :: "r"(saddr), "l"(g));
}
#define CP_COMMIT() asm volatile("cp.async.commit_group;\n" ::: "memory")
#define CP_WAIT1()  asm volatile("cp.async.wait_group 1;\n" ::: "memory")

// ---------------------------------------------------------------------------
// TF32 GEMM-NT core (128x128 tile, BK=16, double-buffered).
// ---------------------------------------------------------------------------
#define BKT 16
#define SSTR 136

template<bool RND>
__device__ __forceinline__ void gemm_body(
    const float* __restrict__ A, const float* __restrict__ Bm,
    float* __restrict__ C, int N, int K, int bm, int bn,
    unsigned (*As)[BKT][SSTR], unsigned (*Bs)[BKT][SSTR])
{
    const int tid  = threadIdx.x;
    const int warp = tid >> 5;
    const int lane = tid & 31;
    const int g    = lane >> 2;
    const int t    = lane & 3;
    const int wm   = (warp >> 2) * 64;
    const int wn   = (warp & 3) * 32;

    const int lrow = tid >> 1;
    const int lkc  = (tid & 1) * 8;
    const float* Ap = A  + (size_t)(bm + lrow) * K + lkc;
    const float* Bp = Bm + (size_t)(bn + lrow) * K + lkc;

    float acc[4][4][4];
#pragma unroll
    for (int i = 0; i < 4; i++)
#pragma unroll
        for (int j = 0; j < 4; j++)
#pragma unroll
            for (int r = 0; r < 4; r++) acc[i][j][r] = 0.f;

    float4 pa0 = *(const float4*)(Ap + 0);
    float4 pa1 = *(const float4*)(Ap + 4);
    float4 pb0 = *(const float4*)(Bp + 0);
    float4 pb1 = *(const float4*)(Bp + 4);
    {
        As[0][lkc+0][lrow] = f2tf32(pa0.x); As[0][lkc+1][lrow] = f2tf32(pa0.y);
        As[0][lkc+2][lrow] = f2tf32(pa0.z); As[0][lkc+3][lrow] = f2tf32(pa0.w);
        As[0][lkc+4][lrow] = f2tf32(pa1.x); As[0][lkc+5][lrow] = f2tf32(pa1.y);
        As[0][lkc+6][lrow] = f2tf32(pa1.z); As[0][lkc+7][lrow] = f2tf32(pa1.w);
        Bs[0][lkc+0][lrow] = f2tf32(pb0.x); Bs[0][lkc+1][lrow] = f2tf32(pb0.y);
        Bs[0][lkc+2][lrow] = f2tf32(pb0.z); Bs[0][lkc+3][lrow] = f2tf32(pb0.w);
        Bs[0][lkc+4][lrow] = f2tf32(pb1.x); Bs[0][lkc+5][lrow] = f2tf32(pb1.y);
        Bs[0][lkc+6][lrow] = f2tf32(pb1.z); Bs[0][lkc+7][lrow] = f2tf32(pb1.w);
    }
    __syncthreads();

    int cur = 0;
    for (int k0 = BKT; k0 <= K; k0 += BKT) {
        const bool more = (k0 < K);
        if (more) {
            pa0 = *(const float4*)(Ap + k0);
            pa1 = *(const float4*)(Ap + k0 + 4);
            pb0 = *(const float4*)(Bp + k0);
            pb1 = *(const float4*)(Bp + k0 + 4);
        }
#pragma unroll
        for (int kh = 0; kh < 2; kh++) {
            const int k8 = kh * 8;
            unsigned af[4][4], bf[4][2];
#pragma unroll
            for (int i = 0; i < 4; i++) {
                int m = wm + 16 * i;
                af[i][0] = As[cur][k8 + t    ][m + g];
                af[i][1] = As[cur][k8 + t    ][m + g + 8];
                af[i][2] = As[cur][k8 + t + 4][m + g];
                af[i][3] = As[cur][k8 + t + 4][m + g + 8];
            }
#pragma unroll
            for (int j = 0; j < 4; j++) {
                int n = wn + 8 * j;
                bf[j][0] = Bs[cur][k8 + t    ][n + g];
                bf[j][1] = Bs[cur][k8 + t + 4][n + g];
            }
#pragma unroll
            for (int i = 0; i < 4; i++)
#pragma unroll
                for (int j = 0; j < 4; j++)
                    mma_tf32(acc[i][j], af[i], bf[j]);
        }
        if (more) {
            int nxt = cur ^ 1;
            As[nxt][lkc+0][lrow] = f2tf32(pa0.x); As[nxt][lkc+1][lrow] = f2tf32(pa0.y);
            As[nxt][lkc+2][lrow] = f2tf32(pa0.z); As[nxt][lkc+3][lrow] = f2tf32(pa0.w);
            As[nxt][lkc+4][lrow] = f2tf32(pa1.x); As[nxt][lkc+5][lrow] = f2tf32(pa1.y);
            As[nxt][lkc+6][lrow] = f2tf32(pa1.z); As[nxt][lkc+7][lrow] = f2tf32(pa1.w);
            Bs[nxt][lkc+0][lrow] = f2tf32(pb0.x); Bs[nxt][lkc+1][lrow] = f2tf32(pb0.y);
            Bs[nxt][lkc+2][lrow] = f2tf32(pb0.z); Bs[nxt][lkc+3][lrow] = f2tf32(pb0.w);
            Bs[nxt][lkc+4][lrow] = f2tf32(pb1.x); Bs[nxt][lkc+5][lrow] = f2tf32(pb1.y);
            Bs[nxt][lkc+6][lrow] = f2tf32(pb1.z); Bs[nxt][lkc+7][lrow] = f2tf32(pb1.w);
        }
        __syncthreads();
        cur ^= 1;
    }

#pragma unroll
    for (int i = 0; i < 4; i++) {
#pragma unroll
        for (int j = 0; j < 4; j++) {
            size_t r0 = (size_t)(bm + wm + 16 * i + g);
            size_t col = (size_t)(bn + wn + 8 * j + 2 * t);
            float v0 = acc[i][j][0], v1 = acc[i][j][1];
            float v2 = acc[i][j][2], v3 = acc[i][j][3];
            if (RND) {
                v0 = __uint_as_float(f2tf32(v0)); v1 = __uint_as_float(f2tf32(v1));
                v2 = __uint_as_float(f2tf32(v2)); v3 = __uint_as_float(f2tf32(v3));
            }
            *(float2*)&C[r0 * N + col]       = make_float2(v0, v1);
            *(float2*)&C[(r0 + 8) * N + col] = make_float2(v2, v3);
        }
    }
}

// O projection (plain)
__global__ void __launch_bounds__(256) sgemm_tf32(
    const float* __restrict__ A, const float* __restrict__ Bm,
    float* __restrict__ C, int M, int N, int K)
{
    __shared__ unsigned As[2][BKT][SSTR];
    __shared__ unsigned Bs[2][BKT][SSTR];
    gemm_body<false>(A, Bm, C, N, K, blockIdx.y << 7, blockIdx.x << 7, As, Bs);
}

// Fused QKV projection: z=0 Q(12 blk), z=1 K(3 blk), z=2 V(4 blk, rounded)
__global__ void __launch_bounds__(256) sgemm_qkv(
    const float* __restrict__ A,
    const float* __restrict__ Wq, const float* __restrict__ Wk,
    const float* __restrict__ Wv,
    float* __restrict__ qb, float* __restrict__ kb, float* __restrict__ vb)
{
    __shared__ unsigned As[2][BKT][SSTR];
    __shared__ unsigned Bs[2][BKT][SSTR];
    const int z = blockIdx.z, bx = blockIdx.x;
    const int bm = blockIdx.y << 7, bn = bx << 7;
    if (z == 0) {
        gemm_body<false>(A, Wq, qb, QN, D_, bm, bn, As, Bs);
    } else if (z == 1) {
        if (bx >= KN / 128) return;
        gemm_body<false>(A, Wk, kb, KN, D_, bm, bn, As, Bs);
    } else {
        if (bx >= VN / 128) return;
        gemm_body<true>(A, Wv, vb, VN, D_, bm, bn, As, Bs);
    }
}

// ---------------------------------------------------------------------------
// Fused RMSNorm+RoPE over Q rows then K rows. K output rounded to tf32 bits.
// ---------------------------------------------------------------------------
#define QROWS (TOK * H_)
#define KROWS (TOK * KV_)

__global__ void rmsnorm_rope_fused(float* qb, float* kb,
                                   const float* __restrict__ qw,
                                   const float* __restrict__ kw,
                                   const int* __restrict__ pos_ids)
{
    __shared__ float sh[4][96];
    const int wid  = threadIdx.x >> 5;
    const int lane = threadIdx.x & 31;
    const int row  = blockIdx.x * 4 + wid;
    if (row >= QROWS + KROWS) return;

    const bool isK = (row >= QROWS);
    const int  r   = isK ? row - QROWS : row;
    const int  token = isK ? (r / KV_) : (r / H_);
    float* x = (isK ? kb : qb) + (size_t)r * 96;
    const float* w = isK ? kw : qw;

    float v0 = x[lane], v1 = x[lane + 32], v2 = x[lane + 64];
    float ss = v0 * v0 + v1 * v1 + v2 * v2;
#pragma unroll
    for (int o = 16; o; o >>= 1) ss += __shfl_xor_sync(0xffffffffu, ss, o);
    float inv = rsqrtf(ss * (1.0f / 96.0f) + 1e-6f);

    sh[wid][lane]      = v0 * inv * w[lane];
    sh[wid][lane + 32] = v1 * inv * w[lane + 32];
    sh[wid][lane + 64] = v2 * inv * w[lane + 64];
    __syncwarp();

    const int pos = pos_ids[token];
    const float* ct = g_cos + pos * 48;
    const float* st = g_sin + pos * 48;
#pragma unroll
    for (int q3 = 0; q3 < 3; q3++) {
        int d = lane + q3 * 32;
        int f = (d < 48) ? d : d - 48;
        float rh = (d < 48) ? -sh[wid][d + 48] : sh[wid][d - 48];
        float val = sh[wid][d] * ct[f] + rh * st[f];
        x[d] = isK ? __uint_as_float(f2tf32(val)) : val;
    }
}

// ---------------------------------------------------------------------------
// Tensor-core flash attention (tf32 MMA, pipelined via cp.async).
// CTA = (128-q tile, head, batch), 256 thr / 8 warps. (R4 config)
// ---------------------------------------------------------------------------
#define QT128 128
#define KT64  64
#define QSTR 100
#define VSTR 136
#define PSTR 68
#define SM_QS   0
#define SM_KF   (128*QSTR)
#define SM_VF   (SM_KF + 2*64*QSTR)
#define SM_PS   (SM_VF + 2*64*VSTR)
#define ATTN_WORDS (SM_PS + 8*16*PSTR)

extern __shared__ unsigned ds_attn[];

__global__ void __launch_bounds__(256) attn_tc_kernel()
{
    const int qt  = blockIdx.x;       // 0..15
    const int h   = blockIdx.y;
    const int b   = blockIdx.z;
    const int kvh = h >> 2;
    const int tid = threadIdx.x;
    const int w   = tid >> 5;
    const int lane = tid & 31;
    const int g   = lane >> 2;
    const int t   = lane & 3;
    const int wm  = w * 16;

    unsigned* Qs  = ds_attn + SM_QS;
    unsigned* Psw = ds_attn + SM_PS + w * 16 * PSTR;
    unsigned kf_s[2], vf_s[2];
    kf_s[0] = (unsigned)__cvta_generic_to_shared(ds_attn + SM_KF);
    kf_s[1] = kf_s[0] + 64 * QSTR * 4;
    vf_s[0] = (unsigned)__cvta_generic_to_shared(ds_attn + SM_VF);
    vf_s[1] = vf_s[0] + 64 * VSTR * 4;
    unsigned* Kf[2] = { ds_attn + SM_KF, ds_attn + SM_KF + 64 * QSTR };
    unsigned* Vf[2] = { ds_attn + SM_VF, ds_attn + SM_VF + 64 * VSTR };

    const float scale = 1.0f / sqrtf(96.0f);
    const float* kb0 = g_k + (size_t)(b * S_) * KN + kvh * KQD_;
    const float* vb0 = g_v + (size_t)(b * S_) * VN + kvh * VD_;

    const float* qbase = g_q + ((size_t)(b * S_ + qt * QT128)) * QN + h * KQD_;
    for (int it = tid; it < 128 * 24; it += 256) {
        int r = it / 24, c4 = (it % 24) * 4;
        float4 v = *(const float4*)(qbase + (size_t)r * QN + c4);
        uint4 u = make_uint4(f2tf32(v.x * scale), f2tf32(v.y * scale),
                             f2tf32(v.z * scale), f2tf32(v.w * scale));
        *(uint4*)&Qs[r * QSTR + c4] = u;
    }

    {
        const float* kbase = kb0;
        for (int it = tid; it < 64 * 24; it += 256) {
            int r = it / 24, c4 = (it % 24) * 4;
            cp_async16(kf_s[0] + (r * QSTR + c4) * 4, kbase + (size_t)r * KN + c4);
        }
        const float* vbase = vb0;
        for (int it = tid; it < 64 * 32; it += 256) {
            int r = it >> 5, c4 = (it & 31) * 4;
            cp_async16(vf_s[0] + (r * VSTR + c4) * 4, vbase + (size_t)r * VN + c4);
        }
        CP_COMMIT();
    }

    float o[16][4];
#pragma unroll
    for (int j = 0; j < 16; j++)
#pragma unroll
        for (int r = 0; r < 4; r++) o[j][r] = 0.f;
    float m0 = -INFINITY, m1 = -INFINITY, l0 = 0.f, l1 = 0.f;

    const int row0g = qt * QT128 + wm + g;
    const int row1g = row0g + 8;
    const int kt_max = 2 * qt + 1;

    for (int kt = 0; kt <= kt_max; kt++) {
        const int cur = kt & 1;
        if (kt < kt_max) {
            const int nb = (kt + 1) & 1;
            const float* kbase = kb0 + (size_t)(kt + 1) * KT64 * KN;
            for (int it = tid; it < 64 * 24; it += 256) {
                int r = it / 24, c4 = (it % 24) * 4;
                cp_async16(kf_s[nb] + (r * QSTR + c4) * 4, kbase + (size_t)r * KN + c4);
            }
            const float* vbase = vb0 + (size_t)(kt + 1) * KT64 * VN;
            for (int it = tid; it < 64 * 32; it += 256) {
                int r = it >> 5, c4 = (it & 31) * 4;
                cp_async16(vf_s[nb] + (r * VSTR + c4) * 4, vbase + (size_t)r * VN + c4);
            }
        }
        CP_COMMIT();
        CP_WAIT1();
        __syncthreads();

        if (KT64 * kt <= qt * QT128 + wm + 15) {
            const unsigned* Kc = Kf[cur];
            const unsigned* Vc = Vf[cur];

            float s[8][4];
#pragma unroll
            for (int j = 0; j < 8; j++)
#pragma unroll
                for (int r = 0; r < 4; r++) s[j][r] = 0.f;
#pragma unroll
            for (int k8 = 0; k8 < 96; k8 += 8) {
                unsigned af[4];
                af[0] = Qs[(wm + g    ) * QSTR + k8 + t    ];
                af[1] = Qs[(wm + g + 8) * QSTR + k8 + t    ];
                af[2] = Qs[(wm + g    ) * QSTR + k8 + t + 4];
                af[3] = Qs[(wm + g + 8) * QSTR + k8 + t + 4];
#pragma unroll
                for (int j = 0; j < 8; j++) {
                    unsigned bf[2];
                    bf[0] = Kc[(8 * j + g) * QSTR + k8 + t    ];
                    bf[1] = Kc[(8 * j + g) * QSTR + k8 + t + 4];
                    mma_tf32(s[j], af, bf);
                }
            }

            if (kt >= 2 * qt) {
#pragma unroll
                for (int j = 0; j < 8; j++) {
                    int c0 = kt * KT64 + 8 * j + 2 * t;
                    if (c0     > row0g) s[j][0] = -INFINITY;
                    if (c0 + 1 > row0g) s[j][1] = -INFINITY;
                    if (c0     > row1g) s[j][2] = -INFINITY;
                    if (c0 + 1 > row1g) s[j][3] = -INFINITY;
                }
            }

            float ml0 = -INFINITY, ml1 = -INFINITY;
#pragma unroll
            for (int j = 0; j < 8; j++) {
                ml0 = fmaxf(ml0, fmaxf(s[j][0], s[j][1]));
                ml1 = fmaxf(ml1, fmaxf(s[j][2], s[j][3]));
            }
            ml0 = fmaxf(ml0, __shfl_xor_sync(0xffffffffu, ml0, 1));
            ml0 = fmaxf(ml0, __shfl_xor_sync(0xffffffffu, ml0, 2));
            ml1 = fmaxf(ml1, __shfl_xor_sync(0xffffffffu, ml1, 1));
            ml1 = fmaxf(ml1, __shfl_xor_sync(0xffffffffu, ml1, 2));
            float mn0 = fmaxf(m0, ml0), mn1 = fmaxf(m1, ml1);
            float al0 = __expf(m0 - mn0), al1 = __expf(m1 - mn1);
            m0 = mn0; m1 = mn1;
            float sum0 = 0.f, sum1 = 0.f;
#pragma unroll
            for (int j = 0; j < 8; j++) {
                s[j][0] = __expf(s[j][0] - mn0); sum0 += s[j][0];
                s[j][1] = __expf(s[j][1] - mn0); sum0 += s[j][1];
                s[j][2] = __expf(s[j][2] - mn1); sum1 += s[j][2];
                s[j][3] = __expf(s[j][3] - mn1); sum1 += s[j][3];
            }
            sum0 += __shfl_xor_sync(0xffffffffu, sum0, 1);
            sum0 += __shfl_xor_sync(0xffffffffu, sum0, 2);
            sum1 += __shfl_xor_sync(0xffffffffu, sum1, 1);
            sum1 += __shfl_xor_sync(0xffffffffu, sum1, 2);
            l0 = l0 * al0 + sum0;
            l1 = l1 * al1 + sum1;
#pragma unroll
            for (int j = 0; j < 16; j++) {
                o[j][0] *= al0; o[j][1] *= al0;
                o[j][2] *= al1; o[j][3] *= al1;
            }

#pragma unroll
            for (int j = 0; j < 8; j++) {
                *(uint2*)&Psw[g * PSTR + 8 * j + 2 * t] =
                    make_uint2(f2tf32(s[j][0]), f2tf32(s[j][1]));
                *(uint2*)&Psw[(g + 8) * PSTR + 8 * j + 2 * t] =
                    make_uint2(f2tf32(s[j][2]), f2tf32(s[j][3]));
            }
            __syncwarp();

#pragma unroll
            for (int k8 = 0; k8 < 64; k8 += 8) {
                unsigned af[4];
                af[0] = Psw[(g    ) * PSTR + k8 + t    ];
                af[1] = Psw[(g + 8) * PSTR + k8 + t    ];
                af[2] = Psw[(g    ) * PSTR + k8 + t + 4];
                af[3] = Psw[(g + 8) * PSTR + k8 + t + 4];
#pragma unroll
                for (int jn = 0; jn < 16; jn++) {
                    unsigned bf[2];
                    bf[0] = Vc[(k8 + t    ) * VSTR + 8 * jn + g];
                    bf[1] = Vc[(k8 + t + 4) * VSTR + 8 * jn + g];
                    mma_tf32(o[jn], af, bf);
                }
            }
        }
        __syncthreads();
    }

    float inv0 = 1.0f / l0, inv1 = 1.0f / l1;
    float* ob = g_ao + ((size_t)(b * S_)) * ON + h * VD_;
    size_t r0 = (size_t)(qt * QT128 + wm + g);
    size_t r1 = r0 + 8;
#pragma unroll
    for (int jn = 0; jn < 16; jn++) {
        int col = 8 * jn + 2 * t;
        *(float2*)&ob[r0 * ON + col] = make_float2(o[jn][0] * inv0, o[jn][1] * inv0);
        *(float2*)&ob[r1 * ON + col] = make_float2(o[jn][2] * inv1, o[jn][3] * inv1);
    }
}

// ---------------------------------------------------------------------------
extern "C" void kernel_launch(void* const* d_in, const int* in_sizes, int n_in,
                              void* d_out, int out_size)
{
    const float* hidden = (const float*)d_in[0];
    const int*   pos    = (const int*)  d_in[1];
    const float* Wq     = (const float*)d_in[2];
    const float* Wk     = (const float*)d_in[3];
    const float* Wv     = (const float*)d_in[4];
    const float* Wo     = (const float*)d_in[5];
    const float* qw     = (const float*)d_in[6];
    const float* kw     = (const float*)d_in[7];
    float* out = (float*)d_out;

    void *pq, *pk, *pv, *pa;
    cudaGetSymbolAddress(&pq, g_q);
    cudaGetSymbolAddress(&pk, g_k);
    cudaGetSymbolAddress(&pv, g_v);
    cudaGetSymbolAddress(&pa, g_ao);
    float* qb = (float*)pq;
    float* kb = (float*)pk;
    float* vb = (float*)pv;
    float* ab = (float*)pa;

    static int smem_set = 0;
    if (!smem_set) {
        cudaFuncSetAttribute(attn_tc_kernel,
                             cudaFuncAttributeMaxDynamicSharedMemorySize,
                             ATTN_WORDS * 4);
        smem_set = 1;
    }

    // 1. inv_freq (tiny fp64) + RoPE table (pure fp32)
    invf_kernel<<<1, 64>>>();
    rope_table_kernel<<<(S_ * 48 + 255) / 256, 256>>>();

    // 2. Fused QKV projection (R4 grid)
    sgemm_qkv<<<dim3(QN / 128, TOK / 128, 3), 256>>>(hidden, Wq, Wk, Wv, qb, kb, vb);

    // 3. Fused RMSNorm + RoPE
    rmsnorm_rope_fused<<<(QROWS + KROWS) / 4, 128>>>(qb, kb, qw, kw, pos);

    // 4. Tensor-core flash attention (R4 ordering)
    attn_tc_kernel<<<dim3(S_ / QT128, H_, B_), 256, ATTN_WORDS * 4>>>();

    // 5. Output projection
    sgemm_tf32<<<dim3(D_ / 128, TOK / 128), 256>>>(ab, Wo, out, TOK, D_, ON);
}

// round 7
// speedup vs baseline: 1.5507x; 1.0058x over previous
#include <cuda_runtime.h>
#include <math.h>

// Problem constants
#define B_   2
#define S_   2048
#define D_   2048
#define H_   16
#define KV_  4
#define KQD_ 96
#define VD_  128
#define TOK  (B_*S_)       // 4096
#define QN   (H_*KQD_)     // 1536
#define KN   (KV_*KQD_)    // 384
#define VN   (KV_*VD_)     // 512
#define ON   (H_*VD_)      // 2048

__device__ float g_q [TOK * QN];
__device__ float g_k [TOK * KN];
__device__ float g_v [TOK * VN];
__device__ float g_ao[TOK * ON];
__device__ float g_cos[S_ * 48];
__device__ float g_sin[S_ * 48];
__device__ double g_invf[48];

// ---------------------------------------------------------------------------
__global__ void invf_kernel() {
    int j = threadIdx.x;
    if (j < 48) g_invf[j] = pow(10000.0, -(double)j / 48.0);
}

// RoPE table: pure fp32 float-pair pipeline.
__global__ void rope_table_kernel() {
    int i = blockIdx.x * blockDim.x + threadIdx.x;
    if (i >= S_ * 48) return;
    int pos = i / 48, j = i % 48;
    double d = g_invf[j];
    float hi = (float)d;
    float lo = (float)(d - (double)hi);
    float fp = (float)pos;
    float p  = fp * hi;
    float e  = fmaf(fp, hi, -p);
    float t2 = fmaf(fp, lo, e);
    const float INV2PI = 0.15915494309189535f;
    const float PIH    = 6.2831854820251465f;
    const float PIL    = -1.7484555314695172e-7f;
    float n = rintf(p * INV2PI);
    float r = fmaf(-n, PIH, p);
    r = fmaf(-n, PIL, r);
    r = r + t2;
    float s, c;
    sincosf(r, &s, &c);
    g_cos[i] = c;
    g_sin[i] = s;
}

// ---------------------------------------------------------------------------
__device__ __forceinline__ unsigned f2tf32(float x) {
    unsigned r;
    asm("cvt.rna.tf32.f32 %0, %1;" : "=r"(r) : "f"(x));
    return r;
}
__device__ __forceinline__ void mma_tf32(float* c, const unsigned* a, const unsigned* b) {
    asm volatile(
        "mma.sync.aligned.m16n8k8.row.col.f32.tf32.tf32.f32 "
        "{%0,%1,%2,%3}, {%4,%5,%6,%7}, {%8,%9}, {%0,%1,%2,%3};\n"
        : "+f"(c[0]), "+f"(c[1]), "+f"(c[2]), "+f"(c[3])
        : "r"(a[0]), "r"(a[1]), "r"(a[2]), "r"(a[3]),
          "r"(b[0]), "r"(b[1]));
}
__device__ __forceinline__ void cp_async16(unsigned saddr, const void* g) {
    asm volatile("cp.async.cg.shared.global [%0], [%1], 16;\n" :: "r"(saddr), "l"(g));
}
#define CP_COMMIT() asm volatile("cp.async.commit_group;\n" ::: "memory")
#define CP_WAIT1()  asm volatile("cp.async.wait_group 1;\n" ::: "memory")

// ---------------------------------------------------------------------------
// TF32 GEMM-NT core (128x128 tile, BK=16, double-buffered).
// ---------------------------------------------------------------------------
#define BKT 16
#define SSTR 136

template<bool RND>
__device__ __forceinline__ void gemm_body(
    const float* __restrict__ A, const float* __restrict__ Bm,
    float* __restrict__ C, int N, int K, int bm, int bn,
    unsigned (*As)[BKT][SSTR], unsigned (*Bs)[BKT][SSTR])
{
    const int tid  = threadIdx.x;
    const int warp = tid >> 5;
    const int lane = tid & 31;
    const int g    = lane >> 2;
    const int t    = lane & 3;
    const int wm   = (warp >> 2) * 64;
    const int wn   = (warp & 3) * 32;

    const int lrow = tid >> 1;
    const int lkc  = (tid & 1) * 8;
    const float* Ap = A  + (size_t)(bm + lrow) * K + lkc;
    const float* Bp = Bm + (size_t)(bn + lrow) * K + lkc;

    float acc[4][4][4];
#pragma unroll
    for (int i = 0; i < 4; i++)
#pragma unroll
        for (int j = 0; j < 4; j++)
#pragma unroll
            for (int r = 0; r < 4; r++) acc[i][j][r] = 0.f;

    float4 pa0 = *(const float4*)(Ap + 0);
    float4 pa1 = *(const float4*)(Ap + 4);
    float4 pb0 = *(const float4*)(Bp + 0);
    float4 pb1 = *(const float4*)(Bp + 4);
    {
        As[0][lkc+0][lrow] = f2tf32(pa0.x); As[0][lkc+1][lrow] = f2tf32(pa0.y);
        As[0][lkc+2][lrow] = f2tf32(pa0.z); As[0][lkc+3][lrow] = f2tf32(pa0.w);
        As[0][lkc+4][lrow] = f2tf32(pa1.x); As[0][lkc+5][lrow] = f2tf32(pa1.y);
        As[0][lkc+6][lrow] = f2tf32(pa1.z); As[0][lkc+7][lrow] = f2tf32(pa1.w);
        Bs[0][lkc+0][lrow] = f2tf32(pb0.x); Bs[0][lkc+1][lrow] = f2tf32(pb0.y);
        Bs[0][lkc+2][lrow] = f2tf32(pb0.z); Bs[0][lkc+3][lrow] = f2tf32(pb0.w);
        Bs[0][lkc+4][lrow] = f2tf32(pb1.x); Bs[0][lkc+5][lrow] = f2tf32(pb1.y);
        Bs[0][lkc+6][lrow] = f2tf32(pb1.z); Bs[0][lkc+7][lrow] = f2tf32(pb1.w);
    }
    __syncthreads();

    int cur = 0;
    for (int k0 = BKT; k0 <= K; k0 += BKT) {
        const bool more = (k0 < K);
        if (more) {
            pa0 = *(const float4*)(Ap + k0);
            pa1 = *(const float4*)(Ap + k0 + 4);
            pb0 = *(const float4*)(Bp + k0);
            pb1 = *(const float4*)(Bp + k0 + 4);
        }
#pragma unroll
        for (int kh = 0; kh < 2; kh++) {
            const int k8 = kh * 8;
            unsigned af[4][4], bf[4][2];
#pragma unroll
            for (int i = 0; i < 4; i++) {
                int m = wm + 16 * i;
                af[i][0] = As[cur][k8 + t    ][m + g];
                af[i][1] = As[cur][k8 + t    ][m + g + 8];
                af[i][2] = As[cur][k8 + t + 4][m + g];
                af[i][3] = As[cur][k8 + t + 4][m + g + 8];
            }
#pragma unroll
            for (int j = 0; j < 4; j++) {
                int n = wn + 8 * j;
                bf[j][0] = Bs[cur][k8 + t    ][n + g];
                bf[j][1] = Bs[cur][k8 + t + 4][n + g];
            }
#pragma unroll
            for (int i = 0; i < 4; i++)
#pragma unroll
                for (int j = 0; j < 4; j++)
                    mma_tf32(acc[i][j], af[i], bf[j]);
        }
        if (more) {
            int nxt = cur ^ 1;
            As[nxt][lkc+0][lrow] = f2tf32(pa0.x); As[nxt][lkc+1][lrow] = f2tf32(pa0.y);
            As[nxt][lkc+2][lrow] = f2tf32(pa0.z); As[nxt][lkc+3][lrow] = f2tf32(pa0.w);
            As[nxt][lkc+4][lrow] = f2tf32(pa1.x); As[nxt][lkc+5][lrow] = f2tf32(pa1.y);
            As[nxt][lkc+6][lrow] = f2tf32(pa1.z); As[nxt][lkc+7][lrow] = f2tf32(pa1.w);
            Bs[nxt][lkc+0][lrow] = f2tf32(pb0.x); Bs[nxt][lkc+1][lrow] = f2tf32(pb0.y);
            Bs[nxt][lkc+2][lrow] = f2tf32(pb0.z); Bs[nxt][lkc+3][lrow] = f2tf32(pb0.w);
            Bs[nxt][lkc+4][lrow] = f2tf32(pb1.x); Bs[nxt][lkc+5][lrow] = f2tf32(pb1.y);
            Bs[nxt][lkc+6][lrow] = f2tf32(pb1.z); Bs[nxt][lkc+7][lrow] = f2tf32(pb1.w);
        }
        __syncthreads();
        cur ^= 1;
    }

#pragma unroll
    for (int i = 0; i < 4; i++) {
#pragma unroll
        for (int j = 0; j < 4; j++) {
            size_t r0 = (size_t)(bm + wm + 16 * i + g);
            size_t col = (size_t)(bn + wn + 8 * j + 2 * t);
            float v0 = acc[i][j][0], v1 = acc[i][j][1];
            float v2 = acc[i][j][2], v3 = acc[i][j][3];
            if (RND) {
                v0 = __uint_as_float(f2tf32(v0)); v1 = __uint_as_float(f2tf32(v1));
                v2 = __uint_as_float(f2tf32(v2)); v3 = __uint_as_float(f2tf32(v3));
            }
            *(float2*)&C[r0 * N + col]       = make_float2(v0, v1);
            *(float2*)&C[(r0 + 8) * N + col] = make_float2(v2, v3);
        }
    }
}

// O projection — 2 CTAs/SM forced
__global__ void __launch_bounds__(256, 2) sgemm_tf32(
    const float* __restrict__ A, const float* __restrict__ Bm,
    float* __restrict__ C, int M, int N, int K)
{
    __shared__ unsigned As[2][BKT][SSTR];
    __shared__ unsigned Bs[2][BKT][SSTR];
    gemm_body<false>(A, Bm, C, N, K, blockIdx.y << 7, blockIdx.x << 7, As, Bs);
}

// Fused QKV projection, compact grid: x in [0,19): 12 Q | 3 K | 4 V
__global__ void __launch_bounds__(256, 2) sgemm_qkv(
    const float* __restrict__ A,
    const float* __restrict__ Wq, const float* __restrict__ Wk,
    const float* __restrict__ Wv,
    float* __restrict__ qb, float* __restrict__ kb, float* __restrict__ vb)
{
    __shared__ unsigned As[2][BKT][SSTR];
    __shared__ unsigned Bs[2][BKT][SSTR];
    const int bx = blockIdx.x;
    const int bm = blockIdx.y << 7;
    if (bx < 12) {
        gemm_body<false>(A, Wq, qb, QN, D_, bm, bx << 7, As, Bs);
    } else if (bx < 15) {
        gemm_body<false>(A, Wk, kb, KN, D_, bm, (bx - 12) << 7, As, Bs);
    } else {
        gemm_body<true>(A, Wv, vb, VN, D_, bm, (bx - 15) << 7, As, Bs);
    }
}

// ---------------------------------------------------------------------------
// Fused RMSNorm+RoPE over Q rows then K rows. K output rounded to tf32 bits.
// ---------------------------------------------------------------------------
#define QROWS (TOK * H_)
#define KROWS (TOK * KV_)

__global__ void rmsnorm_rope_fused(float* qb, float* kb,
                                   const float* __restrict__ qw,
                                   const float* __restrict__ kw,
                                   const int* __restrict__ pos_ids)
{
    __shared__ float sh[4][96];
    const int wid  = threadIdx.x >> 5;
    const int lane = threadIdx.x & 31;
    const int row  = blockIdx.x * 4 + wid;
    if (row >= QROWS + KROWS) return;

    const bool isK = (row >= QROWS);
    const int  r   = isK ? row - QROWS : row;
    const int  token = isK ? (r / KV_) : (r / H_);
    float* x = (isK ? kb : qb) + (size_t)r * 96;
    const float* w = isK ? kw : qw;

    float v0 = x[lane], v1 = x[lane + 32], v2 = x[lane + 64];
    float ss = v0 * v0 + v1 * v1 + v2 * v2;
#pragma unroll
    for (int o = 16; o; o >>= 1) ss += __shfl_xor_sync(0xffffffffu, ss, o);
    float inv = rsqrtf(ss * (1.0f / 96.0f) + 1e-6f);

    sh[wid][lane]      = v0 * inv * w[lane];
    sh[wid][lane + 32] = v1 * inv * w[lane + 32];
    sh[wid][lane + 64] = v2 * inv * w[lane + 64];
    __syncwarp();

    const int pos = pos_ids[token];
    const float* ct = g_cos + pos * 48;
    const float* st = g_sin + pos * 48;
#pragma unroll
    for (int q3 = 0; q3 < 3; q3++) {
        int d = lane + q3 * 32;
        int f = (d < 48) ? d : d - 48;
        float rh = (d < 48) ? -sh[wid][d + 48] : sh[wid][d - 48];
        float val = sh[wid][d] * ct[f] + rh * st[f];
        x[d] = isK ? __uint_as_float(f2tf32(val)) : val;
    }
}

// ---------------------------------------------------------------------------
// Tensor-core flash attention (tf32 MMA, pipelined via cp.async). R4/R6 config.
// ---------------------------------------------------------------------------
#define QT128 128
#define KT64  64
#define QSTR 100
#define VSTR 136
#define PSTR 68
#define SM_QS   0
#define SM_KF   (128*QSTR)
#define SM_VF   (SM_KF + 2*64*QSTR)
#define SM_PS   (SM_VF + 2*64*VSTR)
#define ATTN_WORDS (SM_PS + 8*16*PSTR)

extern __shared__ unsigned ds_attn[];

__global__ void __launch_bounds__(256) attn_tc_kernel()
{
    const int qt  = blockIdx.x;       // 0..15
    const int h   = blockIdx.y;
    const int b   = blockIdx.z;
    const int kvh = h >> 2;
    const int tid = threadIdx.x;
    const int w   = tid >> 5;
    const int lane = tid & 31;
    const int g   = lane >> 2;
    const int t   = lane & 3;
    const int wm  = w * 16;

    unsigned* Qs  = ds_attn + SM_QS;
    unsigned* Psw = ds_attn + SM_PS + w * 16 * PSTR;
    unsigned kf_s[2], vf_s[2];
    kf_s[0] = (unsigned)__cvta_generic_to_shared(ds_attn + SM_KF);
    kf_s[1] = kf_s[0] + 64 * QSTR * 4;
    vf_s[0] = (unsigned)__cvta_generic_to_shared(ds_attn + SM_VF);
    vf_s[1] = vf_s[0] + 64 * VSTR * 4;
    unsigned* Kf[2] = { ds_attn + SM_KF, ds_attn + SM_KF + 64 * QSTR };
    unsigned* Vf[2] = { ds_attn + SM_VF, ds_attn + SM_VF + 64 * VSTR };

    const float scale = 1.0f / sqrtf(96.0f);
    const float* kb0 = g_k + (size_t)(b * S_) * KN + kvh * KQD_;
    const float* vb0 = g_v + (size_t)(b * S_) * VN + kvh * VD_;

    const float* qbase = g_q + ((size_t)(b * S_ + qt * QT128)) * QN + h * KQD_;
    for (int it = tid; it < 128 * 24; it += 256) {
        int r = it / 24, c4 = (it % 24) * 4;
        float4 v = *(const float4*)(qbase + (size_t)r * QN + c4);
        uint4 u = make_uint4(f2tf32(v.x * scale), f2tf32(v.y * scale),
                             f2tf32(v.z * scale), f2tf32(v.w * scale));
        *(uint4*)&Qs[r * QSTR + c4] = u;
    }

    {
        const float* kbase = kb0;
        for (int it = tid; it < 64 * 24; it += 256) {
            int r = it / 24, c4 = (it % 24) * 4;
            cp_async16(kf_s[0] + (r * QSTR + c4) * 4, kbase + (size_t)r * KN + c4);
        }
        const float* vbase = vb0;
        for (int it = tid; it < 64 * 32; it += 256) {
            int r = it >> 5, c4 = (it & 31) * 4;
            cp_async16(vf_s[0] + (r * VSTR + c4) * 4, vbase + (size_t)r * VN + c4);
        }
        CP_COMMIT();
    }

    float o[16][4];
#pragma unroll
    for (int j = 0; j < 16; j++)
#pragma unroll
        for (int r = 0; r < 4; r++) o[j][r] = 0.f;
    float m0 = -INFINITY, m1 = -INFINITY, l0 = 0.f, l1 = 0.f;

    const int row0g = qt * QT128 + wm + g;
    const int row1g = row0g + 8;
    const int kt_max = 2 * qt + 1;

    for (int kt = 0; kt <= kt_max; kt++) {
        const int cur = kt & 1;
        if (kt < kt_max) {
            const int nb = (kt + 1) & 1;
            const float* kbase = kb0 + (size_t)(kt + 1) * KT64 * KN;
            for (int it = tid; it < 64 * 24; it += 256) {
                int r = it / 24, c4 = (it % 24) * 4;
                cp_async16(kf_s[nb] + (r * QSTR + c4) * 4, kbase + (size_t)r * KN + c4);
            }
            const float* vbase = vb0 + (size_t)(kt + 1) * KT64 * VN;
            for (int it = tid; it < 64 * 32; it += 256) {
                int r = it >> 5, c4 = (it & 31) * 4;
                cp_async16(vf_s[nb] + (r * VSTR + c4) * 4, vbase + (size_t)r * VN + c4);
            }
        }
        CP_COMMIT();
        CP_WAIT1();
        __syncthreads();

        if (KT64 * kt <= qt * QT128 + wm + 15) {
            const unsigned* Kc = Kf[cur];
            const unsigned* Vc = Vf[cur];

            float s[8][4];
#pragma unroll
            for (int j = 0; j < 8; j++)
#pragma unroll
                for (int r = 0; r < 4; r++) s[j][r] = 0.f;
#pragma unroll
            for (int k8 = 0; k8 < 96; k8 += 8) {
                unsigned af[4];
                af[0] = Qs[(wm + g    ) * QSTR + k8 + t    ];
                af[1] = Qs[(wm + g + 8) * QSTR + k8 + t    ];
                af[2] = Qs[(wm + g    ) * QSTR + k8 + t + 4];
                af[3] = Qs[(wm + g + 8) * QSTR + k8 + t + 4];
#pragma unroll
                for (int j = 0; j < 8; j++) {
                    unsigned bf[2];
                    bf[0] = Kc[(8 * j + g) * QSTR + k8 + t    ];
                    bf[1] = Kc[(8 * j + g) * QSTR + k8 + t + 4];
                    mma_tf32(s[j], af, bf);
                }
            }

            if (kt >= 2 * qt) {
#pragma unroll
                for (int j = 0; j < 8; j++) {
                    int c0 = kt * KT64 + 8 * j + 2 * t;
                    if (c0     > row0g) s[j][0] = -INFINITY;
                    if (c0 + 1 > row0g) s[j][1] = -INFINITY;
                    if (c0     > row1g) s[j][2] = -INFINITY;
                    if (c0 + 1 > row1g) s[j][3] = -INFINITY;
                }
            }

            float ml0 = -INFINITY, ml1 = -INFINITY;
#pragma unroll
            for (int j = 0; j < 8; j++) {
                ml0 = fmaxf(ml0, fmaxf(s[j][0], s[j][1]));
                ml1 = fmaxf(ml1, fmaxf(s[j][2], s[j][3]));
            }
            ml0 = fmaxf(ml0, __shfl_xor_sync(0xffffffffu, ml0, 1));
            ml0 = fmaxf(ml0, __shfl_xor_sync(0xffffffffu, ml0, 2));
            ml1 = fmaxf(ml1, __shfl_xor_sync(0xffffffffu, ml1, 1));
            ml1 = fmaxf(ml1, __shfl_xor_sync(0xffffffffu, ml1, 2));
            float mn0 = fmaxf(m0, ml0), mn1 = fmaxf(m1, ml1);
            float al0 = __expf(m0 - mn0), al1 = __expf(m1 - mn1);
            m0 = mn0; m1 = mn1;
            float sum0 = 0.f, sum1 = 0.f;
#pragma unroll
            for (int j = 0; j < 8; j++) {
                s[j][0] = __expf(s[j][0] - mn0); sum0 += s[j][0];
                s[j][1] = __expf(s[j][1] - mn0); sum0 += s[j][1];
                s[j][2] = __expf(s[j][2] - mn1); sum1 += s[j][2];
                s[j][3] = __expf(s[j][3] - mn1); sum1 += s[j][3];
            }
            sum0 += __shfl_xor_sync(0xffffffffu, sum0, 1);
            sum0 += __shfl_xor_sync(0xffffffffu, sum0, 2);
            sum1 += __shfl_xor_sync(0xffffffffu, sum1, 1);
            sum1 += __shfl_xor_sync(0xffffffffu, sum1, 2);
            l0 = l0 * al0 + sum0;
            l1 = l1 * al1 + sum1;
#pragma unroll
            for (int j = 0; j < 16; j++) {
                o[j][0] *= al0; o[j][1] *= al0;
                o[j][2] *= al1; o[j][3] *= al1;
            }

#pragma unroll
            for (int j = 0; j < 8; j++) {
                *(uint2*)&Psw[g * PSTR + 8 * j + 2 * t] =
                    make_uint2(f2tf32(s[j][0]), f2tf32(s[j][1]));
                *(uint2*)&Psw[(g + 8) * PSTR + 8 * j + 2 * t] =
                    make_uint2(f2tf32(s[j][2]), f2tf32(s[j][3]));
            }
            __syncwarp();

#pragma unroll
            for (int k8 = 0; k8 < 64; k8 += 8) {
                unsigned af[4];
                af[0] = Psw[(g    ) * PSTR + k8 + t    ];
                af[1] = Psw[(g + 8) * PSTR + k8 + t    ];
                af[2] = Psw[(g    ) * PSTR + k8 + t + 4];
                af[3] = Psw[(g + 8) * PSTR + k8 + t + 4];
#pragma unroll
                for (int jn = 0; jn < 16; jn++) {
                    unsigned bf[2];
                    bf[0] = Vc[(k8 + t    ) * VSTR + 8 * jn + g];
                    bf[1] = Vc[(k8 + t + 4) * VSTR + 8 * jn + g];
                    mma_tf32(o[jn], af, bf);
                }
            }
        }
        __syncthreads();
    }

    float inv0 = 1.0f / l0, inv1 = 1.0f / l1;
    float* ob = g_ao + ((size_t)(b * S_)) * ON + h * VD_;
    size_t r0 = (size_t)(qt * QT128 + wm + g);
    size_t r1 = r0 + 8;
#pragma unroll
    for (int jn = 0; jn < 16; jn++) {
        int col = 8 * jn + 2 * t;
        *(float2*)&ob[r0 * ON + col] = make_float2(o[jn][0] * inv0, o[jn][1] * inv0);
        *(float2*)&ob[r1 * ON + col] = make_float2(o[jn][2] * inv1, o[jn][3] * inv1);
    }
}

// ---------------------------------------------------------------------------
extern "C" void kernel_launch(void* const* d_in, const int* in_sizes, int n_in,
                              void* d_out, int out_size)
{
    const float* hidden = (const float*)d_in[0];
    const int*   pos    = (const int*)  d_in[1];
    const float* Wq     = (const float*)d_in[2];
    const float* Wk     = (const float*)d_in[3];
    const float* Wv     = (const float*)d_in[4];
    const float* Wo     = (const float*)d_in[5];
    const float* qw     = (const float*)d_in[6];
    const float* kw     = (const float*)d_in[7];
    float* out = (float*)d_out;

    void *pq, *pk, *pv, *pa;
    cudaGetSymbolAddress(&pq, g_q);
    cudaGetSymbolAddress(&pk, g_k);
    cudaGetSymbolAddress(&pv, g_v);
    cudaGetSymbolAddress(&pa, g_ao);
    float* qb = (float*)pq;
    float* kb = (float*)pk;
    float* vb = (float*)pv;
    float* ab = (float*)pa;

    static int smem_set = 0;
    if (!smem_set) {
        cudaFuncSetAttribute(attn_tc_kernel,
                             cudaFuncAttributeMaxDynamicSharedMemorySize,
                             ATTN_WORDS * 4);
        smem_set = 1;
    }

    // 1. inv_freq + RoPE table
    invf_kernel<<<1, 64>>>();
    rope_table_kernel<<<(S_ * 48 + 255) / 256, 256>>>();

    // 2. Fused QKV projection, compact 19-wide grid, 2 CTAs/SM
    sgemm_qkv<<<dim3(19, TOK / 128), 256>>>(hidden, Wq, Wk, Wv, qb, kb, vb);

    // 3. Fused RMSNorm + RoPE
    rmsnorm_rope_fused<<<(QROWS + KROWS) / 4, 128>>>(qb, kb, qw, kw, pos);

    // 4. Tensor-core flash attention (unchanged R6 config)
    attn_tc_kernel<<<dim3(S_ / QT128, H_, B_), 256, ATTN_WORDS * 4>>>();

    // 5. Output projection, 2 CTAs/SM
    sgemm_tf32<<<dim3(D_ / 128, TOK / 128), 256>>>(ab, Wo, out, TOK, D_, ON);
}

// round 8
// speedup vs baseline: 1.6210x; 1.0453x over previous
#include <cuda_runtime.h>
#include <math.h>

// Problem constants
#define B_   2
#define S_   2048
#define D_   2048
#define H_   16
#define KV_  4
#define KQD_ 96
#define VD_  128
#define TOK  (B_*S_)       // 4096
#define QN   (H_*KQD_)     // 1536
#define KN   (KV_*KQD_)    // 384
#define VN   (KV_*VD_)     // 512
#define ON   (H_*VD_)      // 2048

__device__ float g_q [TOK * QN];
__device__ float g_k [TOK * KN];
__device__ float g_v [TOK * VN];
__device__ float g_ao[TOK * ON];
__device__ float g_cos[S_ * 48];
__device__ float g_sin[S_ * 48];
__device__ double g_invf[48];

// Single dynamic-smem symbol shared by all kernels
extern __shared__ unsigned ds_dyn[];

// ---------------------------------------------------------------------------
__global__ void invf_kernel() {
    int j = threadIdx.x;
    if (j < 48) g_invf[j] = pow(10000.0, -(double)j / 48.0);
}

// RoPE table: pure fp32 float-pair pipeline.
__global__ void rope_table_kernel() {
    int i = blockIdx.x * blockDim.x + threadIdx.x;
    if (i >= S_ * 48) return;
    int pos = i / 48, j = i % 48;
    double d = g_invf[j];
    float hi = (float)d;
    float lo = (float)(d - (double)hi);
    float fp = (float)pos;
    float p  = fp * hi;
    float e  = fmaf(fp, hi, -p);
    float t2 = fmaf(fp, lo, e);
    const float INV2PI = 0.15915494309189535f;
    const float PIH    = 6.2831854820251465f;
    const float PIL    = -1.7484555314695172e-7f;
    float n = rintf(p * INV2PI);
    float r = fmaf(-n, PIH, p);
    r = fmaf(-n, PIL, r);
    r = r + t2;
    float s, c;
    sincosf(r, &s, &c);
    g_cos[i] = c;
    g_sin[i] = s;
}

// ---------------------------------------------------------------------------
__device__ __forceinline__ unsigned f2tf32(float x) {
    unsigned r;
    asm("cvt.rna.tf32.f32 %0, %1;" : "=r"(r) : "f"(x));
    return r;
}
__device__ __forceinline__ void mma_tf32(float* c, const unsigned* a, const unsigned* b) {
    asm volatile(
        "mma.sync.aligned.m16n8k8.row.col.f32.tf32.tf32.f32 "
        "{%0,%1,%2,%3}, {%4,%5,%6,%7}, {%8,%9}, {%0,%1,%2,%3};\n"
        : "+f"(c[0]), "+f"(c[1]), "+f"(c[2]), "+f"(c[3])
        : "r"(a[0]), "r"(a[1]), "r"(a[2]), "r"(a[3]),
          "r"(b[0]), "r"(b[1]));
}
__device__ __forceinline__ void cp_async16(unsigned saddr, const void* g) {
    asm volatile("cp.async.cg.shared.global [%0], [%1], 16;\n" :: "r"(saddr), "l"(g));
}
#define CP_COMMIT() asm volatile("cp.async.commit_group;\n" ::: "memory")
#define CP_WAIT1()  asm volatile("cp.async.wait_group 1;\n" ::: "memory")
#define CP_WAIT2()  asm volatile("cp.async.wait_group 2;\n" ::: "memory")

// ---------------------------------------------------------------------------
// TF32 GEMM-NT core v2: cp.async 4-stage pipeline, raw fp32 in smem,
// row-major [row][GSTR] (GSTR=20 -> fragment LDS conflict-free),
// tf32 conversion at fragment load. 128x128 tile, BK=16, 256 threads.
// ---------------------------------------------------------------------------
#define BKT 16
#define GSTAGES 4
#define GSTR 20                       // words per row; 20*g+t covers all banks
#define GAHALF (128*GSTR)             // 2560 words: A block
#define GSTAGE_WORDS (2*GAHALF)       // 5120 words per stage (A+B)
#define GEMM_SMEM_BYTES (GSTAGES*GSTAGE_WORDS*4)   // 81920

template<bool RND>
__device__ __forceinline__ void gemm_body(
    const float* __restrict__ A, const float* __restrict__ Bm,
    float* __restrict__ C, int N, int K, int bm, int bn, float* ds)
{
    const int tid  = threadIdx.x;
    const int warp = tid >> 5;
    const int lane = tid & 31;
    const int g    = lane >> 2;
    const int t    = lane & 3;
    const int wm   = (warp >> 2) * 64;
    const int wn   = (warp & 3) * 32;

    const int lrow = tid >> 1;          // 0..127
    const int lkc  = (tid & 1) * 8;     // 0 or 8
    const float* Ap = A  + (size_t)(bm + lrow) * K + lkc;
    const float* Bp = Bm + (size_t)(bn + lrow) * K + lkc;

    const unsigned sbase = (unsigned)__cvta_generic_to_shared(ds);
    const unsigned aoff  = (lrow * GSTR + lkc) * 4;
    const unsigned boff  = (GAHALF + lrow * GSTR + lkc) * 4;

    float acc[4][4][4];
#pragma unroll
    for (int i = 0; i < 4; i++)
#pragma unroll
        for (int j = 0; j < 4; j++)
#pragma unroll
            for (int r = 0; r < 4; r++) acc[i][j][r] = 0.f;

    // Prologue: stages 0..2
#pragma unroll
    for (int s = 0; s < GSTAGES - 1; s++) {
        unsigned sb = sbase + s * GSTAGE_WORDS * 4;
        cp_async16(sb + aoff,      Ap + s * BKT);
        cp_async16(sb + aoff + 16, Ap + s * BKT + 4);
        cp_async16(sb + boff,      Bp + s * BKT);
        cp_async16(sb + boff + 16, Bp + s * BKT + 4);
        CP_COMMIT();
    }

    const int nst = K / BKT;
    for (int ks = 0; ks < nst; ks++) {
        CP_WAIT2();          // stage ks complete (3 groups pending max)
        __syncthreads();     // all warps finished compute(ks-1) -> slot reusable

        if (ks + GSTAGES - 1 < nst) {
            int slot = (ks + GSTAGES - 1) & 3;
            unsigned sb = sbase + slot * GSTAGE_WORDS * 4;
            const float* Ap2 = Ap + (size_t)(ks + GSTAGES - 1) * BKT;
            const float* Bp2 = Bp + (size_t)(ks + GSTAGES - 1) * BKT;
            cp_async16(sb + aoff,      Ap2);
            cp_async16(sb + aoff + 16, Ap2 + 4);
            cp_async16(sb + boff,      Bp2);
            cp_async16(sb + boff + 16, Bp2 + 4);
        }
        CP_COMMIT();         // commit (possibly empty) keeps group count aligned

        const float* As = ds + (ks & 3) * GSTAGE_WORDS;
        const float* Bs = As + GAHALF;

#pragma unroll
        for (int kh = 0; kh < 2; kh++) {
            const int k8 = kh * 8;
            unsigned af[4][4], bf[4][2];
#pragma unroll
            for (int i = 0; i < 4; i++) {
                int m = wm + 16 * i;
                af[i][0] = f2tf32(As[(m + g    ) * GSTR + k8 + t    ]);
                af[i][1] = f2tf32(As[(m + g + 8) * GSTR + k8 + t    ]);
                af[i][2] = f2tf32(As[(m + g    ) * GSTR + k8 + t + 4]);
                af[i][3] = f2tf32(As[(m + g + 8) * GSTR + k8 + t + 4]);
            }
#pragma unroll
            for (int j = 0; j < 4; j++) {
                int n = wn + 8 * j;
                bf[j][0] = f2tf32(Bs[(n + g) * GSTR + k8 + t    ]);
                bf[j][1] = f2tf32(Bs[(n + g) * GSTR + k8 + t + 4]);
            }
#pragma unroll
            for (int i = 0; i < 4; i++)
#pragma unroll
                for (int j = 0; j < 4; j++)
                    mma_tf32(acc[i][j], af[i], bf[j]);
        }
    }

#pragma unroll
    for (int i = 0; i < 4; i++) {
#pragma unroll
        for (int j = 0; j < 4; j++) {
            size_t r0 = (size_t)(bm + wm + 16 * i + g);
            size_t col = (size_t)(bn + wn + 8 * j + 2 * t);
            float v0 = acc[i][j][0], v1 = acc[i][j][1];
            float v2 = acc[i][j][2], v3 = acc[i][j][3];
            if (RND) {
                v0 = __uint_as_float(f2tf32(v0)); v1 = __uint_as_float(f2tf32(v1));
                v2 = __uint_as_float(f2tf32(v2)); v3 = __uint_as_float(f2tf32(v3));
            }
            *(float2*)&C[r0 * N + col]       = make_float2(v0, v1);
            *(float2*)&C[(r0 + 8) * N + col] = make_float2(v2, v3);
        }
    }
}

// O projection
__global__ void __launch_bounds__(256) sgemm_tf32(
    const float* __restrict__ A, const float* __restrict__ Bm,
    float* __restrict__ C, int M, int N, int K)
{
    gemm_body<false>(A, Bm, C, N, K, blockIdx.y << 7, blockIdx.x << 7,
                     (float*)ds_dyn);
}

// Fused QKV projection, compact grid: x in [0,19): 12 Q | 3 K | 4 V
__global__ void __launch_bounds__(256) sgemm_qkv(
    const float* __restrict__ A,
    const float* __restrict__ Wq, const float* __restrict__ Wk,
    const float* __restrict__ Wv,
    float* __restrict__ qb, float* __restrict__ kb, float* __restrict__ vb)
{
    const int bx = blockIdx.x;
    const int bm = blockIdx.y << 7;
    float* ds = (float*)ds_dyn;
    if (bx < 12) {
        gemm_body<false>(A, Wq, qb, QN, D_, bm, bx << 7, ds);
    } else if (bx < 15) {
        gemm_body<false>(A, Wk, kb, KN, D_, bm, (bx - 12) << 7, ds);
    } else {
        gemm_body<true>(A, Wv, vb, VN, D_, bm, (bx - 15) << 7, ds);
    }
}

// ---------------------------------------------------------------------------
// Fused RMSNorm+RoPE over Q rows then K rows. K output rounded to tf32 bits.
// ---------------------------------------------------------------------------
#define QROWS (TOK * H_)
#define KROWS (TOK * KV_)

__global__ void rmsnorm_rope_fused(float* qb, float* kb,
                                   const float* __restrict__ qw,
                                   const float* __restrict__ kw,
                                   const int* __restrict__ pos_ids)
{
    __shared__ float sh[4][96];
    const int wid  = threadIdx.x >> 5;
    const int lane = threadIdx.x & 31;
    const int row  = blockIdx.x * 4 + wid;
    if (row >= QROWS + KROWS) return;

    const bool isK = (row >= QROWS);
    const int  r   = isK ? row - QROWS : row;
    const int  token = isK ? (r / KV_) : (r / H_);
    float* x = (isK ? kb : qb) + (size_t)r * 96;
    const float* w = isK ? kw : qw;

    float v0 = x[lane], v1 = x[lane + 32], v2 = x[lane + 64];
    float ss = v0 * v0 + v1 * v1 + v2 * v2;
#pragma unroll
    for (int o = 16; o; o >>= 1) ss += __shfl_xor_sync(0xffffffffu, ss, o);
    float inv = rsqrtf(ss * (1.0f / 96.0f) + 1e-6f);

    sh[wid][lane]      = v0 * inv * w[lane];
    sh[wid][lane + 32] = v1 * inv * w[lane + 32];
    sh[wid][lane + 64] = v2 * inv * w[lane + 64];
    __syncwarp();

    const int pos = pos_ids[token];
    const float* ct = g_cos + pos * 48;
    const float* st = g_sin + pos * 48;
#pragma unroll
    for (int q3 = 0; q3 < 3; q3++) {
        int d = lane + q3 * 32;
        int f = (d < 48) ? d : d - 48;
        float rh = (d < 48) ? -sh[wid][d + 48] : sh[wid][d - 48];
        float val = sh[wid][d] * ct[f] + rh * st[f];
        x[d] = isK ? __uint_as_float(f2tf32(val)) : val;
    }
}

// ---------------------------------------------------------------------------
// Tensor-core flash attention (tf32 MMA, pipelined via cp.async). R6 config.
// ---------------------------------------------------------------------------
#define QT128 128
#define KT64  64
#define QSTR 100
#define VSTR 136
#define PSTR 68
#define SM_QS   0
#define SM_KF   (128*QSTR)
#define SM_VF   (SM_KF + 2*64*QSTR)
#define SM_PS   (SM_VF + 2*64*VSTR)
#define ATTN_WORDS (SM_PS + 8*16*PSTR)

__global__ void __launch_bounds__(256) attn_tc_kernel()
{
    const int qt  = blockIdx.x;       // 0..15
    const int h   = blockIdx.y;
    const int b   = blockIdx.z;
    const int kvh = h >> 2;
    const int tid = threadIdx.x;
    const int w   = tid >> 5;
    const int lane = tid & 31;
    const int g   = lane >> 2;
    const int t   = lane & 3;
    const int wm  = w * 16;

    unsigned* ds_attn = ds_dyn;
    unsigned* Qs  = ds_attn + SM_QS;
    unsigned* Psw = ds_attn + SM_PS + w * 16 * PSTR;
    unsigned kf_s[2], vf_s[2];
    kf_s[0] = (unsigned)__cvta_generic_to_shared(ds_attn + SM_KF);
    kf_s[1] = kf_s[0] + 64 * QSTR * 4;
    vf_s[0] = (unsigned)__cvta_generic_to_shared(ds_attn + SM_VF);
    vf_s[1] = vf_s[0] + 64 * VSTR * 4;
    unsigned* Kf[2] = { ds_attn + SM_KF, ds_attn + SM_KF + 64 * QSTR };
    unsigned* Vf[2] = { ds_attn + SM_VF, ds_attn + SM_VF + 64 * VSTR };

    const float scale = 1.0f / sqrtf(96.0f);
    const float* kb0 = g_k + (size_t)(b * S_) * KN + kvh * KQD_;
    const float* vb0 = g_v + (size_t)(b * S_) * VN + kvh * VD_;

    const float* qbase = g_q + ((size_t)(b * S_ + qt * QT128)) * QN + h * KQD_;
    for (int it = tid; it < 128 * 24; it += 256) {
        int r = it / 24, c4 = (it % 24) * 4;
        float4 v = *(const float4*)(qbase + (size_t)r * QN + c4);
        uint4 u = make_uint4(f2tf32(v.x * scale), f2tf32(v.y * scale),
                             f2tf32(v.z * scale), f2tf32(v.w * scale));
        *(uint4*)&Qs[r * QSTR + c4] = u;
    }

    {
        const float* kbase = kb0;
        for (int it = tid; it < 64 * 24; it += 256) {
            int r = it / 24, c4 = (it % 24) * 4;
            cp_async16(kf_s[0] + (r * QSTR + c4) * 4, kbase + (size_t)r * KN + c4);
        }
        const float* vbase = vb0;
        for (int it = tid; it < 64 * 32; it += 256) {
            int r = it >> 5, c4 = (it & 31) * 4;
            cp_async16(vf_s[0] + (r * VSTR + c4) * 4, vbase + (size_t)r * VN + c4);
        }
        CP_COMMIT();
    }

    float o[16][4];
#pragma unroll
    for (int j = 0; j < 16; j++)
#pragma unroll
        for (int r = 0; r < 4; r++) o[j][r] = 0.f;
    float m0 = -INFINITY, m1 = -INFINITY, l0 = 0.f, l1 = 0.f;

    const int row0g = qt * QT128 + wm + g;
    const int row1g = row0g + 8;
    const int kt_max = 2 * qt + 1;

    for (int kt = 0; kt <= kt_max; kt++) {
        const int cur = kt & 1;
        if (kt < kt_max) {
            const int nb = (kt + 1) & 1;
            const float* kbase = kb0 + (size_t)(kt + 1) * KT64 * KN;
            for (int it = tid; it < 64 * 24; it += 256) {
                int r = it / 24, c4 = (it % 24) * 4;
                cp_async16(kf_s[nb] + (r * QSTR + c4) * 4, kbase + (size_t)r * KN + c4);
            }
            const float* vbase = vb0 + (size_t)(kt + 1) * KT64 * VN;
            for (int it = tid; it < 64 * 32; it += 256) {
                int r = it >> 5, c4 = (it & 31) * 4;
                cp_async16(vf_s[nb] + (r * VSTR + c4) * 4, vbase + (size_t)r * VN + c4);
            }
        }
        CP_COMMIT();
        CP_WAIT1();
        __syncthreads();

        if (KT64 * kt <= qt * QT128 + wm + 15) {
            const unsigned* Kc = Kf[cur];
            const unsigned* Vc = Vf[cur];

            float s[8][4];
#pragma unroll
            for (int j = 0; j < 8; j++)
#pragma unroll
                for (int r = 0; r < 4; r++) s[j][r] = 0.f;
#pragma unroll
            for (int k8 = 0; k8 < 96; k8 += 8) {
                unsigned af[4];
                af[0] = Qs[(wm + g    ) * QSTR + k8 + t    ];
                af[1] = Qs[(wm + g + 8) * QSTR + k8 + t    ];
                af[2] = Qs[(wm + g    ) * QSTR + k8 + t + 4];
                af[3] = Qs[(wm + g + 8) * QSTR + k8 + t + 4];
#pragma unroll
                for (int j = 0; j < 8; j++) {
                    unsigned bf[2];
                    bf[0] = Kc[(8 * j + g) * QSTR + k8 + t    ];
                    bf[1] = Kc[(8 * j + g) * QSTR + k8 + t + 4];
                    mma_tf32(s[j], af, bf);
                }
            }

            if (kt >= 2 * qt) {
#pragma unroll
                for (int j = 0; j < 8; j++) {
                    int c0 = kt * KT64 + 8 * j + 2 * t;
                    if (c0     > row0g) s[j][0] = -INFINITY;
                    if (c0 + 1 > row0g) s[j][1] = -INFINITY;
                    if (c0     > row1g) s[j][2] = -INFINITY;
                    if (c0 + 1 > row1g) s[j][3] = -INFINITY;
                }
            }

            float ml0 = -INFINITY, ml1 = -INFINITY;
#pragma unroll
            for (int j = 0; j < 8; j++) {
                ml0 = fmaxf(ml0, fmaxf(s[j][0], s[j][1]));
                ml1 = fmaxf(ml1, fmaxf(s[j][2], s[j][3]));
            }
            ml0 = fmaxf(ml0, __shfl_xor_sync(0xffffffffu, ml0, 1));
            ml0 = fmaxf(ml0, __shfl_xor_sync(0xffffffffu, ml0, 2));
            ml1 = fmaxf(ml1, __shfl_xor_sync(0xffffffffu, ml1, 1));
            ml1 = fmaxf(ml1, __shfl_xor_sync(0xffffffffu, ml1, 2));
            float mn0 = fmaxf(m0, ml0), mn1 = fmaxf(m1, ml1);
            float al0 = __expf(m0 - mn0), al1 = __expf(m1 - mn1);
            m0 = mn0; m1 = mn1;
            float sum0 = 0.f, sum1 = 0.f;
#pragma unroll
            for (int j = 0; j < 8; j++) {
                s[j][0] = __expf(s[j][0] - mn0); sum0 += s[j][0];
                s[j][1] = __expf(s[j][1] - mn0); sum0 += s[j][1];
                s[j][2] = __expf(s[j][2] - mn1); sum1 += s[j][2];
                s[j][3] = __expf(s[j][3] - mn1); sum1 += s[j][3];
            }
            sum0 += __shfl_xor_sync(0xffffffffu, sum0, 1);
            sum0 += __shfl_xor_sync(0xffffffffu, sum0, 2);
            sum1 += __shfl_xor_sync(0xffffffffu, sum1, 1);
            sum1 += __shfl_xor_sync(0xffffffffu, sum1, 2);
            l0 = l0 * al0 + sum0;
            l1 = l1 * al1 + sum1;
#pragma unroll
            for (int j = 0; j < 16; j++) {
                o[j][0] *= al0; o[j][1] *= al0;
                o[j][2] *= al1; o[j][3] *= al1;
            }

#pragma unroll
            for (int j = 0; j < 8; j++) {
                *(uint2*)&Psw[g * PSTR + 8 * j + 2 * t] =
                    make_uint2(f2tf32(s[j][0]), f2tf32(s[j][1]));
                *(uint2*)&Psw[(g + 8) * PSTR + 8 * j + 2 * t] =
                    make_uint2(f2tf32(s[j][2]), f2tf32(s[j][3]));
            }
            __syncwarp();

#pragma unroll
            for (int k8 = 0; k8 < 64; k8 += 8) {
                unsigned af[4];
                af[0] = Psw[(g    ) * PSTR + k8 + t    ];
                af[1] = Psw[(g + 8) * PSTR + k8 + t    ];
                af[2] = Psw[(g    ) * PSTR + k8 + t + 4];
                af[3] = Psw[(g + 8) * PSTR + k8 + t + 4];
#pragma unroll
                for (int jn = 0; jn < 16; jn++) {
                    unsigned bf[2];
                    bf[0] = Vc[(k8 + t    ) * VSTR + 8 * jn + g];
                    bf[1] = Vc[(k8 + t + 4) * VSTR + 8 * jn + g];
                    mma_tf32(o[jn], af, bf);
                }
            }
        }
        __syncthreads();
    }

    float inv0 = 1.0f / l0, inv1 = 1.0f / l1;
    float* ob = g_ao + ((size_t)(b * S_)) * ON + h * VD_;
    size_t r0 = (size_t)(qt * QT128 + wm + g);
    size_t r1 = r0 + 8;
#pragma unroll
    for (int jn = 0; jn < 16; jn++) {
        int col = 8 * jn + 2 * t;
        *(float2*)&ob[r0 * ON + col] = make_float2(o[jn][0] * inv0, o[jn][1] * inv0);
        *(float2*)&ob[r1 * ON + col] = make_float2(o[jn][2] * inv1, o[jn][3] * inv1);
    }
}

// ---------------------------------------------------------------------------
extern "C" void kernel_launch(void* const* d_in, const int* in_sizes, int n_in,
                              void* d_out, int out_size)
{
    const float* hidden = (const float*)d_in[0];
    const int*   pos    = (const int*)  d_in[1];
    const float* Wq     = (const float*)d_in[2];
    const float* Wk     = (const float*)d_in[3];
    const float* Wv     = (const float*)d_in[4];
    const float* Wo     = (const float*)d_in[5];
    const float* qw     = (const float*)d_in[6];
    const float* kw     = (const float*)d_in[7];
    float* out = (float*)d_out;

    void *pq, *pk, *pv, *pa;
    cudaGetSymbolAddress(&pq, g_q);
    cudaGetSymbolAddress(&pk, g_k);
    cudaGetSymbolAddress(&pv, g_v);
    cudaGetSymbolAddress(&pa, g_ao);
    float* qb = (float*)pq;
    float* kb = (float*)pk;
    float* vb = (float*)pv;
    float* ab = (float*)pa;

    static int smem_set = 0;
    if (!smem_set) {
        cudaFuncSetAttribute(attn_tc_kernel,
                             cudaFuncAttributeMaxDynamicSharedMemorySize,
                             ATTN_WORDS * 4);
        cudaFuncSetAttribute(sgemm_tf32,
                             cudaFuncAttributeMaxDynamicSharedMemorySize,
                             GEMM_SMEM_BYTES);
        cudaFuncSetAttribute(sgemm_qkv,
                             cudaFuncAttributeMaxDynamicSharedMemorySize,
                             GEMM_SMEM_BYTES);
        smem_set = 1;
    }

    // 1. inv_freq + RoPE table
    invf_kernel<<<1, 64>>>();
    rope_table_kernel<<<(S_ * 48 + 255) / 256, 256>>>();

    // 2. Fused QKV projection (cp.async pipelined GEMM)
    sgemm_qkv<<<dim3(19, TOK / 128), 256, GEMM_SMEM_BYTES>>>(
        hidden, Wq, Wk, Wv, qb, kb, vb);

    // 3. Fused RMSNorm + RoPE
    rmsnorm_rope_fused<<<(QROWS + KROWS) / 4, 128>>>(qb, kb, qw, kw, pos);

    // 4. Tensor-core flash attention (unchanged R6 config)
    attn_tc_kernel<<<dim3(S_ / QT128, H_, B_), 256, ATTN_WORDS * 4>>>();

    // 5. Output projection (cp.async pipelined GEMM)
    sgemm_tf32<<<dim3(D_ / 128, TOK / 128), 256, GEMM_SMEM_BYTES>>>(
        ab, Wo, out, TOK, D_, ON);
}

// round 9
// speedup vs baseline: 1.8323x; 1.1303x over previous
#include <cuda_runtime.h>
#include <math.h>

// Problem constants
#define B_   2
#define S_   2048
#define D_   2048
#define H_   16
#define KV_  4
#define KQD_ 96
#define VD_  128
#define TOK  (B_*S_)       // 4096
#define QN   (H_*KQD_)     // 1536
#define KN   (KV_*KQD_)    // 384
#define VN   (KV_*VD_)     // 512
#define ON   (H_*VD_)      // 2048

__device__ float g_q [TOK * QN];
__device__ float g_k [TOK * KN];
__device__ float g_v [TOK * VN];
__device__ float g_ao[TOK * ON];
__device__ float g_cos[S_ * 48];
__device__ float g_sin[S_ * 48];
__device__ double g_invf[48];
__device__ int    g_ctr;          // persistent-attention work counter

// Single dynamic-smem symbol shared by all kernels
extern __shared__ unsigned ds_dyn[];

// ---------------------------------------------------------------------------
__global__ void invf_kernel() {
    int j = threadIdx.x;
    if (j < 48) g_invf[j] = pow(10000.0, -(double)j / 48.0);
    if (j == 0) g_ctr = 0;        // reset work queue every replay
}

// RoPE table: pure fp32 float-pair pipeline.
__global__ void rope_table_kernel() {
    int i = blockIdx.x * blockDim.x + threadIdx.x;
    if (i >= S_ * 48) return;
    int pos = i / 48, j = i % 48;
    double d = g_invf[j];
    float hi = (float)d;
    float lo = (float)(d - (double)hi);
    float fp = (float)pos;
    float p  = fp * hi;
    float e  = fmaf(fp, hi, -p);
    float t2 = fmaf(fp, lo, e);
    const float INV2PI = 0.15915494309189535f;
    const float PIH    = 6.2831854820251465f;
    const float PIL    = -1.7484555314695172e-7f;
    float n = rintf(p * INV2PI);
    float r = fmaf(-n, PIH, p);
    r = fmaf(-n, PIL, r);
    r = r + t2;
    float s, c;
    sincosf(r, &s, &c);
    g_cos[i] = c;
    g_sin[i] = s;
}

// ---------------------------------------------------------------------------
__device__ __forceinline__ unsigned f2tf32(float x) {
    unsigned r;
    asm("cvt.rna.tf32.f32 %0, %1;" : "=r"(r) : "f"(x));
    return r;
}
__device__ __forceinline__ void mma_tf32(float* c, const unsigned* a, const unsigned* b) {
    asm volatile(
        "mma.sync.aligned.m16n8k8.row.col.f32.tf32.tf32.f32 "
        "{%0,%1,%2,%3}, {%4,%5,%6,%7}, {%8,%9}, {%0,%1,%2,%3};\n"
        : "+f"(c[0]), "+f"(c[1]), "+f"(c[2]), "+f"(c[3])
        : "r"(a[0]), "r"(a[1]), "r"(a[2]), "r"(a[3]),
          "r"(b[0]), "r"(b[1]));
}
__device__ __forceinline__ void cp_async16(unsigned saddr, const void* g) {
    asm volatile("cp.async.cg.shared.global [%0], [%1], 16;\n" :: "r"(saddr), "l"(g));
}
#define CP_COMMIT() asm volatile("cp.async.commit_group;\n" ::: "memory")
#define CP_WAIT0()  asm volatile("cp.async.wait_group 0;\n" ::: "memory")
#define CP_WAIT1()  asm volatile("cp.async.wait_group 1;\n" ::: "memory")
#define CP_WAIT2()  asm volatile("cp.async.wait_group 2;\n" ::: "memory")

// ---------------------------------------------------------------------------
// TF32 GEMM-NT core: cp.async 4-stage pipeline, raw fp32 in smem,
// row-major [row][GSTR] (GSTR=20 -> conflict-free fragment LDS),
// tf32 conversion at fragment load. 128x128 tile, BK=16, 256 threads.
// ---------------------------------------------------------------------------
#define BKT 16
#define GSTAGES 4
#define GSTR 20
#define GAHALF (128*GSTR)
#define GSTAGE_WORDS (2*GAHALF)
#define GEMM_SMEM_BYTES (GSTAGES*GSTAGE_WORDS*4)   // 81920

template<bool RND>
__device__ __forceinline__ void gemm_body(
    const float* __restrict__ A, const float* __restrict__ Bm,
    float* __restrict__ C, int N, int K, int bm, int bn, float* ds)
{
    const int tid  = threadIdx.x;
    const int warp = tid >> 5;
    const int lane = tid & 31;
    const int g    = lane >> 2;
    const int t    = lane & 3;
    const int wm   = (warp >> 2) * 64;
    const int wn   = (warp & 3) * 32;

    const int lrow = tid >> 1;
    const int lkc  = (tid & 1) * 8;
    const float* Ap = A  + (size_t)(bm + lrow) * K + lkc;
    const float* Bp = Bm + (size_t)(bn + lrow) * K + lkc;

    const unsigned sbase = (unsigned)__cvta_generic_to_shared(ds);
    const unsigned aoff  = (lrow * GSTR + lkc) * 4;
    const unsigned boff  = (GAHALF + lrow * GSTR + lkc) * 4;

    float acc[4][4][4];
#pragma unroll
    for (int i = 0; i < 4; i++)
#pragma unroll
        for (int j = 0; j < 4; j++)
#pragma unroll
            for (int r = 0; r < 4; r++) acc[i][j][r] = 0.f;

#pragma unroll
    for (int s = 0; s < GSTAGES - 1; s++) {
        unsigned sb = sbase + s * GSTAGE_WORDS * 4;
        cp_async16(sb + aoff,      Ap + s * BKT);
        cp_async16(sb + aoff + 16, Ap + s * BKT + 4);
        cp_async16(sb + boff,      Bp + s * BKT);
        cp_async16(sb + boff + 16, Bp + s * BKT + 4);
        CP_COMMIT();
    }

    const int nst = K / BKT;
    for (int ks = 0; ks < nst; ks++) {
        CP_WAIT2();
        __syncthreads();

        if (ks + GSTAGES - 1 < nst) {
            int slot = (ks + GSTAGES - 1) & 3;
            unsigned sb = sbase + slot * GSTAGE_WORDS * 4;
            const float* Ap2 = Ap + (size_t)(ks + GSTAGES - 1) * BKT;
            const float* Bp2 = Bp + (size_t)(ks + GSTAGES - 1) * BKT;
            cp_async16(sb + aoff,      Ap2);
            cp_async16(sb + aoff + 16, Ap2 + 4);
            cp_async16(sb + boff,      Bp2);
            cp_async16(sb + boff + 16, Bp2 + 4);
        }
        CP_COMMIT();

        const float* As = ds + (ks & 3) * GSTAGE_WORDS;
        const float* Bs = As + GAHALF;

#pragma unroll
        for (int kh = 0; kh < 2; kh++) {
            const int k8 = kh * 8;
            unsigned af[4][4], bf[4][2];
#pragma unroll
            for (int i = 0; i < 4; i++) {
                int m = wm + 16 * i;
                af[i][0] = f2tf32(As[(m + g    ) * GSTR + k8 + t    ]);
                af[i][1] = f2tf32(As[(m + g + 8) * GSTR + k8 + t    ]);
                af[i][2] = f2tf32(As[(m + g    ) * GSTR + k8 + t + 4]);
                af[i][3] = f2tf32(As[(m + g + 8) * GSTR + k8 + t + 4]);
            }
#pragma unroll
            for (int j = 0; j < 4; j++) {
                int n = wn + 8 * j;
                bf[j][0] = f2tf32(Bs[(n + g) * GSTR + k8 + t    ]);
                bf[j][1] = f2tf32(Bs[(n + g) * GSTR + k8 + t + 4]);
            }
#pragma unroll
            for (int i = 0; i < 4; i++)
#pragma unroll
                for (int j = 0; j < 4; j++)
                    mma_tf32(acc[i][j], af[i], bf[j]);
        }
    }

#pragma unroll
    for (int i = 0; i < 4; i++) {
#pragma unroll
        for (int j = 0; j < 4; j++) {
            size_t r0 = (size_t)(bm + wm + 16 * i + g);
            size_t col = (size_t)(bn + wn + 8 * j + 2 * t);
            float v0 = acc[i][j][0], v1 = acc[i][j][1];
            float v2 = acc[i][j][2], v3 = acc[i][j][3];
            if (RND) {
                v0 = __uint_as_float(f2tf32(v0)); v1 = __uint_as_float(f2tf32(v1));
                v2 = __uint_as_float(f2tf32(v2)); v3 = __uint_as_float(f2tf32(v3));
            }
            *(float2*)&C[r0 * N + col]       = make_float2(v0, v1);
            *(float2*)&C[(r0 + 8) * N + col] = make_float2(v2, v3);
        }
    }
}

// O projection — 2 CTAs/SM guaranteed
__global__ void __launch_bounds__(256, 2) sgemm_tf32(
    const float* __restrict__ A, const float* __restrict__ Bm,
    float* __restrict__ C, int M, int N, int K)
{
    gemm_body<false>(A, Bm, C, N, K, blockIdx.y << 7, blockIdx.x << 7,
                     (float*)ds_dyn);
}

// Fused QKV projection, compact grid: x in [0,19): 12 Q | 3 K | 4 V
__global__ void __launch_bounds__(256, 2) sgemm_qkv(
    const float* __restrict__ A,
    const float* __restrict__ Wq, const float* __restrict__ Wk,
    const float* __restrict__ Wv,
    float* __restrict__ qb, float* __restrict__ kb, float* __restrict__ vb)
{
    const int bx = blockIdx.x;
    const int bm = blockIdx.y << 7;
    float* ds = (float*)ds_dyn;
    if (bx < 12) {
        gemm_body<false>(A, Wq, qb, QN, D_, bm, bx << 7, ds);
    } else if (bx < 15) {
        gemm_body<false>(A, Wk, kb, KN, D_, bm, (bx - 12) << 7, ds);
    } else {
        gemm_body<true>(A, Wv, vb, VN, D_, bm, (bx - 15) << 7, ds);
    }
}

// ---------------------------------------------------------------------------
// Fused RMSNorm+RoPE over Q rows then K rows. K output rounded to tf32 bits.
// ---------------------------------------------------------------------------
#define QROWS (TOK * H_)
#define KROWS (TOK * KV_)

__global__ void rmsnorm_rope_fused(float* qb, float* kb,
                                   const float* __restrict__ qw,
                                   const float* __restrict__ kw,
                                   const int* __restrict__ pos_ids)
{
    __shared__ float sh[4][96];
    const int wid  = threadIdx.x >> 5;
    const int lane = threadIdx.x & 31;
    const int row  = blockIdx.x * 4 + wid;
    if (row >= QROWS + KROWS) return;

    const bool isK = (row >= QROWS);
    const int  r   = isK ? row - QROWS : row;
    const int  token = isK ? (r / KV_) : (r / H_);
    float* x = (isK ? kb : qb) + (size_t)r * 96;
    const float* w = isK ? kw : qw;

    float v0 = x[lane], v1 = x[lane + 32], v2 = x[lane + 64];
    float ss = v0 * v0 + v1 * v1 + v2 * v2;
#pragma unroll
    for (int o = 16; o; o >>= 1) ss += __shfl_xor_sync(0xffffffffu, ss, o);
    float inv = rsqrtf(ss * (1.0f / 96.0f) + 1e-6f);

    sh[wid][lane]      = v0 * inv * w[lane];
    sh[wid][lane + 32] = v1 * inv * w[lane + 32];
    sh[wid][lane + 64] = v2 * inv * w[lane + 64];
    __syncwarp();

    const int pos = pos_ids[token];
    const float* ct = g_cos + pos * 48;
    const float* st = g_sin + pos * 48;
#pragma unroll
    for (int q3 = 0; q3 < 3; q3++) {
        int d = lane + q3 * 32;
        int f = (d < 48) ? d : d - 48;
        float rh = (d < 48) ? -sh[wid][d + 48] : sh[wid][d - 48];
        float val = sh[wid][d] * ct[f] + rh * st[f];
        x[d] = isK ? __uint_as_float(f2tf32(val)) : val;
    }
}

// ---------------------------------------------------------------------------
// Tensor-core flash attention — PERSISTENT version.
// 152 CTAs (1/SM, 207KB smem). Work items (qt,h,b) pulled heavy-first
// (qt descending) from a global atomic counter. Math identical to R6.
// ---------------------------------------------------------------------------
#define QT128 128
#define KT64  64
#define QSTR 100
#define VSTR 136
#define PSTR 68
#define SM_QS   0
#define SM_KF   (128*QSTR)
#define SM_VF   (SM_KF + 2*64*QSTR)
#define SM_PS   (SM_VF + 2*64*VSTR)
#define ATTN_WORDS (SM_PS + 8*16*PSTR)
#define N_ITEMS (16 * H_ * B_)     // 512

__global__ void __launch_bounds__(256) attn_tc_kernel()
{
    const int tid = threadIdx.x;
    const int w   = tid >> 5;
    const int lane = tid & 31;
    const int g   = lane >> 2;
    const int t   = lane & 3;
    const int wm  = w * 16;

    unsigned* ds_attn = ds_dyn;
    unsigned* Qs  = ds_attn + SM_QS;
    unsigned* Psw = ds_attn + SM_PS + w * 16 * PSTR;
    unsigned kf_s[2], vf_s[2];
    kf_s[0] = (unsigned)__cvta_generic_to_shared(ds_attn + SM_KF);
    kf_s[1] = kf_s[0] + 64 * QSTR * 4;
    vf_s[0] = (unsigned)__cvta_generic_to_shared(ds_attn + SM_VF);
    vf_s[1] = vf_s[0] + 64 * VSTR * 4;
    unsigned* Kf[2] = { ds_attn + SM_KF, ds_attn + SM_KF + 64 * QSTR };
    unsigned* Vf[2] = { ds_attn + SM_VF, ds_attn + SM_VF + 64 * VSTR };

    const float scale = 1.0f / sqrtf(96.0f);
    __shared__ int s_item;

    for (;;) {
        if (tid == 0) s_item = atomicAdd(&g_ctr, 1);
        __syncthreads();
        const int item = s_item;
        if (item >= N_ITEMS) return;

        // heavy-first: qt descending
        const int qt = 15 - (item >> 5);
        const int hb = item & 31;
        const int h  = hb & 15;
        const int b  = hb >> 4;
        const int kvh = h >> 2;

        const float* kb0 = g_k + (size_t)(b * S_) * KN + kvh * KQD_;
        const float* vb0 = g_v + (size_t)(b * S_) * VN + kvh * VD_;

        // Load Q tile (scaled, tf32)
        const float* qbase = g_q + ((size_t)(b * S_ + qt * QT128)) * QN + h * KQD_;
        for (int it = tid; it < 128 * 24; it += 256) {
            int r = it / 24, c4 = (it % 24) * 4;
            float4 v = *(const float4*)(qbase + (size_t)r * QN + c4);
            uint4 u = make_uint4(f2tf32(v.x * scale), f2tf32(v.y * scale),
                                 f2tf32(v.z * scale), f2tf32(v.w * scale));
            *(uint4*)&Qs[r * QSTR + c4] = u;
        }

        // Prologue: async-load tile 0
        {
            const float* kbase = kb0;
            for (int it = tid; it < 64 * 24; it += 256) {
                int r = it / 24, c4 = (it % 24) * 4;
                cp_async16(kf_s[0] + (r * QSTR + c4) * 4, kbase + (size_t)r * KN + c4);
            }
            const float* vbase = vb0;
            for (int it = tid; it < 64 * 32; it += 256) {
                int r = it >> 5, c4 = (it & 31) * 4;
                cp_async16(vf_s[0] + (r * VSTR + c4) * 4, vbase + (size_t)r * VN + c4);
            }
            CP_COMMIT();
        }

        float o[16][4];
#pragma unroll
        for (int j = 0; j < 16; j++)
#pragma unroll
            for (int r = 0; r < 4; r++) o[j][r] = 0.f;
        float m0 = -INFINITY, m1 = -INFINITY, l0 = 0.f, l1 = 0.f;

        const int row0g = qt * QT128 + wm + g;
        const int row1g = row0g + 8;
        const int kt_max = 2 * qt + 1;

        for (int kt = 0; kt <= kt_max; kt++) {
            const int cur = kt & 1;
            if (kt < kt_max) {
                const int nb = (kt + 1) & 1;
                const float* kbase = kb0 + (size_t)(kt + 1) * KT64 * KN;
                for (int it = tid; it < 64 * 24; it += 256) {
                    int r = it / 24, c4 = (it % 24) * 4;
                    cp_async16(kf_s[nb] + (r * QSTR + c4) * 4, kbase + (size_t)r * KN + c4);
                }
                const float* vbase = vb0 + (size_t)(kt + 1) * KT64 * VN;
                for (int it = tid; it < 64 * 32; it += 256) {
                    int r = it >> 5, c4 = (it & 31) * 4;
                    cp_async16(vf_s[nb] + (r * VSTR + c4) * 4, vbase + (size_t)r * VN + c4);
                }
            }
            CP_COMMIT();
            CP_WAIT1();
            __syncthreads();

            if (KT64 * kt <= qt * QT128 + wm + 15) {
                const unsigned* Kc = Kf[cur];
                const unsigned* Vc = Vf[cur];

                float s[8][4];
#pragma unroll
                for (int j = 0; j < 8; j++)
#pragma unroll
                    for (int r = 0; r < 4; r++) s[j][r] = 0.f;
#pragma unroll
                for (int k8 = 0; k8 < 96; k8 += 8) {
                    unsigned af[4];
                    af[0] = Qs[(wm + g    ) * QSTR + k8 + t    ];
                    af[1] = Qs[(wm + g + 8) * QSTR + k8 + t    ];
                    af[2] = Qs[(wm + g    ) * QSTR + k8 + t + 4];
                    af[3] = Qs[(wm + g + 8) * QSTR + k8 + t + 4];
#pragma unroll
                    for (int j = 0; j < 8; j++) {
                        unsigned bf[2];
                        bf[0] = Kc[(8 * j + g) * QSTR + k8 + t    ];
                        bf[1] = Kc[(8 * j + g) * QSTR + k8 + t + 4];
                        mma_tf32(s[j], af, bf);
                    }
                }

                if (kt >= 2 * qt) {
#pragma unroll
                    for (int j = 0; j < 8; j++) {
                        int c0 = kt * KT64 + 8 * j + 2 * t;
                        if (c0     > row0g) s[j][0] = -INFINITY;
                        if (c0 + 1 > row0g) s[j][1] = -INFINITY;
                        if (c0     > row1g) s[j][2] = -INFINITY;
                        if (c0 + 1 > row1g) s[j][3] = -INFINITY;
                    }
                }

                float ml0 = -INFINITY, ml1 = -INFINITY;
#pragma unroll
                for (int j = 0; j < 8; j++) {
                    ml0 = fmaxf(ml0, fmaxf(s[j][0], s[j][1]));
                    ml1 = fmaxf(ml1, fmaxf(s[j][2], s[j][3]));
                }
                ml0 = fmaxf(ml0, __shfl_xor_sync(0xffffffffu, ml0, 1));
                ml0 = fmaxf(ml0, __shfl_xor_sync(0xffffffffu, ml0, 2));
                ml1 = fmaxf(ml1, __shfl_xor_sync(0xffffffffu, ml1, 1));
                ml1 = fmaxf(ml1, __shfl_xor_sync(0xffffffffu, ml1, 2));
                float mn0 = fmaxf(m0, ml0), mn1 = fmaxf(m1, ml1);
                float al0 = __expf(m0 - mn0), al1 = __expf(m1 - mn1);
                m0 = mn0; m1 = mn1;
                float sum0 = 0.f, sum1 = 0.f;
#pragma unroll
                for (int j = 0; j < 8; j++) {
                    s[j][0] = __expf(s[j][0] - mn0); sum0 += s[j][0];
                    s[j][1] = __expf(s[j][1] - mn0); sum0 += s[j][1];
                    s[j][2] = __expf(s[j][2] - mn1); sum1 += s[j][2];
                    s[j][3] = __expf(s[j][3] - mn1); sum1 += s[j][3];
                }
                sum0 += __shfl_xor_sync(0xffffffffu, sum0, 1);
                sum0 += __shfl_xor_sync(0xffffffffu, sum0, 2);
                sum1 += __shfl_xor_sync(0xffffffffu, sum1, 1);
                sum1 += __shfl_xor_sync(0xffffffffu, sum1, 2);
                l0 = l0 * al0 + sum0;
                l1 = l1 * al1 + sum1;
#pragma unroll
                for (int j = 0; j < 16; j++) {
                    o[j][0] *= al0; o[j][1] *= al0;
                    o[j][2] *= al1; o[j][3] *= al1;
                }

#pragma unroll
                for (int j = 0; j < 8; j++) {
                    *(uint2*)&Psw[g * PSTR + 8 * j + 2 * t] =
                        make_uint2(f2tf32(s[j][0]), f2tf32(s[j][1]));
                    *(uint2*)&Psw[(g + 8) * PSTR + 8 * j + 2 * t] =
                        make_uint2(f2tf32(s[j][2]), f2tf32(s[j][3]));
                }
                __syncwarp();

#pragma unroll
                for (int k8 = 0; k8 < 64; k8 += 8) {
                    unsigned af[4];
                    af[0] = Psw[(g    ) * PSTR + k8 + t    ];
                    af[1] = Psw[(g + 8) * PSTR + k8 + t    ];
                    af[2] = Psw[(g    ) * PSTR + k8 + t + 4];
                    af[3] = Psw[(g + 8) * PSTR + k8 + t + 4];
#pragma unroll
                    for (int jn = 0; jn < 16; jn++) {
                        unsigned bf[2];
                        bf[0] = Vc[(k8 + t    ) * VSTR + 8 * jn + g];
                        bf[1] = Vc[(k8 + t + 4) * VSTR + 8 * jn + g];
                        mma_tf32(o[jn], af, bf);
                    }
                }
            }
            __syncthreads();
        }

        // Epilogue
        float inv0 = 1.0f / l0, inv1 = 1.0f / l1;
        float* ob = g_ao + ((size_t)(b * S_)) * ON + h * VD_;
        size_t r0 = (size_t)(qt * QT128 + wm + g);
        size_t r1 = r0 + 8;
#pragma unroll
        for (int jn = 0; jn < 16; jn++) {
            int col = 8 * jn + 2 * t;
            *(float2*)&ob[r0 * ON + col] = make_float2(o[jn][0] * inv0, o[jn][1] * inv0);
            *(float2*)&ob[r1 * ON + col] = make_float2(o[jn][2] * inv1, o[jn][3] * inv1);
        }

        // Drain outstanding cp.async before buffers are reused for next item
        CP_WAIT0();
        __syncthreads();
    }
}

// ---------------------------------------------------------------------------
extern "C" void kernel_launch(void* const* d_in, const int* in_sizes, int n_in,
                              void* d_out, int out_size)
{
    const float* hidden = (const float*)d_in[0];
    const int*   pos    = (const int*)  d_in[1];
    const float* Wq     = (const float*)d_in[2];
    const float* Wk     = (const float*)d_in[3];
    const float* Wv     = (const float*)d_in[4];
    const float* Wo     = (const float*)d_in[5];
    const float* qw     = (const float*)d_in[6];
    const float* kw     = (const float*)d_in[7];
    float* out = (float*)d_out;

    void *pq, *pk, *pv, *pa;
    cudaGetSymbolAddress(&pq, g_q);
    cudaGetSymbolAddress(&pk, g_k);
    cudaGetSymbolAddress(&pv, g_v);
    cudaGetSymbolAddress(&pa, g_ao);
    float* qb = (float*)pq;
    float* kb = (float*)pk;
    float* vb = (float*)pv;
    float* ab = (float*)pa;

    static int smem_set = 0;
    if (!smem_set) {
        cudaFuncSetAttribute(attn_tc_kernel,
                             cudaFuncAttributeMaxDynamicSharedMemorySize,
                             ATTN_WORDS * 4);
        cudaFuncSetAttribute(sgemm_tf32,
                             cudaFuncAttributeMaxDynamicSharedMemorySize,
                             GEMM_SMEM_BYTES);
        cudaFuncSetAttribute(sgemm_qkv,
                             cudaFuncAttributeMaxDynamicSharedMemorySize,
                             GEMM_SMEM_BYTES);
        smem_set = 1;
    }

    // 1. inv_freq + work-counter reset + RoPE table
    invf_kernel<<<1, 64>>>();
    rope_table_kernel<<<(S_ * 48 + 255) / 256, 256>>>();

    // 2. Fused QKV projection (cp.async pipelined GEMM, 2 CTAs/SM)
    sgemm_qkv<<<dim3(19, TOK / 128), 256, GEMM_SMEM_BYTES>>>(
        hidden, Wq, Wk, Wv, qb, kb, vb);

    // 3. Fused RMSNorm + RoPE
    rmsnorm_rope_fused<<<(QROWS + KROWS) / 4, 128>>>(qb, kb, qw, kw, pos);

    // 4. Persistent tensor-core flash attention (152 CTAs = 1/SM on GB300)
    attn_tc_kernel<<<152, 256, ATTN_WORDS * 4>>>();

    // 5. Output projection (cp.async pipelined GEMM, 2 CTAs/SM)
    sgemm_tf32<<<dim3(D_ / 128, TOK / 128), 256, GEMM_SMEM_BYTES>>>(
        ab, Wo, out, TOK, D_, ON);
}

// round 10
// speedup vs baseline: 1.8372x; 1.0027x over previous
#include <cuda_runtime.h>
#include <math.h>

// Problem constants
#define B_   2
#define S_   2048
#define D_   2048
#define H_   16
#define KV_  4
#define KQD_ 96
#define VD_  128
#define TOK  (B_*S_)       // 4096
#define QN   (H_*KQD_)     // 1536
#define KN   (KV_*KQD_)    // 384
#define VN   (KV_*VD_)     // 512
#define ON   (H_*VD_)      // 2048

__device__ float g_q [TOK * QN];
__device__ float g_k [TOK * KN];
__device__ float g_v [TOK * VN];
__device__ float g_ao[TOK * ON];
__device__ float g_cos[S_ * 48];
__device__ float g_sin[S_ * 48];
__device__ double g_invf[48];
__device__ int    g_ctr;          // persistent-attention work counter

// Single dynamic-smem symbol shared by all kernels
extern __shared__ unsigned ds_dyn[];

// ---------------------------------------------------------------------------
// RoPE table: pure fp32 float-pair pipeline. Also resets the work counter.
// ---------------------------------------------------------------------------
__global__ void rope_table_kernel() {
    int i = blockIdx.x * blockDim.x + threadIdx.x;
    if (i == 0) g_ctr = 0;                    // reset work queue every replay
    if (i >= S_ * 48) return;
    int pos = i / 48, j = i % 48;
    double d = g_invf[j];
    float hi = (float)d;
    float lo = (float)(d - (double)hi);
    float fp = (float)pos;
    float p  = fp * hi;
    float e  = fmaf(fp, hi, -p);
    float t2 = fmaf(fp, lo, e);
    const float INV2PI = 0.15915494309189535f;
    const float PIH    = 6.2831854820251465f;
    const float PIL    = -1.7484555314695172e-7f;
    float n = rintf(p * INV2PI);
    float r = fmaf(-n, PIH, p);
    r = fmaf(-n, PIL, r);
    r = r + t2;
    float s, c;
    sincosf(r, &s, &c);
    g_cos[i] = c;
    g_sin[i] = s;
}

// ---------------------------------------------------------------------------
__device__ __forceinline__ unsigned f2tf32(float x) {
    unsigned r;
    asm("cvt.rna.tf32.f32 %0, %1;" : "=r"(r) : "f"(x));
    return r;
}
__device__ __forceinline__ void mma_tf32(float* c, const unsigned* a, const unsigned* b) {
    asm volatile(
        "mma.sync.aligned.m16n8k8.row.col.f32.tf32.tf32.f32 "
        "{%0,%1,%2,%3}, {%4,%5,%6,%7}, {%8,%9}, {%0,%1,%2,%3};\n"
        : "+f"(c[0]), "+f"(c[1]), "+f"(c[2]), "+f"(c[3])
        : "r"(a[0]), "r"(a[1]), "r"(a[2]), "r"(a[3]),
          "r"(b[0]), "r"(b[1]));
}
__device__ __forceinline__ void cp_async16(unsigned saddr, const void* g) {
    asm volatile("cp.async.cg.shared.global [%0], [%1], 16;\n" :: "r"(saddr), "l"(g));
}
#define CP_COMMIT() asm volatile("cp.async.commit_group;\n" ::: "memory")
#define CP_WAIT0()  asm volatile("cp.async.wait_group 0;\n" ::: "memory")
#define CP_WAIT1()  asm volatile("cp.async.wait_group 1;\n" ::: "memory")
#define CP_WAIT2()  asm volatile("cp.async.wait_group 2;\n" ::: "memory")

// ---------------------------------------------------------------------------
// TF32 GEMM-NT core: cp.async 4-stage pipeline, raw fp32 in smem,
// row-major [row][GSTR] (GSTR=20 -> conflict-free fragment LDS),
// tf32 conversion at fragment load. 128x128 tile, BK=16, 256 threads.
// ---------------------------------------------------------------------------
#define BKT 16
#define GSTAGES 4
#define GSTR 20
#define GAHALF (128*GSTR)
#define GSTAGE_WORDS (2*GAHALF)
#define GEMM_SMEM_BYTES (GSTAGES*GSTAGE_WORDS*4)   // 81920

template<bool RND>
__device__ __forceinline__ void gemm_body(
    const float* __restrict__ A, const float* __restrict__ Bm,
    float* __restrict__ C, int N, int K, int bm, int bn, float* ds)
{
    const int tid  = threadIdx.x;
    const int warp = tid >> 5;
    const int lane = tid & 31;
    const int g    = lane >> 2;
    const int t    = lane & 3;
    const int wm   = (warp >> 2) * 64;
    const int wn   = (warp & 3) * 32;

    const int lrow = tid >> 1;
    const int lkc  = (tid & 1) * 8;
    const float* Ap = A  + (size_t)(bm + lrow) * K + lkc;
    const float* Bp = Bm + (size_t)(bn + lrow) * K + lkc;

    const unsigned sbase = (unsigned)__cvta_generic_to_shared(ds);
    const unsigned aoff  = (lrow * GSTR + lkc) * 4;
    const unsigned boff  = (GAHALF + lrow * GSTR + lkc) * 4;

    float acc[4][4][4];
#pragma unroll
    for (int i = 0; i < 4; i++)
#pragma unroll
        for (int j = 0; j < 4; j++)
#pragma unroll
            for (int r = 0; r < 4; r++) acc[i][j][r] = 0.f;

#pragma unroll
    for (int s = 0; s < GSTAGES - 1; s++) {
        unsigned sb = sbase + s * GSTAGE_WORDS * 4;
        cp_async16(sb + aoff,      Ap + s * BKT);
        cp_async16(sb + aoff + 16, Ap + s * BKT + 4);
        cp_async16(sb + boff,      Bp + s * BKT);
        cp_async16(sb + boff + 16, Bp + s * BKT + 4);
        CP_COMMIT();
    }

    const int nst = K / BKT;
    for (int ks = 0; ks < nst; ks++) {
        CP_WAIT2();
        __syncthreads();

        if (ks + GSTAGES - 1 < nst) {
            int slot = (ks + GSTAGES - 1) & 3;
            unsigned sb = sbase + slot * GSTAGE_WORDS * 4;
            const float* Ap2 = Ap + (size_t)(ks + GSTAGES - 1) * BKT;
            const float* Bp2 = Bp + (size_t)(ks + GSTAGES - 1) * BKT;
            cp_async16(sb + aoff,      Ap2);
            cp_async16(sb + aoff + 16, Ap2 + 4);
            cp_async16(sb + boff,      Bp2);
            cp_async16(sb + boff + 16, Bp2 + 4);
        }
        CP_COMMIT();

        const float* As = ds + (ks & 3) * GSTAGE_WORDS;
        const float* Bs = As + GAHALF;

#pragma unroll
        for (int kh = 0; kh < 2; kh++) {
            const int k8 = kh * 8;
            unsigned af[4][4], bf[4][2];
#pragma unroll
            for (int i = 0; i < 4; i++) {
                int m = wm + 16 * i;
                af[i][0] = f2tf32(As[(m + g    ) * GSTR + k8 + t    ]);
                af[i][1] = f2tf32(As[(m + g + 8) * GSTR + k8 + t    ]);
                af[i][2] = f2tf32(As[(m + g    ) * GSTR + k8 + t + 4]);
                af[i][3] = f2tf32(As[(m + g + 8) * GSTR + k8 + t + 4]);
            }
#pragma unroll
            for (int j = 0; j < 4; j++) {
                int n = wn + 8 * j;
                bf[j][0] = f2tf32(Bs[(n + g) * GSTR + k8 + t    ]);
                bf[j][1] = f2tf32(Bs[(n + g) * GSTR + k8 + t + 4]);
            }
#pragma unroll
            for (int i = 0; i < 4; i++)
#pragma unroll
                for (int j = 0; j < 4; j++)
                    mma_tf32(acc[i][j], af[i], bf[j]);
        }
    }

#pragma unroll
    for (int i = 0; i < 4; i++) {
#pragma unroll
        for (int j = 0; j < 4; j++) {
            size_t r0 = (size_t)(bm + wm + 16 * i + g);
            size_t col = (size_t)(bn + wn + 8 * j + 2 * t);
            float v0 = acc[i][j][0], v1 = acc[i][j][1];
            float v2 = acc[i][j][2], v3 = acc[i][j][3];
            if (RND) {
                v0 = __uint_as_float(f2tf32(v0)); v1 = __uint_as_float(f2tf32(v1));
                v2 = __uint_as_float(f2tf32(v2)); v3 = __uint_as_float(f2tf32(v3));
            }
            *(float2*)&C[r0 * N + col]       = make_float2(v0, v1);
            *(float2*)&C[(r0 + 8) * N + col] = make_float2(v2, v3);
        }
    }
}

// O projection — 2 CTAs/SM guaranteed
__global__ void __launch_bounds__(256, 2) sgemm_tf32(
    const float* __restrict__ A, const float* __restrict__ Bm,
    float* __restrict__ C, int M, int N, int K)
{
    gemm_body<false>(A, Bm, C, N, K, blockIdx.y << 7, blockIdx.x << 7,
                     (float*)ds_dyn);
}

// Fused QKV projection, compact grid: x in [0,19): 12 Q | 3 K | 4 V
__global__ void __launch_bounds__(256, 2) sgemm_qkv(
    const float* __restrict__ A,
    const float* __restrict__ Wq, const float* __restrict__ Wk,
    const float* __restrict__ Wv,
    float* __restrict__ qb, float* __restrict__ kb, float* __restrict__ vb)
{
    const int bx = blockIdx.x;
    const int bm = blockIdx.y << 7;
    float* ds = (float*)ds_dyn;
    if (bx < 12) {
        gemm_body<false>(A, Wq, qb, QN, D_, bm, bx << 7, ds);
    } else if (bx < 15) {
        gemm_body<false>(A, Wk, kb, KN, D_, bm, (bx - 12) << 7, ds);
    } else {
        gemm_body<true>(A, Wv, vb, VN, D_, bm, (bx - 15) << 7, ds);
    }
}

// ---------------------------------------------------------------------------
// Fused RMSNorm+RoPE over Q rows then K rows. K output rounded to tf32 bits.
// ---------------------------------------------------------------------------
#define QROWS (TOK * H_)
#define KROWS (TOK * KV_)

__global__ void rmsnorm_rope_fused(float* qb, float* kb,
                                   const float* __restrict__ qw,
                                   const float* __restrict__ kw,
                                   const int* __restrict__ pos_ids)
{
    __shared__ float sh[4][96];
    const int wid  = threadIdx.x >> 5;
    const int lane = threadIdx.x & 31;
    const int row  = blockIdx.x * 4 + wid;
    if (row >= QROWS + KROWS) return;

    const bool isK = (row >= QROWS);
    const int  r   = isK ? row - QROWS : row;
    const int  token = isK ? (r / KV_) : (r / H_);
    float* x = (isK ? kb : qb) + (size_t)r * 96;
    const float* w = isK ? kw : qw;

    float v0 = x[lane], v1 = x[lane + 32], v2 = x[lane + 64];
    float ss = v0 * v0 + v1 * v1 + v2 * v2;
#pragma unroll
    for (int o = 16; o; o >>= 1) ss += __shfl_xor_sync(0xffffffffu, ss, o);
    float inv = rsqrtf(ss * (1.0f / 96.0f) + 1e-6f);

    sh[wid][lane]      = v0 * inv * w[lane];
    sh[wid][lane + 32] = v1 * inv * w[lane + 32];
    sh[wid][lane + 64] = v2 * inv * w[lane + 64];
    __syncwarp();

    const int pos = pos_ids[token];
    const float* ct = g_cos + pos * 48;
    const float* st = g_sin + pos * 48;
#pragma unroll
    for (int q3 = 0; q3 < 3; q3++) {
        int d = lane + q3 * 32;
        int f = (d < 48) ? d : d - 48;
        float rh = (d < 48) ? -sh[wid][d + 48] : sh[wid][d - 48];
        float val = sh[wid][d] * ct[f] + rh * st[f];
        x[d] = isK ? __uint_as_float(f2tf32(val)) : val;
    }
}

// ---------------------------------------------------------------------------
// Tensor-core flash attention — PERSISTENT (152 CTAs, heavy-first queue).
// K/V tile-0 prologue issued BEFORE the Q-tile load (overlap).
// ---------------------------------------------------------------------------
#define QT128 128
#define KT64  64
#define QSTR 100
#define VSTR 136
#define PSTR 68
#define SM_QS   0
#define SM_KF   (128*QSTR)
#define SM_VF   (SM_KF + 2*64*QSTR)
#define SM_PS   (SM_VF + 2*64*VSTR)
#define ATTN_WORDS (SM_PS + 8*16*PSTR)
#define N_ITEMS (16 * H_ * B_)     // 512

__global__ void __launch_bounds__(256) attn_tc_kernel()
{
    const int tid = threadIdx.x;
    const int w   = tid >> 5;
    const int lane = tid & 31;
    const int g   = lane >> 2;
    const int t   = lane & 3;
    const int wm  = w * 16;

    unsigned* ds_attn = ds_dyn;
    unsigned* Qs  = ds_attn + SM_QS;
    unsigned* Psw = ds_attn + SM_PS + w * 16 * PSTR;
    unsigned kf_s[2], vf_s[2];
    kf_s[0] = (unsigned)__cvta_generic_to_shared(ds_attn + SM_KF);
    kf_s[1] = kf_s[0] + 64 * QSTR * 4;
    vf_s[0] = (unsigned)__cvta_generic_to_shared(ds_attn + SM_VF);
    vf_s[1] = vf_s[0] + 64 * VSTR * 4;
    unsigned* Kf[2] = { ds_attn + SM_KF, ds_attn + SM_KF + 64 * QSTR };
    unsigned* Vf[2] = { ds_attn + SM_VF, ds_attn + SM_VF + 64 * VSTR };

    const float scale = 1.0f / sqrtf(96.0f);
    __shared__ int s_item;

    for (;;) {
        if (tid == 0) s_item = atomicAdd(&g_ctr, 1);
        __syncthreads();
        const int item = s_item;
        if (item >= N_ITEMS) return;

        const int qt = 15 - (item >> 5);      // heavy-first
        const int hb = item & 31;
        const int h  = hb & 15;
        const int b  = hb >> 4;
        const int kvh = h >> 2;

        const float* kb0 = g_k + (size_t)(b * S_) * KN + kvh * KQD_;
        const float* vb0 = g_v + (size_t)(b * S_) * VN + kvh * VD_;

        // Prologue FIRST: async-load K/V tile 0 (overlaps with Q load below)
        {
            const float* kbase = kb0;
            for (int it = tid; it < 64 * 24; it += 256) {
                int r = it / 24, c4 = (it % 24) * 4;
                cp_async16(kf_s[0] + (r * QSTR + c4) * 4, kbase + (size_t)r * KN + c4);
            }
            const float* vbase = vb0;
            for (int it = tid; it < 64 * 32; it += 256) {
                int r = it >> 5, c4 = (it & 31) * 4;
                cp_async16(vf_s[0] + (r * VSTR + c4) * 4, vbase + (size_t)r * VN + c4);
            }
            CP_COMMIT();
        }

        // Load Q tile (scaled, tf32) — overlapped with tile-0 cp.async
        const float* qbase = g_q + ((size_t)(b * S_ + qt * QT128)) * QN + h * KQD_;
        for (int it = tid; it < 128 * 24; it += 256) {
            int r = it / 24, c4 = (it % 24) * 4;
            float4 v = *(const float4*)(qbase + (size_t)r * QN + c4);
            uint4 u = make_uint4(f2tf32(v.x * scale), f2tf32(v.y * scale),
                                 f2tf32(v.z * scale), f2tf32(v.w * scale));
            *(uint4*)&Qs[r * QSTR + c4] = u;
        }

        float o[16][4];
#pragma unroll
        for (int j = 0; j < 16; j++)
#pragma unroll
            for (int r = 0; r < 4; r++) o[j][r] = 0.f;
        float m0 = -INFINITY, m1 = -INFINITY, l0 = 0.f, l1 = 0.f;

        const int row0g = qt * QT128 + wm + g;
        const int row1g = row0g + 8;
        const int kt_max = 2 * qt + 1;

        for (int kt = 0; kt <= kt_max; kt++) {
            const int cur = kt & 1;
            if (kt < kt_max) {
                const int nb = (kt + 1) & 1;
                const float* kbase = kb0 + (size_t)(kt + 1) * KT64 * KN;
                for (int it = tid; it < 64 * 24; it += 256) {
                    int r = it / 24, c4 = (it % 24) * 4;
                    cp_async16(kf_s[nb] + (r * QSTR + c4) * 4, kbase + (size_t)r * KN + c4);
                }
                const float* vbase = vb0 + (size_t)(kt + 1) * KT64 * VN;
                for (int it = tid; it < 64 * 32; it += 256) {
                    int r = it >> 5, c4 = (it & 31) * 4;
                    cp_async16(vf_s[nb] + (r * VSTR + c4) * 4, vbase + (size_t)r * VN + c4);
                }
            }
            CP_COMMIT();
            CP_WAIT1();
            __syncthreads();

            if (KT64 * kt <= qt * QT128 + wm + 15) {
                const unsigned* Kc = Kf[cur];
                const unsigned* Vc = Vf[cur];

                float s[8][4];
#pragma unroll
                for (int j = 0; j < 8; j++)
#pragma unroll
                    for (int r = 0; r < 4; r++) s[j][r] = 0.f;
#pragma unroll
                for (int k8 = 0; k8 < 96; k8 += 8) {
                    unsigned af[4];
                    af[0] = Qs[(wm + g    ) * QSTR + k8 + t    ];
                    af[1] = Qs[(wm + g + 8) * QSTR + k8 + t    ];
                    af[2] = Qs[(wm + g    ) * QSTR + k8 + t + 4];
                    af[3] = Qs[(wm + g + 8) * QSTR + k8 + t + 4];
#pragma unroll
                    for (int j = 0; j < 8; j++) {
                        unsigned bf[2];
                        bf[0] = Kc[(8 * j + g) * QSTR + k8 + t    ];
                        bf[1] = Kc[(8 * j + g) * QSTR + k8 + t + 4];
                        mma_tf32(s[j], af, bf);
                    }
                }

                if (kt >= 2 * qt) {
#pragma unroll
                    for (int j = 0; j < 8; j++) {
                        int c0 = kt * KT64 + 8 * j + 2 * t;
                        if (c0     > row0g) s[j][0] = -INFINITY;
                        if (c0 + 1 > row0g) s[j][1] = -INFINITY;
                        if (c0     > row1g) s[j][2] = -INFINITY;
                        if (c0 + 1 > row1g) s[j][3] = -INFINITY;
                    }
                }

                float ml0 = -INFINITY, ml1 = -INFINITY;
#pragma unroll
                for (int j = 0; j < 8; j++) {
                    ml0 = fmaxf(ml0, fmaxf(s[j][0], s[j][1]));
                    ml1 = fmaxf(ml1, fmaxf(s[j][2], s[j][3]));
                }
                ml0 = fmaxf(ml0, __shfl_xor_sync(0xffffffffu, ml0, 1));
                ml0 = fmaxf(ml0, __shfl_xor_sync(0xffffffffu, ml0, 2));
                ml1 = fmaxf(ml1, __shfl_xor_sync(0xffffffffu, ml1, 1));
                ml1 = fmaxf(ml1, __shfl_xor_sync(0xffffffffu, ml1, 2));
                float mn0 = fmaxf(m0, ml0), mn1 = fmaxf(m1, ml1);
                float al0 = __expf(m0 - mn0), al1 = __expf(m1 - mn1);
                m0 = mn0; m1 = mn1;
                float sum0 = 0.f, sum1 = 0.f;
#pragma unroll
                for (int j = 0; j < 8; j++) {
                    s[j][0] = __expf(s[j][0] - mn0); sum0 += s[j][0];
                    s[j][1] = __expf(s[j][1] - mn0); sum0 += s[j][1];
                    s[j][2] = __expf(s[j][2] - mn1); sum1 += s[j][2];
                    s[j][3] = __expf(s[j][3] - mn1); sum1 += s[j][3];
                }
                sum0 += __shfl_xor_sync(0xffffffffu, sum0, 1);
                sum0 += __shfl_xor_sync(0xffffffffu, sum0, 2);
                sum1 += __shfl_xor_sync(0xffffffffu, sum1, 1);
                sum1 += __shfl_xor_sync(0xffffffffu, sum1, 2);
                l0 = l0 * al0 + sum0;
                l1 = l1 * al1 + sum1;
#pragma unroll
                for (int j = 0; j < 16; j++) {
                    o[j][0] *= al0; o[j][1] *= al0;
                    o[j][2] *= al1; o[j][3] *= al1;
                }

#pragma unroll
                for (int j = 0; j < 8; j++) {
                    *(uint2*)&Psw[g * PSTR + 8 * j + 2 * t] =
                        make_uint2(f2tf32(s[j][0]), f2tf32(s[j][1]));
                    *(uint2*)&Psw[(g + 8) * PSTR + 8 * j + 2 * t] =
                        make_uint2(f2tf32(s[j][2]), f2tf32(s[j][3]));
                }
                __syncwarp();

#pragma unroll
                for (int k8 = 0; k8 < 64; k8 += 8) {
                    unsigned af[4];
                    af[0] = Psw[(g    ) * PSTR + k8 + t    ];
                    af[1] = Psw[(g + 8) * PSTR + k8 + t    ];
                    af[2] = Psw[(g    ) * PSTR + k8 + t + 4];
                    af[3] = Psw[(g + 8) * PSTR + k8 + t + 4];
#pragma unroll
                    for (int jn = 0; jn < 16; jn++) {
                        unsigned bf[2];
                        bf[0] = Vc[(k8 + t    ) * VSTR + 8 * jn + g];
                        bf[1] = Vc[(k8 + t + 4) * VSTR + 8 * jn + g];
                        mma_tf32(o[jn], af, bf);
                    }
                }
            }
            __syncthreads();
        }

        // Epilogue
        float inv0 = 1.0f / l0, inv1 = 1.0f / l1;
        float* ob = g_ao + ((size_t)(b * S_)) * ON + h * VD_;
        size_t r0 = (size_t)(qt * QT128 + wm + g);
        size_t r1 = r0 + 8;
#pragma unroll
        for (int jn = 0; jn < 16; jn++) {
            int col = 8 * jn + 2 * t;
            *(float2*)&ob[r0 * ON + col] = make_float2(o[jn][0] * inv0, o[jn][1] * inv0);
            *(float2*)&ob[r1 * ON + col] = make_float2(o[jn][2] * inv1, o[jn][3] * inv1);
        }

        CP_WAIT0();
        __syncthreads();
    }
}

// ---------------------------------------------------------------------------
extern "C" void kernel_launch(void* const* d_in, const int* in_sizes, int n_in,
                              void* d_out, int out_size)
{
    const float* hidden = (const float*)d_in[0];
    const int*   pos    = (const int*)  d_in[1];
    const float* Wq     = (const float*)d_in[2];
    const float* Wk     = (const float*)d_in[3];
    const float* Wv     = (const float*)d_in[4];
    const float* Wo     = (const float*)d_in[5];
    const float* qw     = (const float*)d_in[6];
    const float* kw     = (const float*)d_in[7];
    float* out = (float*)d_out;

    void *pq, *pk, *pv, *pa;
    cudaGetSymbolAddress(&pq, g_q);
    cudaGetSymbolAddress(&pk, g_k);
    cudaGetSymbolAddress(&pv, g_v);
    cudaGetSymbolAddress(&pa, g_ao);
    float* qb = (float*)pq;
    float* kb = (float*)pk;
    float* vb = (float*)pv;
    float* ab = (float*)pa;

    // Host-side constants (computed once; async-copied each call — capturable)
    static double h_invf[48];
    static int init_done = 0;
    if (!init_done) {
        for (int j = 0; j < 48; j++) h_invf[j] = pow(10000.0, -(double)j / 48.0);
        cudaFuncSetAttribute(attn_tc_kernel,
                             cudaFuncAttributeMaxDynamicSharedMemorySize,
                             ATTN_WORDS * 4);
        cudaFuncSetAttribute(sgemm_tf32,
                             cudaFuncAttributeMaxDynamicSharedMemorySize,
                             GEMM_SMEM_BYTES);
        cudaFuncSetAttribute(sgemm_qkv,
                             cudaFuncAttributeMaxDynamicSharedMemorySize,
                             GEMM_SMEM_BYTES);
        init_done = 1;
    }
    cudaMemcpyToSymbolAsync(g_invf, h_invf, sizeof(h_invf), 0,
                            cudaMemcpyHostToDevice);

    // 1. RoPE table (+ work-counter reset)
    rope_table_kernel<<<(S_ * 48 + 255) / 256, 256>>>();

    // 2. Fused QKV projection (cp.async pipelined GEMM, 2 CTAs/SM)
    sgemm_qkv<<<dim3(19, TOK / 128), 256, GEMM_SMEM_BYTES>>>(
        hidden, Wq, Wk, Wv, qb, kb, vb);

    // 3. Fused RMSNorm + RoPE
    rmsnorm_rope_fused<<<(QROWS + KROWS) / 4, 128>>>(qb, kb, qw, kw, pos);

    // 4. Persistent tensor-core flash attention
    attn_tc_kernel<<<152, 256, ATTN_WORDS * 4>>>();

    // 5. Output projection (cp.async pipelined GEMM, 2 CTAs/SM)
    sgemm_tf32<<<dim3(D_ / 128, TOK / 128), 256, GEMM_SMEM_BYTES>>>(
        ab, Wo, out, TOK, D_, ON);
}

// round 14
// speedup vs baseline: 1.8760x; 1.0211x over previous
#include <cuda_runtime.h>
#include <math.h>

// Problem constants
#define B_   2
#define S_   2048
#define D_   2048
#define H_   16
#define KV_  4
#define KQD_ 96
#define VD_  128
#define TOK  (B_*S_)       // 4096
#define QN   (H_*KQD_)     // 1536
#define KN   (KV_*KQD_)    // 384
#define VN   (KV_*VD_)     // 512
#define ON   (H_*VD_)      // 2048

__device__ float g_q [TOK * QN];
__device__ float g_k [TOK * KN];
__device__ float g_v [TOK * VN];
__device__ float g_ao[TOK * ON];
__device__ float g_cos[S_ * 48];
__device__ float g_sin[S_ * 48];
__device__ double g_invf[48];
__device__ int    g_ctr;

// Pre-rounded (tf32-bit) copies of inputs — filled by round_inputs
__device__ float g_hid[TOK * D_];     // 33.5 MB
__device__ float g_wq [QN * D_];      // 12.6 MB
__device__ float g_wk [KN * D_];      //  3.1 MB
__device__ float g_wv [VN * D_];      //  4.2 MB
__device__ float g_wo [D_ * ON];      // 16.8 MB

extern __shared__ unsigned ds_dyn[];

// ---------------------------------------------------------------------------
__device__ __forceinline__ unsigned f2tf32(float x) {
    unsigned r;
    asm("cvt.rna.tf32.f32 %0, %1;" : "=r"(r) : "f"(x));
    return r;
}
__device__ __forceinline__ float rndf(float x) {
    return __uint_as_float(f2tf32(x));
}
__device__ __forceinline__ float4 rnd4(float4 v) {
    return make_float4(rndf(v.x), rndf(v.y), rndf(v.z), rndf(v.w));
}
__device__ __forceinline__ void mma_tf32(float* c, const unsigned* a, const unsigned* b) {
    asm volatile(
        "mma.sync.aligned.m16n8k8.row.col.f32.tf32.tf32.f32 "
        "{%0,%1,%2,%3}, {%4,%5,%6,%7}, {%8,%9}, {%0,%1,%2,%3};\n"
        : "+f"(c[0]), "+f"(c[1]), "+f"(c[2]), "+f"(c[3])
        : "r"(a[0]), "r"(a[1]), "r"(a[2]), "r"(a[3]),
          "r"(b[0]), "r"(b[1]));
}
__device__ __forceinline__ void cp_async16(unsigned saddr, const void* g) {
    asm volatile("cp.async.cg.shared.global [%0], [%1], 16;\n" :: "r"(saddr), "l"(g));
}
#define CP_COMMIT() asm volatile("cp.async.commit_group;\n" ::: "memory")
#define CP_WAIT0()  asm volatile("cp.async.wait_group 0;\n" ::: "memory")
#define CP_WAIT1()  asm volatile("cp.async.wait_group 1;\n" ::: "memory")
#define CP_WAIT2()  asm volatile("cp.async.wait_group 2;\n" ::: "memory")

// ---------------------------------------------------------------------------
// Round all GEMM inputs to tf32 bits once (idempotent, bitwise = old cvt path)
// ---------------------------------------------------------------------------
#define N4H  (TOK * D_ / 4)
#define N4WQ (QN * D_ / 4)
#define N4WK (KN * D_ / 4)
#define N4WV (VN * D_ / 4)
#define N4WO (D_ * ON / 4)
#define N4TOT (N4H + N4WQ + N4WK + N4WV + N4WO)

__global__ void round_inputs(const float4* __restrict__ hid,
                             const float4* __restrict__ wq,
                             const float4* __restrict__ wk,
                             const float4* __restrict__ wv,
                             const float4* __restrict__ wo)
{
    int i = blockIdx.x * blockDim.x + threadIdx.x;
    if (i >= N4TOT) return;
    if (i < N4H) {
        ((float4*)g_hid)[i] = rnd4(hid[i]);
    } else if (i < N4H + N4WQ) {
        int j = i - N4H;               ((float4*)g_wq)[j] = rnd4(wq[j]);
    } else if (i < N4H + N4WQ + N4WK) {
        int j = i - N4H - N4WQ;        ((float4*)g_wk)[j] = rnd4(wk[j]);
    } else if (i < N4H + N4WQ + N4WK + N4WV) {
        int j = i - N4H - N4WQ - N4WK; ((float4*)g_wv)[j] = rnd4(wv[j]);
    } else {
        int j = i - N4H - N4WQ - N4WK - N4WV; ((float4*)g_wo)[j] = rnd4(wo[j]);
    }
}

// ---------------------------------------------------------------------------
// RoPE table (fp32 float-pair pipeline) + work-counter reset
// ---------------------------------------------------------------------------
__global__ void rope_table_kernel() {
    int i = blockIdx.x * blockDim.x + threadIdx.x;
    if (i == 0) g_ctr = 0;
    if (i >= S_ * 48) return;
    int pos = i / 48, j = i % 48;
    double d = g_invf[j];
    float hi = (float)d;
    float lo = (float)(d - (double)hi);
    float fp = (float)pos;
    float p  = fp * hi;
    float e  = fmaf(fp, hi, -p);
    float t2 = fmaf(fp, lo, e);
    const float INV2PI = 0.15915494309189535f;
    const float PIH    = 6.2831854820251465f;
    const float PIL    = -1.7484555314695172e-7f;
    float n = rintf(p * INV2PI);
    float r = fmaf(-n, PIH, p);
    r = fmaf(-n, PIL, r);
    r = r + t2;
    float s, c;
    sincosf(r, &s, &c);
    g_cos[i] = c;
    g_sin[i] = s;
}

// ---------------------------------------------------------------------------
// TF32 GEMM-NT core: cp.async 4-stage pipeline. Operands PRE-ROUNDED in gmem
// -> fragment loads are raw LDS (no cvt in the hot loop).
// ---------------------------------------------------------------------------
#define BKT 16
#define GSTAGES 4
#define GSTR 20
#define GAHALF (128*GSTR)
#define GSTAGE_WORDS (2*GAHALF)
#define GEMM_SMEM_BYTES (GSTAGES*GSTAGE_WORDS*4)   // 81920

template<bool RND>
__device__ __forceinline__ void gemm_body(
    const float* __restrict__ A, const float* __restrict__ Bm,
    float* __restrict__ C, int N, int K, int bm, int bn, float* ds)
{
    const int tid  = threadIdx.x;
    const int warp = tid >> 5;
    const int lane = tid & 31;
    const int g    = lane >> 2;
    const int t    = lane & 3;
    const int wm   = (warp >> 2) * 64;
    const int wn   = (warp & 3) * 32;

    const int lrow = tid >> 1;
    const int lkc  = (tid & 1) * 8;
    const float* Ap = A  + (size_t)(bm + lrow) * K + lkc;
    const float* Bp = Bm + (size_t)(bn + lrow) * K + lkc;

    const unsigned sbase = (unsigned)__cvta_generic_to_shared(ds);
    const unsigned aoff  = (lrow * GSTR + lkc) * 4;
    const unsigned boff  = (GAHALF + lrow * GSTR + lkc) * 4;

    float acc[4][4][4];
#pragma unroll
    for (int i = 0; i < 4; i++)
#pragma unroll
        for (int j = 0; j < 4; j++)
#pragma unroll
            for (int r = 0; r < 4; r++) acc[i][j][r] = 0.f;

#pragma unroll
    for (int s = 0; s < GSTAGES - 1; s++) {
        unsigned sb = sbase + s * GSTAGE_WORDS * 4;
        cp_async16(sb + aoff,      Ap + s * BKT);
        cp_async16(sb + aoff + 16, Ap + s * BKT + 4);
        cp_async16(sb + boff,      Bp + s * BKT);
        cp_async16(sb + boff + 16, Bp + s * BKT + 4);
        CP_COMMIT();
    }

    const int nst = K / BKT;
    for (int ks = 0; ks < nst; ks++) {
        CP_WAIT2();
        __syncthreads();

        if (ks + GSTAGES - 1 < nst) {
            int slot = (ks + GSTAGES - 1) & 3;
            unsigned sb = sbase + slot * GSTAGE_WORDS * 4;
            const float* Ap2 = Ap + (size_t)(ks + GSTAGES - 1) * BKT;
            const float* Bp2 = Bp + (size_t)(ks + GSTAGES - 1) * BKT;
            cp_async16(sb + aoff,      Ap2);
            cp_async16(sb + aoff + 16, Ap2 + 4);
            cp_async16(sb + boff,      Bp2);
            cp_async16(sb + boff + 16, Bp2 + 4);
        }
        CP_COMMIT();

        const unsigned* As = (const unsigned*)(ds + (ks & 3) * GSTAGE_WORDS);
        const unsigned* Bs = As + GAHALF;

#pragma unroll
        for (int kh = 0; kh < 2; kh++) {
            const int k8 = kh * 8;
            unsigned af[4][4], bf[4][2];
#pragma unroll
            for (int i = 0; i < 4; i++) {
                int m = wm + 16 * i;
                af[i][0] = As[(m + g    ) * GSTR + k8 + t    ];
                af[i][1] = As[(m + g + 8) * GSTR + k8 + t    ];
                af[i][2] = As[(m + g    ) * GSTR + k8 + t + 4];
                af[i][3] = As[(m + g + 8) * GSTR + k8 + t + 4];
            }
#pragma unroll
            for (int j = 0; j < 4; j++) {
                int n = wn + 8 * j;
                bf[j][0] = Bs[(n + g) * GSTR + k8 + t    ];
                bf[j][1] = Bs[(n + g) * GSTR + k8 + t + 4];
            }
#pragma unroll
            for (int i = 0; i < 4; i++)
#pragma unroll
                for (int j = 0; j < 4; j++)
                    mma_tf32(acc[i][j], af[i], bf[j]);
        }
    }

#pragma unroll
    for (int i = 0; i < 4; i++) {
#pragma unroll
        for (int j = 0; j < 4; j++) {
            size_t r0 = (size_t)(bm + wm + 16 * i + g);
            size_t col = (size_t)(bn + wn + 8 * j + 2 * t);
            float v0 = acc[i][j][0], v1 = acc[i][j][1];
            float v2 = acc[i][j][2], v3 = acc[i][j][3];
            if (RND) {
                v0 = rndf(v0); v1 = rndf(v1);
                v2 = rndf(v2); v3 = rndf(v3);
            }
            *(float2*)&C[r0 * N + col]       = make_float2(v0, v1);
            *(float2*)&C[(r0 + 8) * N + col] = make_float2(v2, v3);
        }
    }
}

// O projection — inputs pre-rounded (ao rounded at attention epilogue)
__global__ void __launch_bounds__(256, 2) sgemm_tf32(
    const float* __restrict__ A, const float* __restrict__ Bm,
    float* __restrict__ C, int M, int N, int K)
{
    gemm_body<false>(A, Bm, C, N, K, blockIdx.y << 7, blockIdx.x << 7,
                     (float*)ds_dyn);
}

// Fused QKV projection: x in [0,19): 12 Q | 3 K | 4 V (V output tf32-rounded)
__global__ void __launch_bounds__(256, 2) sgemm_qkv(
    float* __restrict__ qb, float* __restrict__ kb, float* __restrict__ vb)
{
    const int bx = blockIdx.x;
    const int bm = blockIdx.y << 7;
    float* ds = (float*)ds_dyn;
    if (bx < 12) {
        gemm_body<false>(g_hid, g_wq, qb, QN, D_, bm, bx << 7, ds);
    } else if (bx < 15) {
        gemm_body<false>(g_hid, g_wk, kb, KN, D_, bm, (bx - 12) << 7, ds);
    } else {
        gemm_body<true>(g_hid, g_wv, vb, VN, D_, bm, (bx - 15) << 7, ds);
    }
}

// ---------------------------------------------------------------------------
// Fused RMSNorm+RoPE over Q rows then K rows. K output rounded to tf32 bits.
// ---------------------------------------------------------------------------
#define QROWS (TOK * H_)
#define KROWS (TOK * KV_)

__global__ void rmsnorm_rope_fused(float* qb, float* kb,
                                   const float* __restrict__ qw,
                                   const float* __restrict__ kw,
                                   const int* __restrict__ pos_ids)
{
    __shared__ float sh[4][96];
    const int wid  = threadIdx.x >> 5;
    const int lane = threadIdx.x & 31;
    const int row  = blockIdx.x * 4 + wid;
    if (row >= QROWS + KROWS) return;

    const bool isK = (row >= QROWS);
    const int  r   = isK ? row - QROWS : row;
    const int  token = isK ? (r / KV_) : (r / H_);
    float* x = (isK ? kb : qb) + (size_t)r * 96;
    const float* w = isK ? kw : qw;

    float v0 = x[lane], v1 = x[lane + 32], v2 = x[lane + 64];
    float ss = v0 * v0 + v1 * v1 + v2 * v2;
#pragma unroll
    for (int o = 16; o; o >>= 1) ss += __shfl_xor_sync(0xffffffffu, ss, o);
    float inv = rsqrtf(ss * (1.0f / 96.0f) + 1e-6f);

    sh[wid][lane]      = v0 * inv * w[lane];
    sh[wid][lane + 32] = v1 * inv * w[lane + 32];
    sh[wid][lane + 64] = v2 * inv * w[lane + 64];
    __syncwarp();

    const int pos = pos_ids[token];
    const float* ct = g_cos + pos * 48;
    const float* st = g_sin + pos * 48;
#pragma unroll
    for (int q3 = 0; q3 < 3; q3++) {
        int d = lane + q3 * 32;
        int f = (d < 48) ? d : d - 48;
        float rh = (d < 48) ? -sh[wid][d + 48] : sh[wid][d - 48];
        float val = sh[wid][d] * ct[f] + rh * st[f];
        x[d] = isK ? rndf(val) : val;
    }
}

// ---------------------------------------------------------------------------
// Tensor-core flash attention — PERSISTENT (152 CTAs, heavy-first queue).
// Epilogue rounds ao to tf32 bits (feeds cvt-free O projection).
// ---------------------------------------------------------------------------
#define QT128 128
#define KT64  64
#define QSTR 100
#define VSTR 136
#define PSTR 68
#define SM_QS   0
#define SM_KF   (128*QSTR)
#define SM_VF   (SM_KF + 2*64*QSTR)
#define SM_PS   (SM_VF + 2*64*VSTR)
#define ATTN_WORDS (SM_PS + 8*16*PSTR)
#define N_ITEMS (16 * H_ * B_)     // 512

__global__ void __launch_bounds__(256) attn_tc_kernel()
{
    const int tid = threadIdx.x;
    const int w   = tid >> 5;
    const int lane = tid & 31;
    const int g   = lane >> 2;
    const int t   = lane & 3;
    const int wm  = w * 16;

    unsigned* ds_attn = ds_dyn;
    unsigned* Qs  = ds_attn + SM_QS;
    unsigned* Psw = ds_attn + SM_PS + w * 16 * PSTR;
    unsigned kf_s[2], vf_s[2];
    kf_s[0] = (unsigned)__cvta_generic_to_shared(ds_attn + SM_KF);
    kf_s[1] = kf_s[0] + 64 * QSTR * 4;
    vf_s[0] = (unsigned)__cvta_generic_to_shared(ds_attn + SM_VF);
    vf_s[1] = vf_s[0] + 64 * VSTR * 4;
    unsigned* Kf[2] = { ds_attn + SM_KF, ds_attn + SM_KF + 64 * QSTR };
    unsigned* Vf[2] = { ds_attn + SM_VF, ds_attn + SM_VF + 64 * VSTR };

    const float scale = 1.0f / sqrtf(96.0f);
    __shared__ int s_item;

    for (;;) {
        if (tid == 0) s_item = atomicAdd(&g_ctr, 1);
        __syncthreads();
        const int item = s_item;
        if (item >= N_ITEMS) return;

        const int qt = 15 - (item >> 5);
        const int hb = item & 31;
        const int h  = hb & 15;
        const int b  = hb >> 4;
        const int kvh = h >> 2;

        const float* kb0 = g_k + (size_t)(b * S_) * KN + kvh * KQD_;
        const float* vb0 = g_v + (size_t)(b * S_) * VN + kvh * VD_;

        {
            const float* kbase = kb0;
            for (int it = tid; it < 64 * 24; it += 256) {
                int r = it / 24, c4 = (it % 24) * 4;
                cp_async16(kf_s[0] + (r * QSTR + c4) * 4, kbase + (size_t)r * KN + c4);
            }
            const float* vbase = vb0;
            for (int it = tid; it < 64 * 32; it += 256) {
                int r = it >> 5, c4 = (it & 31) * 4;
                cp_async16(vf_s[0] + (r * VSTR + c4) * 4, vbase + (size_t)r * VN + c4);
            }
            CP_COMMIT();
        }

        const float* qbase = g_q + ((size_t)(b * S_ + qt * QT128)) * QN + h * KQD_;
        for (int it = tid; it < 128 * 24; it += 256) {
            int r = it / 24, c4 = (it % 24) * 4;
            float4 v = *(const float4*)(qbase + (size_t)r * QN + c4);
            uint4 u = make_uint4(f2tf32(v.x * scale), f2tf32(v.y * scale),
                                 f2tf32(v.z * scale), f2tf32(v.w * scale));
            *(uint4*)&Qs[r * QSTR + c4] = u;
        }

        float o[16][4];
#pragma unroll
        for (int j = 0; j < 16; j++)
#pragma unroll
            for (int r = 0; r < 4; r++) o[j][r] = 0.f;
        float m0 = -INFINITY, m1 = -INFINITY, l0 = 0.f, l1 = 0.f;

        const int row0g = qt * QT128 + wm + g;
        const int row1g = row0g + 8;
        const int kt_max = 2 * qt + 1;

        for (int kt = 0; kt <= kt_max; kt++) {
            const int cur = kt & 1;
            if (kt < kt_max) {
                const int nb = (kt + 1) & 1;
                const float* kbase = kb0 + (size_t)(kt + 1) * KT64 * KN;
                for (int it = tid; it < 64 * 24; it += 256) {
                    int r = it / 24, c4 = (it % 24) * 4;
                    cp_async16(kf_s[nb] + (r * QSTR + c4) * 4, kbase + (size_t)r * KN + c4);
                }
                const float* vbase = vb0 + (size_t)(kt + 1) * KT64 * VN;
                for (int it = tid; it < 64 * 32; it += 256) {
                    int r = it >> 5, c4 = (it & 31) * 4;
                    cp_async16(vf_s[nb] + (r * VSTR + c4) * 4, vbase + (size_t)r * VN + c4);
                }
            }
            CP_COMMIT();
            CP_WAIT1();
            __syncthreads();

            if (KT64 * kt <= qt * QT128 + wm + 15) {
                const unsigned* Kc = Kf[cur];
                const unsigned* Vc = Vf[cur];

                float s[8][4];
#pragma unroll
                for (int j = 0; j < 8; j++)
#pragma unroll
                    for (int r = 0; r < 4; r++) s[j][r] = 0.f;
#pragma unroll
                for (int k8 = 0; k8 < 96; k8 += 8) {
                    unsigned af[4];
                    af[0] = Qs[(wm + g    ) * QSTR + k8 + t    ];
                    af[1] = Qs[(wm + g + 8) * QSTR + k8 + t    ];
                    af[2] = Qs[(wm + g    ) * QSTR + k8 + t + 4];
                    af[3] = Qs[(wm + g + 8) * QSTR + k8 + t + 4];
#pragma unroll
                    for (int j = 0; j < 8; j++) {
                        unsigned bf[2];
                        bf[0] = Kc[(8 * j + g) * QSTR + k8 + t    ];
                        bf[1] = Kc[(8 * j + g) * QSTR + k8 + t + 4];
                        mma_tf32(s[j], af, bf);
                    }
                }

                if (kt >= 2 * qt) {
#pragma unroll
                    for (int j = 0; j < 8; j++) {
                        int c0 = kt * KT64 + 8 * j + 2 * t;
                        if (c0     > row0g) s[j][0] = -INFINITY;
                        if (c0 + 1 > row0g) s[j][1] = -INFINITY;
                        if (c0     > row1g) s[j][2] = -INFINITY;
                        if (c0 + 1 > row1g) s[j][3] = -INFINITY;
                    }
                }

                float ml0 = -INFINITY, ml1 = -INFINITY;
#pragma unroll
                for (int j = 0; j < 8; j++) {
                    ml0 = fmaxf(ml0, fmaxf(s[j][0], s[j][1]));
                    ml1 = fmaxf(ml1, fmaxf(s[j][2], s[j][3]));
                }
                ml0 = fmaxf(ml0, __shfl_xor_sync(0xffffffffu, ml0, 1));
                ml0 = fmaxf(ml0, __shfl_xor_sync(0xffffffffu, ml0, 2));
                ml1 = fmaxf(ml1, __shfl_xor_sync(0xffffffffu, ml1, 1));
                ml1 = fmaxf(ml1, __shfl_xor_sync(0xffffffffu, ml1, 2));
                float mn0 = fmaxf(m0, ml0), mn1 = fmaxf(m1, ml1);
                float al0 = __expf(m0 - mn0), al1 = __expf(m1 - mn1);
                m0 = mn0; m1 = mn1;
                float sum0 = 0.f, sum1 = 0.f;
#pragma unroll
                for (int j = 0; j < 8; j++) {
                    s[j][0] = __expf(s[j][0] - mn0); sum0 += s[j][0];
                    s[j][1] = __expf(s[j][1] - mn0); sum0 += s[j][1];
                    s[j][2] = __expf(s[j][2] - mn1); sum1 += s[j][2];
                    s[j][3] = __expf(s[j][3] - mn1); sum1 += s[j][3];
                }
                sum0 += __shfl_xor_sync(0xffffffffu, sum0, 1);
                sum0 += __shfl_xor_sync(0xffffffffu, sum0, 2);
                sum1 += __shfl_xor_sync(0xffffffffu, sum1, 1);
                sum1 += __shfl_xor_sync(0xffffffffu, sum1, 2);
                l0 = l0 * al0 + sum0;
                l1 = l1 * al1 + sum1;
#pragma unroll
                for (int j = 0; j < 16; j++) {
                    o[j][0] *= al0; o[j][1] *= al0;
                    o[j][2] *= al1; o[j][3] *= al1;
                }

#pragma unroll
                for (int j = 0; j < 8; j++) {
                    *(uint2*)&Psw[g * PSTR + 8 * j + 2 * t] =
                        make_uint2(f2tf32(s[j][0]), f2tf32(s[j][1]));
                    *(uint2*)&Psw[(g + 8) * PSTR + 8 * j + 2 * t] =
                        make_uint2(f2tf32(s[j][2]), f2tf32(s[j][3]));
                }
                __syncwarp();

#pragma unroll
                for (int k8 = 0; k8 < 64; k8 += 8) {
                    unsigned af[4];
                    af[0] = Psw[(g    ) * PSTR + k8 + t    ];
                    af[1] = Psw[(g + 8) * PSTR + k8 + t    ];
                    af[2] = Psw[(g    ) * PSTR + k8 + t + 4];
                    af[3] = Psw[(g + 8) * PSTR + k8 + t + 4];
#pragma unroll
                    for (int jn = 0; jn < 16; jn++) {
                        unsigned bf[2];
                        bf[0] = Vc[(k8 + t    ) * VSTR + 8 * jn + g];
                        bf[1] = Vc[(k8 + t + 4) * VSTR + 8 * jn + g];
                        mma_tf32(o[jn], af, bf);
                    }
                }
            }
            __syncthreads();
        }

        // Epilogue — write tf32-rounded (feeds cvt-free O projection)
        float inv0 = 1.0f / l0, inv1 = 1.0f / l1;
        float* ob = g_ao + ((size_t)(b * S_)) * ON + h * VD_;
        size_t r0 = (size_t)(qt * QT128 + wm + g);
        size_t r1 = r0 + 8;
#pragma unroll
        for (int jn = 0; jn < 16; jn++) {
            int col = 8 * jn + 2 * t;
            *(float2*)&ob[r0 * ON + col] =
                make_float2(rndf(o[jn][0] * inv0), rndf(o[jn][1] * inv0));
            *(float2*)&ob[r1 * ON + col] =
                make_float2(rndf(o[jn][2] * inv1), rndf(o[jn][3] * inv1));
        }

        CP_WAIT0();
        __syncthreads();
    }
}

// ---------------------------------------------------------------------------
extern "C" void kernel_launch(void* const* d_in, const int* in_sizes, int n_in,
                              void* d_out, int out_size)
{
    const float* hidden = (const float*)d_in[0];
    const int*   pos    = (const int*)  d_in[1];
    const float* Wq     = (const float*)d_in[2];
    const float* Wk     = (const float*)d_in[3];
    const float* Wv     = (const float*)d_in[4];
    const float* Wo     = (const float*)d_in[5];
    const float* qw     = (const float*)d_in[6];
    const float* kw     = (const float*)d_in[7];
    float* out = (float*)d_out;

    void *pq, *pk, *pv, *pa, *pwo;
    cudaGetSymbolAddress(&pq, g_q);
    cudaGetSymbolAddress(&pk, g_k);
    cudaGetSymbolAddress(&pv, g_v);
    cudaGetSymbolAddress(&pa, g_ao);
    cudaGetSymbolAddress(&pwo, g_wo);   // FIX: device address, not host shadow
    float* qb  = (float*)pq;
    float* kb  = (float*)pk;
    float* vb  = (float*)pv;
    float* ab  = (float*)pa;
    float* wob = (float*)pwo;

    static double h_invf[48];
    static int init_done = 0;
    if (!init_done) {
        for (int j = 0; j < 48; j++) h_invf[j] = pow(10000.0, -(double)j / 48.0);
        cudaFuncSetAttribute(attn_tc_kernel,
                             cudaFuncAttributeMaxDynamicSharedMemorySize,
                             ATTN_WORDS * 4);
        cudaFuncSetAttribute(sgemm_tf32,
                             cudaFuncAttributeMaxDynamicSharedMemorySize,
                             GEMM_SMEM_BYTES);
        cudaFuncSetAttribute(sgemm_qkv,
                             cudaFuncAttributeMaxDynamicSharedMemorySize,
                             GEMM_SMEM_BYTES);
        init_done = 1;
    }
    cudaMemcpyToSymbolAsync(g_invf, h_invf, sizeof(h_invf), 0,
                            cudaMemcpyHostToDevice);

    // 1. Round all GEMM inputs to tf32 bits (scratch copies)
    round_inputs<<<(N4TOT + 255) / 256, 256>>>(
        (const float4*)hidden, (const float4*)Wq, (const float4*)Wk,
        (const float4*)Wv, (const float4*)Wo);

    // 2. RoPE table (+ work-counter reset)
    rope_table_kernel<<<(S_ * 48 + 255) / 256, 256>>>();

    // 3. Fused QKV projection (cvt-free mainloop)
    sgemm_qkv<<<dim3(19, TOK / 128), 256, GEMM_SMEM_BYTES>>>(qb, kb, vb);

    // 4. Fused RMSNorm + RoPE
    rmsnorm_rope_fused<<<(QROWS + KROWS) / 4, 128>>>(qb, kb, qw, kw, pos);

    // 5. Persistent tensor-core flash attention
    attn_tc_kernel<<<152, 256, ATTN_WORDS * 4>>>();

    // 6. Output projection (cvt-free mainloop, device address for g_wo)
    sgemm_tf32<<<dim3(D_ / 128, TOK / 128), 256, GEMM_SMEM_BYTES>>>(
        ab, wob, out, TOK, D_, ON);
}

// round 15
// speedup vs baseline: 2.7036x; 1.4412x over previous
#include <cuda_runtime.h>
#include <cuda_fp16.h>
#include <math.h>

// Problem constants
#define B_   2
#define S_   2048
#define D_   2048
#define H_   16
#define KV_  4
#define KQD_ 96
#define VD_  128
#define TOK  (B_*S_)       // 4096
#define QN   (H_*KQD_)     // 1536
#define KN   (KV_*KQD_)    // 384
#define VN   (KV_*VD_)     // 512
#define ON   (H_*VD_)      // 2048

__device__ float  g_q [TOK * QN];
__device__ float  g_k [TOK * KN];
__device__ float  g_v [TOK * VN];
__device__ __half g_ao[TOK * ON];     // fp16 (11-bit mantissa = tf32)
__device__ float  g_cos[S_ * 48];
__device__ float  g_sin[S_ * 48];
__device__ double g_invf[48];
__device__ int    g_ctr;

// fp16 copies of GEMM inputs
__device__ __half g_hid[TOK * D_];
__device__ __half g_wq [QN * D_];
__device__ __half g_wk [KN * D_];
__device__ __half g_wv [VN * D_];
__device__ __half g_wo [D_ * ON];

extern __shared__ unsigned ds_dyn[];

// ---------------------------------------------------------------------------
__device__ __forceinline__ unsigned f2tf32(float x) {
    unsigned r;
    asm("cvt.rna.tf32.f32 %0, %1;" : "=r"(r) : "f"(x));
    return r;
}
__device__ __forceinline__ float rndf(float x) {
    return __uint_as_float(f2tf32(x));
}
__device__ __forceinline__ void mma_tf32(float* c, const unsigned* a, const unsigned* b) {
    asm volatile(
        "mma.sync.aligned.m16n8k8.row.col.f32.tf32.tf32.f32 "
        "{%0,%1,%2,%3}, {%4,%5,%6,%7}, {%8,%9}, {%0,%1,%2,%3};\n"
        : "+f"(c[0]), "+f"(c[1]), "+f"(c[2]), "+f"(c[3])
        : "r"(a[0]), "r"(a[1]), "r"(a[2]), "r"(a[3]),
          "r"(b[0]), "r"(b[1]));
}
__device__ __forceinline__ void mma_f16(float* c, const unsigned* a, const unsigned* b) {
    asm volatile(
        "mma.sync.aligned.m16n8k16.row.col.f32.f16.f16.f32 "
        "{%0,%1,%2,%3}, {%4,%5,%6,%7}, {%8,%9}, {%0,%1,%2,%3};\n"
        : "+f"(c[0]), "+f"(c[1]), "+f"(c[2]), "+f"(c[3])
        : "r"(a[0]), "r"(a[1]), "r"(a[2]), "r"(a[3]),
          "r"(b[0]), "r"(b[1]));
}
__device__ __forceinline__ void cp_async16(unsigned saddr, const void* g) {
    asm volatile("cp.async.cg.shared.global [%0], [%1], 16;\n" :: "r"(saddr), "l"(g));
}
#define CP_COMMIT() asm volatile("cp.async.commit_group;\n" ::: "memory")
#define CP_WAIT0()  asm volatile("cp.async.wait_group 0;\n" ::: "memory")
#define CP_WAIT1()  asm volatile("cp.async.wait_group 1;\n" ::: "memory")
#define CP_WAIT2()  asm volatile("cp.async.wait_group 2;\n" ::: "memory")

// ---------------------------------------------------------------------------
// Convert inputs to fp16 (same 11-bit mantissa as tf32)
// ---------------------------------------------------------------------------
#define NH4  (TOK * D_ / 4)
#define NW4Q (QN * D_ / 4)
#define NW4K (KN * D_ / 4)
#define NW4V (VN * D_ / 4)
#define NW4O (D_ * ON / 4)
#define NW4T (NW4Q + NW4K + NW4V + NW4O)

__device__ __forceinline__ void cvt4(__half* dst, const float4* src, int i) {
    float4 v = src[i];
    __half2* d = (__half2*)(dst + i * 4);
    d[0] = __floats2half2_rn(v.x, v.y);
    d[1] = __floats2half2_rn(v.z, v.w);
}

__global__ void cvt_hid(const float4* __restrict__ hid) {
    int i = blockIdx.x * blockDim.x + threadIdx.x;
    if (i < NH4) cvt4(g_hid, hid, i);
}
__global__ void cvt_weights(const float4* __restrict__ wq,
                            const float4* __restrict__ wk,
                            const float4* __restrict__ wv,
                            const float4* __restrict__ wo) {
    int i = blockIdx.x * blockDim.x + threadIdx.x;
    if (i >= NW4T) return;
    if (i < NW4Q)                     cvt4(g_wq, wq, i);
    else if (i < NW4Q + NW4K)         cvt4(g_wk, wk, i - NW4Q);
    else if (i < NW4Q + NW4K + NW4V)  cvt4(g_wv, wv, i - NW4Q - NW4K);
    else                              cvt4(g_wo, wo, i - NW4Q - NW4K - NW4V);
}

// ---------------------------------------------------------------------------
// RoPE table + work-counter reset
// ---------------------------------------------------------------------------
__global__ void rope_table_kernel() {
    int i = blockIdx.x * blockDim.x + threadIdx.x;
    if (i == 0) g_ctr = 0;
    if (i >= S_ * 48) return;
    int pos = i / 48, j = i % 48;
    double d = g_invf[j];
    float hi = (float)d;
    float lo = (float)(d - (double)hi);
    float fp = (float)pos;
    float p  = fp * hi;
    float e  = fmaf(fp, hi, -p);
    float t2 = fmaf(fp, lo, e);
    const float INV2PI = 0.15915494309189535f;
    const float PIH    = 6.2831854820251465f;
    const float PIL    = -1.7484555314695172e-7f;
    float n = rintf(p * INV2PI);
    float r = fmaf(-n, PIH, p);
    r = fmaf(-n, PIL, r);
    r = r + t2;
    float s, c;
    sincosf(r, &s, &c);
    g_cos[i] = c;
    g_sin[i] = s;
}

// ---------------------------------------------------------------------------
// FP16 GEMM-NT core: cp.async 4-stage pipeline, BK=32 halves per stage.
// Smem rows of 16 data words + 4 pad (stride 20 words -> conflict-free).
// 128x128 tile, 256 threads, warp tile 64x32, m16n8k16 f16 MMA, fp32 acc.
// ---------------------------------------------------------------------------
#define HBK 32
#define HSTR 20                        // 32-bit words per row
#define HAHALF (128*HSTR)              // 2560 words per matrix block
#define HSTAGE_WORDS (2*HAHALF)        // 5120 words per stage
#define HSTAGES 4
#define GEMM_SMEM_BYTES (HSTAGES*HSTAGE_WORDS*4)   // 81920

template<bool RND>
__device__ __forceinline__ void gemm_h_body(
    const __half* __restrict__ A, const __half* __restrict__ Bm,
    float* __restrict__ C, int N, int K, int bm, int bn)
{
    unsigned* ds = ds_dyn;
    const int tid  = threadIdx.x;
    const int warp = tid >> 5;
    const int lane = tid & 31;
    const int g    = lane >> 2;
    const int t    = lane & 3;
    const int wm   = (warp >> 2) * 64;
    const int wn   = (warp & 3) * 32;

    const int lrow = tid >> 1;             // 0..127
    const int lkh  = (tid & 1) * 16;       // half offset 0 or 16
    const __half* Ap = A  + (size_t)(bm + lrow) * K + lkh;
    const __half* Bp = Bm + (size_t)(bn + lrow) * K + lkh;

    const unsigned sbase = (unsigned)__cvta_generic_to_shared(ds);
    const unsigned aoff  = (lrow * HSTR + (tid & 1) * 8) * 4;
    const unsigned boff  = (HAHALF + lrow * HSTR + (tid & 1) * 8) * 4;

    float acc[4][4][4];
#pragma unroll
    for (int i = 0; i < 4; i++)
#pragma unroll
        for (int j = 0; j < 4; j++)
#pragma unroll
            for (int r = 0; r < 4; r++) acc[i][j][r] = 0.f;

#pragma unroll
    for (int s = 0; s < HSTAGES - 1; s++) {
        unsigned sb = sbase + s * HSTAGE_WORDS * 4;
        cp_async16(sb + aoff,      Ap + (size_t)s * HBK);
        cp_async16(sb + aoff + 16, Ap + (size_t)s * HBK + 8);
        cp_async16(sb + boff,      Bp + (size_t)s * HBK);
        cp_async16(sb + boff + 16, Bp + (size_t)s * HBK + 8);
        CP_COMMIT();
    }

    const int nst = K / HBK;
    for (int ks = 0; ks < nst; ks++) {
        CP_WAIT2();
        __syncthreads();

        if (ks + HSTAGES - 1 < nst) {
            int slot = (ks + HSTAGES - 1) & 3;
            unsigned sb = sbase + slot * HSTAGE_WORDS * 4;
            const __half* Ap2 = Ap + (size_t)(ks + HSTAGES - 1) * HBK;
            const __half* Bp2 = Bp + (size_t)(ks + HSTAGES - 1) * HBK;
            cp_async16(sb + aoff,      Ap2);
            cp_async16(sb + aoff + 16, Ap2 + 8);
            cp_async16(sb + boff,      Bp2);
            cp_async16(sb + boff + 16, Bp2 + 8);
        }
        CP_COMMIT();

        const unsigned* As = ds + (ks & 3) * HSTAGE_WORDS;
        const unsigned* Bs = As + HAHALF;

#pragma unroll
        for (int kh2 = 0; kh2 < 2; kh2++) {      // two k16 halves of BK=32
            const int kw = kh2 * 8;              // word offset
            unsigned af[4][4], bf[4][2];
#pragma unroll
            for (int i = 0; i < 4; i++) {
                int m = wm + 16 * i;
                af[i][0] = As[(m + g    ) * HSTR + kw + t    ];
                af[i][1] = As[(m + g + 8) * HSTR + kw + t    ];
                af[i][2] = As[(m + g    ) * HSTR + kw + t + 4];
                af[i][3] = As[(m + g + 8) * HSTR + kw + t + 4];
            }
#pragma unroll
            for (int j = 0; j < 4; j++) {
                int n = wn + 8 * j;
                bf[j][0] = Bs[(n + g) * HSTR + kw + t    ];
                bf[j][1] = Bs[(n + g) * HSTR + kw + t + 4];
            }
#pragma unroll
            for (int i = 0; i < 4; i++)
#pragma unroll
                for (int j = 0; j < 4; j++)
                    mma_f16(acc[i][j], af[i], bf[j]);
        }
    }

#pragma unroll
    for (int i = 0; i < 4; i++) {
#pragma unroll
        for (int j = 0; j < 4; j++) {
            size_t r0 = (size_t)(bm + wm + 16 * i + g);
            size_t col = (size_t)(bn + wn + 8 * j + 2 * t);
            float v0 = acc[i][j][0], v1 = acc[i][j][1];
            float v2 = acc[i][j][2], v3 = acc[i][j][3];
            if (RND) {
                v0 = rndf(v0); v1 = rndf(v1);
                v2 = rndf(v2); v3 = rndf(v3);
            }
            *(float2*)&C[r0 * N + col]       = make_float2(v0, v1);
            *(float2*)&C[(r0 + 8) * N + col] = make_float2(v2, v3);
        }
    }
}

// Fused QKV projection: x in [0,19): 12 Q | 3 K | 4 V (V tf32-rounded)
__global__ void __launch_bounds__(256, 2) sgemm_qkv(
    float* __restrict__ qb, float* __restrict__ kb, float* __restrict__ vb)
{
    const int bx = blockIdx.x;
    const int bm = blockIdx.y << 7;
    if (bx < 12) {
        gemm_h_body<false>(g_hid, g_wq, qb, QN, D_, bm, bx << 7);
    } else if (bx < 15) {
        gemm_h_body<false>(g_hid, g_wk, kb, KN, D_, bm, (bx - 12) << 7);
    } else {
        gemm_h_body<true>(g_hid, g_wv, vb, VN, D_, bm, (bx - 15) << 7);
    }
}

// O projection: references g_ao / g_wo from device code (no host-shadow trap)
__global__ void __launch_bounds__(256, 2) sgemm_o(float* __restrict__ C)
{
    gemm_h_body<false>(g_ao, g_wo, C, D_, ON, blockIdx.y << 7, blockIdx.x << 7);
}

// ---------------------------------------------------------------------------
// Fused RMSNorm+RoPE over Q rows then K rows. K output rounded to tf32 bits.
// ---------------------------------------------------------------------------
#define QROWS (TOK * H_)
#define KROWS (TOK * KV_)

__global__ void rmsnorm_rope_fused(float* qb, float* kb,
                                   const float* __restrict__ qw,
                                   const float* __restrict__ kw,
                                   const int* __restrict__ pos_ids)
{
    __shared__ float sh[4][96];
    const int wid  = threadIdx.x >> 5;
    const int lane = threadIdx.x & 31;
    const int row  = blockIdx.x * 4 + wid;
    if (row >= QROWS + KROWS) return;

    const bool isK = (row >= QROWS);
    const int  r   = isK ? row - QROWS : row;
    const int  token = isK ? (r / KV_) : (r / H_);
    float* x = (isK ? kb : qb) + (size_t)r * 96;
    const float* w = isK ? kw : qw;

    float v0 = x[lane], v1 = x[lane + 32], v2 = x[lane + 64];
    float ss = v0 * v0 + v1 * v1 + v2 * v2;
#pragma unroll
    for (int o = 16; o; o >>= 1) ss += __shfl_xor_sync(0xffffffffu, ss, o);
    float inv = rsqrtf(ss * (1.0f / 96.0f) + 1e-6f);

    sh[wid][lane]      = v0 * inv * w[lane];
    sh[wid][lane + 32] = v1 * inv * w[lane + 32];
    sh[wid][lane + 64] = v2 * inv * w[lane + 64];
    __syncwarp();

    const int pos = pos_ids[token];
    const float* ct = g_cos + pos * 48;
    const float* st = g_sin + pos * 48;
#pragma unroll
    for (int q3 = 0; q3 < 3; q3++) {
        int d = lane + q3 * 32;
        int f = (d < 48) ? d : d - 48;
        float rh = (d < 48) ? -sh[wid][d + 48] : sh[wid][d - 48];
        float val = sh[wid][d] * ct[f] + rh * st[f];
        x[d] = isK ? rndf(val) : val;
    }
}

// ---------------------------------------------------------------------------
// Tensor-core flash attention — PERSISTENT (152 CTAs, heavy-first queue).
// tf32 math unchanged; epilogue writes fp16 ao (same mantissa as tf32 round).
// ---------------------------------------------------------------------------
#define QT128 128
#define KT64  64
#define QSTR 100
#define VSTR 136
#define PSTR 68
#define SM_QS   0
#define SM_KF   (128*QSTR)
#define SM_VF   (SM_KF + 2*64*QSTR)
#define SM_PS   (SM_VF + 2*64*VSTR)
#define ATTN_WORDS (SM_PS + 8*16*PSTR)
#define N_ITEMS (16 * H_ * B_)     // 512

__global__ void __launch_bounds__(256) attn_tc_kernel()
{
    const int tid = threadIdx.x;
    const int w   = tid >> 5;
    const int lane = tid & 31;
    const int g   = lane >> 2;
    const int t   = lane & 3;
    const int wm  = w * 16;

    unsigned* ds_attn = ds_dyn;
    unsigned* Qs  = ds_attn + SM_QS;
    unsigned* Psw = ds_attn + SM_PS + w * 16 * PSTR;
    unsigned kf_s[2], vf_s[2];
    kf_s[0] = (unsigned)__cvta_generic_to_shared(ds_attn + SM_KF);
    kf_s[1] = kf_s[0] + 64 * QSTR * 4;
    vf_s[0] = (unsigned)__cvta_generic_to_shared(ds_attn + SM_VF);
    vf_s[1] = vf_s[0] + 64 * VSTR * 4;
    unsigned* Kf[2] = { ds_attn + SM_KF, ds_attn + SM_KF + 64 * QSTR };
    unsigned* Vf[2] = { ds_attn + SM_VF, ds_attn + SM_VF + 64 * VSTR };

    const float scale = 1.0f / sqrtf(96.0f);
    __shared__ int s_item;

    for (;;) {
        if (tid == 0) s_item = atomicAdd(&g_ctr, 1);
        __syncthreads();
        const int item = s_item;
        if (item >= N_ITEMS) return;

        const int qt = 15 - (item >> 5);
        const int hb = item & 31;
        const int h  = hb & 15;
        const int b  = hb >> 4;
        const int kvh = h >> 2;

        const float* kb0 = g_k + (size_t)(b * S_) * KN + kvh * KQD_;
        const float* vb0 = g_v + (size_t)(b * S_) * VN + kvh * VD_;

        {
            const float* kbase = kb0;
            for (int it = tid; it < 64 * 24; it += 256) {
                int r = it / 24, c4 = (it % 24) * 4;
                cp_async16(kf_s[0] + (r * QSTR + c4) * 4, kbase + (size_t)r * KN + c4);
            }
            const float* vbase = vb0;
            for (int it = tid; it < 64 * 32; it += 256) {
                int r = it >> 5, c4 = (it & 31) * 4;
                cp_async16(vf_s[0] + (r * VSTR + c4) * 4, vbase + (size_t)r * VN + c4);
            }
            CP_COMMIT();
        }

        const float* qbase = g_q + ((size_t)(b * S_ + qt * QT128)) * QN + h * KQD_;
        for (int it = tid; it < 128 * 24; it += 256) {
            int r = it / 24, c4 = (it % 24) * 4;
            float4 v = *(const float4*)(qbase + (size_t)r * QN + c4);
            uint4 u = make_uint4(f2tf32(v.x * scale), f2tf32(v.y * scale),
                                 f2tf32(v.z * scale), f2tf32(v.w * scale));
            *(uint4*)&Qs[r * QSTR + c4] = u;
        }

        float o[16][4];
#pragma unroll
        for (int j = 0; j < 16; j++)
#pragma unroll
            for (int r = 0; r < 4; r++) o[j][r] = 0.f;
        float m0 = -INFINITY, m1 = -INFINITY, l0 = 0.f, l1 = 0.f;

        const int row0g = qt * QT128 + wm + g;
        const int row1g = row0g + 8;
        const int kt_max = 2 * qt + 1;

        for (int kt = 0; kt <= kt_max; kt++) {
            const int cur = kt & 1;
            if (kt < kt_max) {
                const int nb = (kt + 1) & 1;
                const float* kbase = kb0 + (size_t)(kt + 1) * KT64 * KN;
                for (int it = tid; it < 64 * 24; it += 256) {
                    int r = it / 24, c4 = (it % 24) * 4;
                    cp_async16(kf_s[nb] + (r * QSTR + c4) * 4, kbase + (size_t)r * KN + c4);
                }
                const float* vbase = vb0 + (size_t)(kt + 1) * KT64 * VN;
                for (int it = tid; it < 64 * 32; it += 256) {
                    int r = it >> 5, c4 = (it & 31) * 4;
                    cp_async16(vf_s[nb] + (r * VSTR + c4) * 4, vbase + (size_t)r * VN + c4);
                }
            }
            CP_COMMIT();
            CP_WAIT1();
            __syncthreads();

            if (KT64 * kt <= qt * QT128 + wm + 15) {
                const unsigned* Kc = Kf[cur];
                const unsigned* Vc = Vf[cur];

                float s[8][4];
#pragma unroll
                for (int j = 0; j < 8; j++)
#pragma unroll
                    for (int r = 0; r < 4; r++) s[j][r] = 0.f;
#pragma unroll
                for (int k8 = 0; k8 < 96; k8 += 8) {
                    unsigned af[4];
                    af[0] = Qs[(wm + g    ) * QSTR + k8 + t    ];
                    af[1] = Qs[(wm + g + 8) * QSTR + k8 + t    ];
                    af[2] = Qs[(wm + g    ) * QSTR + k8 + t + 4];
                    af[3] = Qs[(wm + g + 8) * QSTR + k8 + t + 4];
#pragma unroll
                    for (int j = 0; j < 8; j++) {
                        unsigned bf[2];
                        bf[0] = Kc[(8 * j + g) * QSTR + k8 + t    ];
                        bf[1] = Kc[(8 * j + g) * QSTR + k8 + t + 4];
                        mma_tf32(s[j], af, bf);
                    }
                }

                if (kt >= 2 * qt) {
#pragma unroll
                    for (int j = 0; j < 8; j++) {
                        int c0 = kt * KT64 + 8 * j + 2 * t;
                        if (c0     > row0g) s[j][0] = -INFINITY;
                        if (c0 + 1 > row0g) s[j][1] = -INFINITY;
                        if (c0     > row1g) s[j][2] = -INFINITY;
                        if (c0 + 1 > row1g) s[j][3] = -INFINITY;
                    }
                }

                float ml0 = -INFINITY, ml1 = -INFINITY;
#pragma unroll
                for (int j = 0; j < 8; j++) {
                    ml0 = fmaxf(ml0, fmaxf(s[j][0], s[j][1]));
                    ml1 = fmaxf(ml1, fmaxf(s[j][2], s[j][3]));
                }
                ml0 = fmaxf(ml0, __shfl_xor_sync(0xffffffffu, ml0, 1));
                ml0 = fmaxf(ml0, __shfl_xor_sync(0xffffffffu, ml0, 2));
                ml1 = fmaxf(ml1, __shfl_xor_sync(0xffffffffu, ml1, 1));
                ml1 = fmaxf(ml1, __shfl_xor_sync(0xffffffffu, ml1, 2));
                float mn0 = fmaxf(m0, ml0), mn1 = fmaxf(m1, ml1);
                float al0 = __expf(m0 - mn0), al1 = __expf(m1 - mn1);
                m0 = mn0; m1 = mn1;
                float sum0 = 0.f, sum1 = 0.f;
#pragma unroll
                for (int j = 0; j < 8; j++) {
                    s[j][0] = __expf(s[j][0] - mn0); sum0 += s[j][0];
                    s[j][1] = __expf(s[j][1] - mn0); sum0 += s[j][1];
                    s[j][2] = __expf(s[j][2] - mn1); sum1 += s[j][2];
                    s[j][3] = __expf(s[j][3] - mn1); sum1 += s[j][3];
                }
                sum0 += __shfl_xor_sync(0xffffffffu, sum0, 1);
                sum0 += __shfl_xor_sync(0xffffffffu, sum0, 2);
                sum1 += __shfl_xor_sync(0xffffffffu, sum1, 1);
                sum1 += __shfl_xor_sync(0xffffffffu, sum1, 2);
                l0 = l0 * al0 + sum0;
                l1 = l1 * al1 + sum1;
#pragma unroll
                for (int j = 0; j < 16; j++) {
                    o[j][0] *= al0; o[j][1] *= al0;
                    o[j][2] *= al1; o[j][3] *= al1;
                }

#pragma unroll
                for (int j = 0; j < 8; j++) {
                    *(uint2*)&Psw[g * PSTR + 8 * j + 2 * t] =
                        make_uint2(f2tf32(s[j][0]), f2tf32(s[j][1]));
                    *(uint2*)&Psw[(g + 8) * PSTR + 8 * j + 2 * t] =
                        make_uint2(f2tf32(s[j][2]), f2tf32(s[j][3]));
                }
                __syncwarp();

#pragma unroll
                for (int k8 = 0; k8 < 64; k8 += 8) {
                    unsigned af[4];
                    af[0] = Psw[(g    ) * PSTR + k8 + t    ];
                    af[1] = Psw[(g + 8) * PSTR + k8 + t    ];
                    af[2] = Psw[(g    ) * PSTR + k8 + t + 4];
                    af[3] = Psw[(g + 8) * PSTR + k8 + t + 4];
#pragma unroll
                    for (int jn = 0; jn < 16; jn++) {
                        unsigned bf[2];
                        bf[0] = Vc[(k8 + t    ) * VSTR + 8 * jn + g];
                        bf[1] = Vc[(k8 + t + 4) * VSTR + 8 * jn + g];
                        mma_tf32(o[jn], af, bf);
                    }
                }
            }
            __syncthreads();
        }

        // Epilogue — write fp16 ao (feeds fp16 O projection)
        float inv0 = 1.0f / l0, inv1 = 1.0f / l1;
        __half* ob = g_ao + ((size_t)(b * S_)) * ON + h * VD_;
        size_t r0 = (size_t)(qt * QT128 + wm + g);
        size_t r1 = r0 + 8;
#pragma unroll
        for (int jn = 0; jn < 16; jn++) {
            int col = 8 * jn + 2 * t;
            *(__half2*)&ob[r0 * ON + col] =
                __floats2half2_rn(o[jn][0] * inv0, o[jn][1] * inv0);
            *(__half2*)&ob[r1 * ON + col] =
                __floats2half2_rn(o[jn][2] * inv1, o[jn][3] * inv1);
        }

        CP_WAIT0();
        __syncthreads();
    }
}

// ---------------------------------------------------------------------------
extern "C" void kernel_launch(void* const* d_in, const int* in_sizes, int n_in,
                              void* d_out, int out_size)
{
    const float* hidden = (const float*)d_in[0];
    const int*   pos    = (const int*)  d_in[1];
    const float* Wq     = (const float*)d_in[2];
    const float* Wk     = (const float*)d_in[3];
    const float* Wv     = (const float*)d_in[4];
    const float* Wo     = (const float*)d_in[5];
    const float* qw     = (const float*)d_in[6];
    const float* kw     = (const float*)d_in[7];
    float* out = (float*)d_out;

    void *pq, *pk, *pv;
    cudaGetSymbolAddress(&pq, g_q);
    cudaGetSymbolAddress(&pk, g_k);
    cudaGetSymbolAddress(&pv, g_v);
    float* qb = (float*)pq;
    float* kb = (float*)pk;
    float* vb = (float*)pv;

    static double h_invf[48];
    static int init_done = 0;
    if (!init_done) {
        for (int j = 0; j < 48; j++) h_invf[j] = pow(10000.0, -(double)j / 48.0);
        cudaFuncSetAttribute(attn_tc_kernel,
                             cudaFuncAttributeMaxDynamicSharedMemorySize,
                             ATTN_WORDS * 4);
        cudaFuncSetAttribute(sgemm_qkv,
                             cudaFuncAttributeMaxDynamicSharedMemorySize,
                             GEMM_SMEM_BYTES);
        cudaFuncSetAttribute(sgemm_o,
                             cudaFuncAttributeMaxDynamicSharedMemorySize,
                             GEMM_SMEM_BYTES);
        init_done = 1;
    }
    cudaMemcpyToSymbolAsync(g_invf, h_invf, sizeof(h_invf), 0,
                            cudaMemcpyHostToDevice);

    // 1-2. fp16 conversions (hid, weights)
    cvt_hid<<<(NH4 + 255) / 256, 256>>>((const float4*)hidden);
    cvt_weights<<<(NW4T + 255) / 256, 256>>>(
        (const float4*)Wq, (const float4*)Wk, (const float4*)Wv,
        (const float4*)Wo);

    // 3. RoPE table (+ work-counter reset)
    rope_table_kernel<<<(S_ * 48 + 255) / 256, 256>>>();

    // 4. Fused QKV projection (fp16 MMA) — profiled slot
    sgemm_qkv<<<dim3(19, TOK / 128), 256, GEMM_SMEM_BYTES>>>(qb, kb, vb);

    // 5. Fused RMSNorm + RoPE
    rmsnorm_rope_fused<<<(QROWS + KROWS) / 4, 128>>>(qb, kb, qw, kw, pos);

    // 6. Persistent tensor-core flash attention (tf32)
    attn_tc_kernel<<<152, 256, ATTN_WORDS * 4>>>();

    // 7. Output projection (fp16 MMA)
    sgemm_o<<<dim3(D_ / 128, TOK / 128), 256, GEMM_SMEM_BYTES>>>(out);
}

// round 16
// speedup vs baseline: 3.4955x; 1.2929x over previous
#include <cuda_runtime.h>
#include <cuda_fp16.h>
#include <math.h>

// Problem constants
#define B_   2
#define S_   2048
#define D_   2048
#define H_   16
#define KV_  4
#define KQD_ 96
#define VD_  128
#define TOK  (B_*S_)       // 4096
#define QN   (H_*KQD_)     // 1536
#define KN   (KV_*KQD_)    // 384
#define VN   (KV_*VD_)     // 512
#define ON   (H_*VD_)      // 2048

__device__ float  g_q [TOK * QN];     // fp32 QKV-GEMM outputs (norm input)
__device__ float  g_k [TOK * KN];
__device__ float  g_v [TOK * VN];
__device__ __half g_qh[TOK * QN];     // fp16 normed+roped+scaled Q
__device__ __half g_kh[TOK * KN];     // fp16 normed+roped K
__device__ __half g_vT[(size_t)B_ * KV_ * VD_ * S_];  // fp16 V transposed
__device__ __half g_ao[TOK * ON];
__device__ float  g_cos[S_ * 48];
__device__ float  g_sin[S_ * 48];
__device__ double g_invf[48];
__device__ int    g_ctr;

// fp16 copies of GEMM inputs
__device__ __half g_hid[TOK * D_];
__device__ __half g_wq [QN * D_];
__device__ __half g_wk [KN * D_];
__device__ __half g_wv [VN * D_];
__device__ __half g_wo [D_ * ON];

extern __shared__ unsigned ds_dyn[];

// ---------------------------------------------------------------------------
__device__ __forceinline__ void mma_f16(float* c, const unsigned* a, const unsigned* b) {
    asm volatile(
        "mma.sync.aligned.m16n8k16.row.col.f32.f16.f16.f32 "
        "{%0,%1,%2,%3}, {%4,%5,%6,%7}, {%8,%9}, {%0,%1,%2,%3};\n"
        : "+f"(c[0]), "+f"(c[1]), "+f"(c[2]), "+f"(c[3])
        : "r"(a[0]), "r"(a[1]), "r"(a[2]), "r"(a[3]),
          "r"(b[0]), "r"(b[1]));
}
__device__ __forceinline__ void cp_async16(unsigned saddr, const void* g) {
    asm volatile("cp.async.cg.shared.global [%0], [%1], 16;\n" :: "r"(saddr), "l"(g));
}
#define CP_COMMIT() asm volatile("cp.async.commit_group;\n" ::: "memory")
#define CP_WAIT0()  asm volatile("cp.async.wait_group 0;\n" ::: "memory")
#define CP_WAIT1()  asm volatile("cp.async.wait_group 1;\n" ::: "memory")
#define CP_WAIT2()  asm volatile("cp.async.wait_group 2;\n" ::: "memory")

// ---------------------------------------------------------------------------
// Merged prologue: fp16 conversion of hid+weights, RoPE table, counter reset
// ---------------------------------------------------------------------------
#define NH4  (TOK * D_ / 4)
#define NW4Q (QN * D_ / 4)
#define NW4K (KN * D_ / 4)
#define NW4V (VN * D_ / 4)
#define NW4O (D_ * ON / 4)
#define NCVT (NH4 + NW4Q + NW4K + NW4V + NW4O)
#define NPRE (NCVT + S_ * 48)

__device__ __forceinline__ void cvt4(__half* dst, const float4* src, int i) {
    float4 v = src[i];
    __half2* d = (__half2*)(dst + i * 4);
    d[0] = __floats2half2_rn(v.x, v.y);
    d[1] = __floats2half2_rn(v.z, v.w);
}

__global__ void prologue_kernel(const float4* __restrict__ hid,
                                const float4* __restrict__ wq,
                                const float4* __restrict__ wk,
                                const float4* __restrict__ wv,
                                const float4* __restrict__ wo)
{
    int i = blockIdx.x * blockDim.x + threadIdx.x;
    if (i == 0) g_ctr = 0;
    if (i >= NPRE) return;
    if (i < NH4) { cvt4(g_hid, hid, i); return; }
    int j = i - NH4;
    if (j < NW4Q) { cvt4(g_wq, wq, j); return; }
    j -= NW4Q;
    if (j < NW4K) { cvt4(g_wk, wk, j); return; }
    j -= NW4K;
    if (j < NW4V) { cvt4(g_wv, wv, j); return; }
    j -= NW4V;
    if (j < NW4O) { cvt4(g_wo, wo, j); return; }
    // RoPE table entries
    int r0 = i - NCVT;
    int pos = r0 / 48, jf = r0 % 48;
    double d = g_invf[jf];
    float hi = (float)d;
    float lo = (float)(d - (double)hi);
    float fp = (float)pos;
    float p  = fp * hi;
    float e  = fmaf(fp, hi, -p);
    float t2 = fmaf(fp, lo, e);
    const float INV2PI = 0.15915494309189535f;
    const float PIH    = 6.2831854820251465f;
    const float PIL    = -1.7484555314695172e-7f;
    float n = rintf(p * INV2PI);
    float r = fmaf(-n, PIH, p);
    r = fmaf(-n, PIL, r);
    r = r + t2;
    float s, c;
    sincosf(r, &s, &c);
    g_cos[r0] = c;
    g_sin[r0] = s;
}

// ---------------------------------------------------------------------------
// FP16 GEMM-NT core (validated R15): cp.async 4-stage, BK=32 halves/stage.
// ---------------------------------------------------------------------------
#define HBK 32
#define HSTR 20
#define HAHALF (128*HSTR)
#define HSTAGE_WORDS (2*HAHALF)
#define HSTAGES 4
#define GEMM_SMEM_BYTES (HSTAGES*HSTAGE_WORDS*4)   // 81920

__device__ __forceinline__ void gemm_h_body(
    const __half* __restrict__ A, const __half* __restrict__ Bm,
    float* __restrict__ C, int N, int K, int bm, int bn)
{
    unsigned* ds = ds_dyn;
    const int tid  = threadIdx.x;
    const int warp = tid >> 5;
    const int lane = tid & 31;
    const int g    = lane >> 2;
    const int t    = lane & 3;
    const int wm   = (warp >> 2) * 64;
    const int wn   = (warp & 3) * 32;

    const int lrow = tid >> 1;
    const int lkh  = (tid & 1) * 16;
    const __half* Ap = A  + (size_t)(bm + lrow) * K + lkh;
    const __half* Bp = Bm + (size_t)(bn + lrow) * K + lkh;

    const unsigned sbase = (unsigned)__cvta_generic_to_shared(ds);
    const unsigned aoff  = (lrow * HSTR + (tid & 1) * 8) * 4;
    const unsigned boff  = (HAHALF + lrow * HSTR + (tid & 1) * 8) * 4;

    float acc[4][4][4];
#pragma unroll
    for (int i = 0; i < 4; i++)
#pragma unroll
        for (int j = 0; j < 4; j++)
#pragma unroll
            for (int r = 0; r < 4; r++) acc[i][j][r] = 0.f;

#pragma unroll
    for (int s = 0; s < HSTAGES - 1; s++) {
        unsigned sb = sbase + s * HSTAGE_WORDS * 4;
        cp_async16(sb + aoff,      Ap + (size_t)s * HBK);
        cp_async16(sb + aoff + 16, Ap + (size_t)s * HBK + 8);
        cp_async16(sb + boff,      Bp + (size_t)s * HBK);
        cp_async16(sb + boff + 16, Bp + (size_t)s * HBK + 8);
        CP_COMMIT();
    }

    const int nst = K / HBK;
    for (int ks = 0; ks < nst; ks++) {
        CP_WAIT2();
        __syncthreads();

        if (ks + HSTAGES - 1 < nst) {
            int slot = (ks + HSTAGES - 1) & 3;
            unsigned sb = sbase + slot * HSTAGE_WORDS * 4;
            const __half* Ap2 = Ap + (size_t)(ks + HSTAGES - 1) * HBK;
            const __half* Bp2 = Bp + (size_t)(ks + HSTAGES - 1) * HBK;
            cp_async16(sb + aoff,      Ap2);
            cp_async16(sb + aoff + 16, Ap2 + 8);
            cp_async16(sb + boff,      Bp2);
            cp_async16(sb + boff + 16, Bp2 + 8);
        }
        CP_COMMIT();

        const unsigned* As = ds + (ks & 3) * HSTAGE_WORDS;
        const unsigned* Bs = As + HAHALF;

#pragma unroll
        for (int kh2 = 0; kh2 < 2; kh2++) {
            const int kw = kh2 * 8;
            unsigned af[4][4], bf[4][2];
#pragma unroll
            for (int i = 0; i < 4; i++) {
                int m = wm + 16 * i;
                af[i][0] = As[(m + g    ) * HSTR + kw + t    ];
                af[i][1] = As[(m + g + 8) * HSTR + kw + t    ];
                af[i][2] = As[(m + g    ) * HSTR + kw + t + 4];
                af[i][3] = As[(m + g + 8) * HSTR + kw + t + 4];
            }
#pragma unroll
            for (int j = 0; j < 4; j++) {
                int n = wn + 8 * j;
                bf[j][0] = Bs[(n + g) * HSTR + kw + t    ];
                bf[j][1] = Bs[(n + g) * HSTR + kw + t + 4];
            }
#pragma unroll
            for (int i = 0; i < 4; i++)
#pragma unroll
                for (int j = 0; j < 4; j++)
                    mma_f16(acc[i][j], af[i], bf[j]);
        }
    }

#pragma unroll
    for (int i = 0; i < 4; i++) {
#pragma unroll
        for (int j = 0; j < 4; j++) {
            size_t r0 = (size_t)(bm + wm + 16 * i + g);
            size_t col = (size_t)(bn + wn + 8 * j + 2 * t);
            *(float2*)&C[r0 * N + col]       = make_float2(acc[i][j][0], acc[i][j][1]);
            *(float2*)&C[(r0 + 8) * N + col] = make_float2(acc[i][j][2], acc[i][j][3]);
        }
    }
}

// Fused QKV projection: x in [0,19): 12 Q | 3 K | 4 V
__global__ void __launch_bounds__(256, 2) sgemm_qkv(
    float* __restrict__ qb, float* __restrict__ kb, float* __restrict__ vb)
{
    const int bx = blockIdx.x;
    const int bm = blockIdx.y << 7;
    if (bx < 12)      gemm_h_body(g_hid, g_wq, qb, QN, D_, bm, bx << 7);
    else if (bx < 15) gemm_h_body(g_hid, g_wk, kb, KN, D_, bm, (bx - 12) << 7);
    else              gemm_h_body(g_hid, g_wv, vb, VN, D_, bm, (bx - 15) << 7);
}

// O projection
__global__ void __launch_bounds__(256, 2) sgemm_o(float* __restrict__ C)
{
    gemm_h_body(g_ao, g_wo, C, D_, ON, blockIdx.y << 7, blockIdx.x << 7);
}

// ---------------------------------------------------------------------------
// Merged: RMSNorm+RoPE (fp16 out, Q scale folded) + V transpose->fp16
// ---------------------------------------------------------------------------
#define QROWS (TOK * H_)
#define KROWS (TOK * KV_)
#define NORM_BLKS ((QROWS + KROWS) / 4)             // 20480
#define VT_BLKS   (B_ * KV_ * (VD_/32) * (S_/32))   // 2048

__global__ void norm_vt_kernel(const float* __restrict__ qb,
                               const float* __restrict__ kb,
                               const float* __restrict__ qw,
                               const float* __restrict__ kw,
                               const int* __restrict__ pos_ids)
{
    if (blockIdx.x < NORM_BLKS) {
        __shared__ float sh[4][96];
        const int wid  = threadIdx.x >> 5;
        const int lane = threadIdx.x & 31;
        const int row  = blockIdx.x * 4 + wid;

        const bool isK = (row >= QROWS);
        const int  r   = isK ? row - QROWS : row;
        const int  token = isK ? (r / KV_) : (r / H_);
        const float* x = (isK ? kb : qb) + (size_t)r * 96;
        const float* w = isK ? kw : qw;
        __half* outp = (isK ? g_kh : g_qh) + (size_t)r * 96;
        const float oscale = isK ? 1.0f : (1.0f / sqrtf(96.0f));

        float v0 = x[lane], v1 = x[lane + 32], v2 = x[lane + 64];
        float ss = v0 * v0 + v1 * v1 + v2 * v2;
#pragma unroll
        for (int o = 16; o; o >>= 1) ss += __shfl_xor_sync(0xffffffffu, ss, o);
        float inv = rsqrtf(ss * (1.0f / 96.0f) + 1e-6f);

        sh[wid][lane]      = v0 * inv * w[lane];
        sh[wid][lane + 32] = v1 * inv * w[lane + 32];
        sh[wid][lane + 64] = v2 * inv * w[lane + 64];
        __syncwarp();

        const int pos = pos_ids[token];
        const float* ct = g_cos + pos * 48;
        const float* st = g_sin + pos * 48;
#pragma unroll
        for (int q3 = 0; q3 < 3; q3++) {
            int d = lane + q3 * 32;
            int f = (d < 48) ? d : d - 48;
            float rh = (d < 48) ? -sh[wid][d + 48] : sh[wid][d - 48];
            float val = sh[wid][d] * ct[f] + rh * st[f];
            outp[d] = __float2half_rn(val * oscale);
        }
    } else {
        // V transpose tile: 32 dims x 32 tokens, 128 threads (each 8 elems)
        __shared__ float tile[32][33];
        int bid = blockIdx.x - NORM_BLKS;
        const int stile = bid & 63;            // 0..63
        const int dtile = (bid >> 6) & 3;      // 0..3
        const int kv    = (bid >> 8) & 3;      // 0..3
        const int b     = bid >> 10;           // 0..1
        const int tx = threadIdx.x & 31;
        const int ty = threadIdx.x >> 5;       // 0..3
#pragma unroll
        for (int i = 0; i < 8; i++) {
            int sl = ty * 8 + i;
            tile[sl][tx] = g_v[(size_t)(b * S_ + stile * 32 + sl) * VN
                               + kv * VD_ + dtile * 32 + tx];
        }
        __syncthreads();
        __half* outbase = g_vT + ((size_t)(b * KV_ + kv) * VD_) * S_;
#pragma unroll
        for (int i = 0; i < 8; i++) {
            int dl = ty * 8 + i;
            outbase[(size_t)(dtile * 32 + dl) * S_ + stile * 32 + tx] =
                __float2half_rn(tile[tx][dl]);
        }
    }
}

// ---------------------------------------------------------------------------
// FP16 tensor-core flash attention — PERSISTENT (152 CTAs, heavy-first).
// Q/K from fp16 gmem (cp.async), V from transposed fp16 gmem, P fp16 smem.
// m16n8k16 MMA throughout; softmax/causal logic identical to tf32 version.
// Strides (words): Q/K 52 (mod32=20 -> conflict-free), V^T/P 36 (mod32=4).
// ---------------------------------------------------------------------------
#define QT128 128
#define KT64  64
#define AQSTR 52
#define AVSTR 36
#define APSTR 36
#define SM_QS   0
#define SM_KF   (128*AQSTR)                 // 6656
#define SM_VF   (SM_KF + 2*64*AQSTR)        // 13312
#define SM_PS   (SM_VF + 2*128*AVSTR)       // 22528
#define ATTN_WORDS (SM_PS + 8*16*APSTR)     // 27136 words = 108544 B
#define N_ITEMS (16 * H_ * B_)              // 512

__global__ void __launch_bounds__(256) attn_tc_kernel()
{
    const int tid = threadIdx.x;
    const int w   = tid >> 5;
    const int lane = tid & 31;
    const int g   = lane >> 2;
    const int t   = lane & 3;
    const int wm  = w * 16;

    unsigned* Qs  = ds_dyn + SM_QS;
    unsigned* Psw = ds_dyn + SM_PS + w * 16 * APSTR;
    unsigned kf_s[2], vf_s[2];
    kf_s[0] = (unsigned)__cvta_generic_to_shared(ds_dyn + SM_KF);
    kf_s[1] = kf_s[0] + 64 * AQSTR * 4;
    vf_s[0] = (unsigned)__cvta_generic_to_shared(ds_dyn + SM_VF);
    vf_s[1] = vf_s[0] + 128 * AVSTR * 4;
    unsigned* Kf[2] = { ds_dyn + SM_KF, ds_dyn + SM_KF + 64 * AQSTR };
    unsigned* Vf[2] = { ds_dyn + SM_VF, ds_dyn + SM_VF + 128 * AVSTR };

    const unsigned qs_s = (unsigned)__cvta_generic_to_shared(Qs);
    __shared__ int s_item;

    for (;;) {
        if (tid == 0) s_item = atomicAdd(&g_ctr, 1);
        __syncthreads();
        const int item = s_item;
        if (item >= N_ITEMS) return;

        const int qt = 15 - (item >> 5);      // heavy-first
        const int hb = item & 31;
        const int h  = hb & 15;
        const int b  = hb >> 4;
        const int kvh = h >> 2;

        const __half* kb0 = g_kh + (size_t)(b * S_) * KN + kvh * KQD_;
        const __half* vT0 = g_vT + ((size_t)(b * KV_ + kvh) * VD_) * S_;

        // Tile 0 K/V + Q, one commit group
        {
            for (int it = tid; it < 64 * 12; it += 256) {
                int r = it / 12, c = it % 12;
                cp_async16(kf_s[0] + (r * AQSTR + c * 4) * 4,
                           kb0 + (size_t)r * KN + c * 8);
            }
            for (int it = tid; it < 128 * 8; it += 256) {
                int d = it >> 3, c = it & 7;
                cp_async16(vf_s[0] + (d * AVSTR + c * 4) * 4,
                           vT0 + (size_t)d * S_ + c * 8);
            }
            const __half* qb0 = g_qh + (size_t)(b * S_ + qt * QT128) * QN + h * KQD_;
            for (int it = tid; it < 128 * 12; it += 256) {
                int r = it / 12, c = it % 12;
                cp_async16(qs_s + (r * AQSTR + c * 4) * 4,
                           qb0 + (size_t)r * QN + c * 8);
            }
            CP_COMMIT();
        }

        float o[16][4];
#pragma unroll
        for (int j = 0; j < 16; j++)
#pragma unroll
            for (int r = 0; r < 4; r++) o[j][r] = 0.f;
        float m0 = -INFINITY, m1 = -INFINITY, l0 = 0.f, l1 = 0.f;

        const int row0g = qt * QT128 + wm + g;
        const int row1g = row0g + 8;
        const int kt_max = 2 * qt + 1;

        for (int kt = 0; kt <= kt_max; kt++) {
            const int cur = kt & 1;
            if (kt < kt_max) {
                const int nb = (kt + 1) & 1;
                const __half* kbase = kb0 + (size_t)(kt + 1) * KT64 * KN;
                for (int it = tid; it < 64 * 12; it += 256) {
                    int r = it / 12, c = it % 12;
                    cp_async16(kf_s[nb] + (r * AQSTR + c * 4) * 4,
                               kbase + (size_t)r * KN + c * 8);
                }
                const __half* vbase = vT0 + (size_t)(kt + 1) * KT64;
                for (int it = tid; it < 128 * 8; it += 256) {
                    int d = it >> 3, c = it & 7;
                    cp_async16(vf_s[nb] + (d * AVSTR + c * 4) * 4,
                               vbase + (size_t)d * S_ + c * 8);
                }
            }
            CP_COMMIT();
            CP_WAIT1();
            __syncthreads();

            if (KT64 * kt <= qt * QT128 + wm + 15) {
                const unsigned* Kc = Kf[cur];
                const unsigned* Vc = Vf[cur];

                // S = Q K^T : 16x64 per warp, K-dim 96 = 6 x k16
                float s[8][4];
#pragma unroll
                for (int j = 0; j < 8; j++)
#pragma unroll
                    for (int r = 0; r < 4; r++) s[j][r] = 0.f;
#pragma unroll
                for (int kc = 0; kc < 6; kc++) {
                    const int kw = kc * 8;
                    unsigned af[4];
                    af[0] = Qs[(wm + g    ) * AQSTR + kw + t    ];
                    af[1] = Qs[(wm + g + 8) * AQSTR + kw + t    ];
                    af[2] = Qs[(wm + g    ) * AQSTR + kw + t + 4];
                    af[3] = Qs[(wm + g + 8) * AQSTR + kw + t + 4];
#pragma unroll
                    for (int j = 0; j < 8; j++) {
                        unsigned bf[2];
                        bf[0] = Kc[(8 * j + g) * AQSTR + kw + t    ];
                        bf[1] = Kc[(8 * j + g) * AQSTR + kw + t + 4];
                        mma_f16(s[j], af, bf);
                    }
                }

                if (kt >= 2 * qt) {
#pragma unroll
                    for (int j = 0; j < 8; j++) {
                        int c0 = kt * KT64 + 8 * j + 2 * t;
                        if (c0     > row0g) s[j][0] = -INFINITY;
                        if (c0 + 1 > row0g) s[j][1] = -INFINITY;
                        if (c0     > row1g) s[j][2] = -INFINITY;
                        if (c0 + 1 > row1g) s[j][3] = -INFINITY;
                    }
                }

                float ml0 = -INFINITY, ml1 = -INFINITY;
#pragma unroll
                for (int j = 0; j < 8; j++) {
                    ml0 = fmaxf(ml0, fmaxf(s[j][0], s[j][1]));
                    ml1 = fmaxf(ml1, fmaxf(s[j][2], s[j][3]));
                }
                ml0 = fmaxf(ml0, __shfl_xor_sync(0xffffffffu, ml0, 1));
                ml0 = fmaxf(ml0, __shfl_xor_sync(0xffffffffu, ml0, 2));
                ml1 = fmaxf(ml1, __shfl_xor_sync(0xffffffffu, ml1, 1));
                ml1 = fmaxf(ml1, __shfl_xor_sync(0xffffffffu, ml1, 2));
                float mn0 = fmaxf(m0, ml0), mn1 = fmaxf(m1, ml1);
                float al0 = __expf(m0 - mn0), al1 = __expf(m1 - mn1);
                m0 = mn0; m1 = mn1;
                float sum0 = 0.f, sum1 = 0.f;
#pragma unroll
                for (int j = 0; j < 8; j++) {
                    s[j][0] = __expf(s[j][0] - mn0); sum0 += s[j][0];
                    s[j][1] = __expf(s[j][1] - mn0); sum0 += s[j][1];
                    s[j][2] = __expf(s[j][2] - mn1); sum1 += s[j][2];
                    s[j][3] = __expf(s[j][3] - mn1); sum1 += s[j][3];
                }
                sum0 += __shfl_xor_sync(0xffffffffu, sum0, 1);
                sum0 += __shfl_xor_sync(0xffffffffu, sum0, 2);
                sum1 += __shfl_xor_sync(0xffffffffu, sum1, 1);
                sum1 += __shfl_xor_sync(0xffffffffu, sum1, 2);
                l0 = l0 * al0 + sum0;
                l1 = l1 * al1 + sum1;
#pragma unroll
                for (int j = 0; j < 16; j++) {
                    o[j][0] *= al0; o[j][1] *= al0;
                    o[j][2] *= al1; o[j][3] *= al1;
                }

                // Store P as fp16 pairs (word = halves k=8j+2t, 8j+2t+1)
#pragma unroll
                for (int j = 0; j < 8; j++) {
                    __half2 p0 = __floats2half2_rn(s[j][0], s[j][1]);
                    __half2 p1 = __floats2half2_rn(s[j][2], s[j][3]);
                    Psw[g * APSTR + 4 * j + t]       = *(unsigned*)&p0;
                    Psw[(g + 8) * APSTR + 4 * j + t] = *(unsigned*)&p1;
                }
                __syncwarp();

                // O += P V : 16x128 per warp, K-dim 64 = 4 x k16
#pragma unroll
                for (int kc = 0; kc < 4; kc++) {
                    const int kw = kc * 8;
                    unsigned af[4];
                    af[0] = Psw[(g    ) * APSTR + kw + t    ];
                    af[1] = Psw[(g + 8) * APSTR + kw + t    ];
                    af[2] = Psw[(g    ) * APSTR + kw + t + 4];
                    af[3] = Psw[(g + 8) * APSTR + kw + t + 4];
#pragma unroll
                    for (int jn = 0; jn < 16; jn++) {
                        unsigned bf[2];
                        bf[0] = Vc[(8 * jn + g) * AVSTR + kw + t    ];
                        bf[1] = Vc[(8 * jn + g) * AVSTR + kw + t + 4];
                        mma_f16(o[jn], af, bf);
                    }
                }
            }
            __syncthreads();
        }

        // Epilogue — fp16 ao
        float inv0 = 1.0f / l0, inv1 = 1.0f / l1;
        __half* ob = g_ao + ((size_t)(b * S_)) * ON + h * VD_;
        size_t r0 = (size_t)(qt * QT128 + wm + g);
        size_t r1 = r0 + 8;
#pragma unroll
        for (int jn = 0; jn < 16; jn++) {
            int col = 8 * jn + 2 * t;
            *(__half2*)&ob[r0 * ON + col] =
                __floats2half2_rn(o[jn][0] * inv0, o[jn][1] * inv0);
            *(__half2*)&ob[r1 * ON + col] =
                __floats2half2_rn(o[jn][2] * inv1, o[jn][3] * inv1);
        }

        CP_WAIT0();
        __syncthreads();
    }
}

// ---------------------------------------------------------------------------
extern "C" void kernel_launch(void* const* d_in, const int* in_sizes, int n_in,
                              void* d_out, int out_size)
{
    const float* hidden = (const float*)d_in[0];
    const int*   pos    = (const int*)  d_in[1];
    const float* Wq     = (const float*)d_in[2];
    const float* Wk     = (const float*)d_in[3];
    const float* Wv     = (const float*)d_in[4];
    const float* Wo     = (const float*)d_in[5];
    const float* qw     = (const float*)d_in[6];
    const float* kw     = (const float*)d_in[7];
    float* out = (float*)d_out;

    void *pq, *pk, *pv;
    cudaGetSymbolAddress(&pq, g_q);
    cudaGetSymbolAddress(&pk, g_k);
    cudaGetSymbolAddress(&pv, g_v);
    float* qb = (float*)pq;
    float* kb = (float*)pk;
    float* vb = (float*)pv;

    static double h_invf[48];
    static int init_done = 0;
    if (!init_done) {
        for (int j = 0; j < 48; j++) h_invf[j] = pow(10000.0, -(double)j / 48.0);
        cudaFuncSetAttribute(attn_tc_kernel,
                             cudaFuncAttributeMaxDynamicSharedMemorySize,
                             ATTN_WORDS * 4);
        cudaFuncSetAttribute(sgemm_qkv,
                             cudaFuncAttributeMaxDynamicSharedMemorySize,
                             GEMM_SMEM_BYTES);
        cudaFuncSetAttribute(sgemm_o,
                             cudaFuncAttributeMaxDynamicSharedMemorySize,
                             GEMM_SMEM_BYTES);
        init_done = 1;
    }
    cudaMemcpyToSymbolAsync(g_invf, h_invf, sizeof(h_invf), 0,
                            cudaMemcpyHostToDevice);

    // 1. Prologue: fp16 conversions + RoPE table + counter reset
    prologue_kernel<<<(NPRE + 255) / 256, 256>>>(
        (const float4*)hidden, (const float4*)Wq, (const float4*)Wk,
        (const float4*)Wv, (const float4*)Wo);

    // 2. Fused QKV projection (fp16 MMA)
    sgemm_qkv<<<dim3(19, TOK / 128), 256, GEMM_SMEM_BYTES>>>(qb, kb, vb);

    // 3. RMSNorm+RoPE (fp16 out, Q scale folded) + V transpose (fused)
    norm_vt_kernel<<<NORM_BLKS + VT_BLKS, 128>>>(qb, kb, qw, kw, pos);

    // 4. FP16 persistent flash attention — profiled slot
    attn_tc_kernel<<<152, 256, ATTN_WORDS * 4>>>();

    // 5. Output projection (fp16 MMA)
    sgemm_o<<<dim3(D_ / 128, TOK / 128), 256, GEMM_SMEM_BYTES>>>(out);
}

// round 17
// speedup vs baseline: 4.0904x; 1.1702x over previous
#include <cuda_runtime.h>
#include <cuda_fp16.h>
#include <math.h>

// Problem constants
#define B_   2
#define S_   2048
#define D_   2048
#define H_   16
#define KV_  4
#define KQD_ 96
#define VD_  128
#define TOK  (B_*S_)       // 4096
#define QN   (H_*KQD_)     // 1536
#define KN   (KV_*KQD_)    // 384
#define VN   (KV_*VD_)     // 512
#define ON   (H_*VD_)      // 2048

__device__ float  g_q [TOK * QN];
__device__ float  g_k [TOK * KN];
__device__ float  g_v [TOK * VN];
__device__ __half g_qh[TOK * QN];
__device__ __half g_kh[TOK * KN];
__device__ __half g_vT[(size_t)B_ * KV_ * VD_ * S_];
__device__ __half g_ao[TOK * ON];
__device__ float  g_cos[S_ * 48];
__device__ float  g_sin[S_ * 48];
__device__ double g_invf[48];
__device__ int    g_ctr;

__device__ __half g_hid[TOK * D_];
__device__ __half g_wq [QN * D_];
__device__ __half g_wk [KN * D_];
__device__ __half g_wv [VN * D_];
__device__ __half g_wo [D_ * ON];

extern __shared__ unsigned ds_dyn[];

// ---------------------------------------------------------------------------
__device__ __forceinline__ void mma_f16(float* c, const unsigned* a, const unsigned* b) {
    asm volatile(
        "mma.sync.aligned.m16n8k16.row.col.f32.f16.f16.f32 "
        "{%0,%1,%2,%3}, {%4,%5,%6,%7}, {%8,%9}, {%0,%1,%2,%3};\n"
        : "+f"(c[0]), "+f"(c[1]), "+f"(c[2]), "+f"(c[3])
        : "r"(a[0]), "r"(a[1]), "r"(a[2]), "r"(a[3]),
          "r"(b[0]), "r"(b[1]));
}
__device__ __forceinline__ void ldsm_x4(unsigned& r0, unsigned& r1,
                                        unsigned& r2, unsigned& r3, unsigned addr) {
    asm volatile("ldmatrix.sync.aligned.m8n8.x4.shared.b16 {%0,%1,%2,%3}, [%4];\n"
        : "=r"(r0), "=r"(r1), "=r"(r2), "=r"(r3) : "r"(addr));
}
__device__ __forceinline__ void cp_async16(unsigned saddr, const void* g) {
    asm volatile("cp.async.cg.shared.global [%0], [%1], 16;\n" :: "r"(saddr), "l"(g));
}
#define CP_COMMIT() asm volatile("cp.async.commit_group;\n" ::: "memory")
#define CP_WAIT0()  asm volatile("cp.async.wait_group 0;\n" ::: "memory")
#define CP_WAIT1()  asm volatile("cp.async.wait_group 1;\n" ::: "memory")
#define CP_WAIT2()  asm volatile("cp.async.wait_group 2;\n" ::: "memory")

// ---------------------------------------------------------------------------
// Merged prologue: fp16 conversion of hid+weights, RoPE table, counter reset
// ---------------------------------------------------------------------------
#define NH4  (TOK * D_ / 4)
#define NW4Q (QN * D_ / 4)
#define NW4K (KN * D_ / 4)
#define NW4V (VN * D_ / 4)
#define NW4O (D_ * ON / 4)
#define NCVT (NH4 + NW4Q + NW4K + NW4V + NW4O)
#define NPRE (NCVT + S_ * 48)

__device__ __forceinline__ void cvt4(__half* dst, const float4* src, int i) {
    float4 v = src[i];
    __half2* d = (__half2*)(dst + i * 4);
    d[0] = __floats2half2_rn(v.x, v.y);
    d[1] = __floats2half2_rn(v.z, v.w);
}

__global__ void prologue_kernel(const float4* __restrict__ hid,
                                const float4* __restrict__ wq,
                                const float4* __restrict__ wk,
                                const float4* __restrict__ wv,
                                const float4* __restrict__ wo)
{
    int i = blockIdx.x * blockDim.x + threadIdx.x;
    if (i == 0) g_ctr = 0;
    if (i >= NPRE) return;
    if (i < NH4) { cvt4(g_hid, hid, i); return; }
    int j = i - NH4;
    if (j < NW4Q) { cvt4(g_wq, wq, j); return; }
    j -= NW4Q;
    if (j < NW4K) { cvt4(g_wk, wk, j); return; }
    j -= NW4K;
    if (j < NW4V) { cvt4(g_wv, wv, j); return; }
    j -= NW4V;
    if (j < NW4O) { cvt4(g_wo, wo, j); return; }
    int r0 = i - NCVT;
    int pos = r0 / 48, jf = r0 % 48;
    double d = g_invf[jf];
    float hi = (float)d;
    float lo = (float)(d - (double)hi);
    float fp = (float)pos;
    float p  = fp * hi;
    float e  = fmaf(fp, hi, -p);
    float t2 = fmaf(fp, lo, e);
    const float INV2PI = 0.15915494309189535f;
    const float PIH    = 6.2831854820251465f;
    const float PIL    = -1.7484555314695172e-7f;
    float n = rintf(p * INV2PI);
    float r = fmaf(-n, PIH, p);
    r = fmaf(-n, PIL, r);
    r = r + t2;
    float s, c;
    sincosf(r, &s, &c);
    g_cos[r0] = c;
    g_sin[r0] = s;
}

// ---------------------------------------------------------------------------
// FP16 GEMM-NT core: cp.async 4-stage, BK=32; ldmatrix.x4 fragment loads.
// ---------------------------------------------------------------------------
#define HBK 32
#define HSTR 20
#define HAHALF (128*HSTR)
#define HSTAGE_WORDS (2*HAHALF)
#define HSTAGES 4
#define GEMM_SMEM_BYTES (HSTAGES*HSTAGE_WORDS*4)   // 81920

__device__ __forceinline__ void gemm_h_body(
    const __half* __restrict__ A, const __half* __restrict__ Bm,
    float* __restrict__ C, int N, int K, int bm, int bn)
{
    unsigned* ds = ds_dyn;
    const int tid  = threadIdx.x;
    const int warp = tid >> 5;
    const int lane = tid & 31;
    const int g    = lane >> 2;
    const int t    = lane & 3;
    const int wm   = (warp >> 2) * 64;
    const int wn   = (warp & 3) * 32;

    const int lrow = tid >> 1;
    const int lkh  = (tid & 1) * 16;
    const __half* Ap = A  + (size_t)(bm + lrow) * K + lkh;
    const __half* Bp = Bm + (size_t)(bn + lrow) * K + lkh;

    const unsigned sbase = (unsigned)__cvta_generic_to_shared(ds);
    const unsigned aoff  = (lrow * HSTR + (tid & 1) * 8) * 4;
    const unsigned boff  = (HAHALF + lrow * HSTR + (tid & 1) * 8) * 4;

    // ldmatrix per-lane offsets (bytes, relative to stage base)
    const unsigned a_lds = ((wm + (lane & 15)) * HSTR + (lane >> 4) * 4) * 4;
    const unsigned b_lds = (HAHALF
        + (wn + (lane >> 4) * 8 + (lane & 7)) * HSTR
        + ((lane >> 3) & 1) * 4) * 4;

    float acc[4][4][4];
#pragma unroll
    for (int i = 0; i < 4; i++)
#pragma unroll
        for (int j = 0; j < 4; j++)
#pragma unroll
            for (int r = 0; r < 4; r++) acc[i][j][r] = 0.f;

#pragma unroll
    for (int s = 0; s < HSTAGES - 1; s++) {
        unsigned sb = sbase + s * HSTAGE_WORDS * 4;
        cp_async16(sb + aoff,      Ap + (size_t)s * HBK);
        cp_async16(sb + aoff + 16, Ap + (size_t)s * HBK + 8);
        cp_async16(sb + boff,      Bp + (size_t)s * HBK);
        cp_async16(sb + boff + 16, Bp + (size_t)s * HBK + 8);
        CP_COMMIT();
    }

    const int nst = K / HBK;
    for (int ks = 0; ks < nst; ks++) {
        CP_WAIT2();
        __syncthreads();

        if (ks + HSTAGES - 1 < nst) {
            int slot = (ks + HSTAGES - 1) & 3;
            unsigned sb = sbase + slot * HSTAGE_WORDS * 4;
            const __half* Ap2 = Ap + (size_t)(ks + HSTAGES - 1) * HBK;
            const __half* Bp2 = Bp + (size_t)(ks + HSTAGES - 1) * HBK;
            cp_async16(sb + aoff,      Ap2);
            cp_async16(sb + aoff + 16, Ap2 + 8);
            cp_async16(sb + boff,      Bp2);
            cp_async16(sb + boff + 16, Bp2 + 8);
        }
        CP_COMMIT();

        const unsigned sb = sbase + (ks & 3) * HSTAGE_WORDS * 4;

#pragma unroll
        for (int kh2 = 0; kh2 < 2; kh2++) {
            unsigned af[4][4], bf[4][2];
            const unsigned ak = sb + a_lds + kh2 * 32;
#pragma unroll
            for (int i = 0; i < 4; i++)
                ldsm_x4(af[i][0], af[i][1], af[i][2], af[i][3],
                        ak + i * 16 * HSTR * 4);
            const unsigned bk = sb + b_lds + kh2 * 32;
            ldsm_x4(bf[0][0], bf[0][1], bf[1][0], bf[1][1], bk);
            ldsm_x4(bf[2][0], bf[2][1], bf[3][0], bf[3][1], bk + 16 * HSTR * 4);
#pragma unroll
            for (int i = 0; i < 4; i++)
#pragma unroll
                for (int j = 0; j < 4; j++)
                    mma_f16(acc[i][j], af[i], bf[j]);
        }
    }

#pragma unroll
    for (int i = 0; i < 4; i++) {
#pragma unroll
        for (int j = 0; j < 4; j++) {
            size_t r0 = (size_t)(bm + wm + 16 * i + g);
            size_t col = (size_t)(bn + wn + 8 * j + 2 * t);
            *(float2*)&C[r0 * N + col]       = make_float2(acc[i][j][0], acc[i][j][1]);
            *(float2*)&C[(r0 + 8) * N + col] = make_float2(acc[i][j][2], acc[i][j][3]);
        }
    }
}

// Fused QKV projection: x in [0,19): 12 Q | 3 K | 4 V
__global__ void __launch_bounds__(256, 2) sgemm_qkv(
    float* __restrict__ qb, float* __restrict__ kb, float* __restrict__ vb)
{
    const int bx = blockIdx.x;
    const int bm = blockIdx.y << 7;
    if (bx < 12)      gemm_h_body(g_hid, g_wq, qb, QN, D_, bm, bx << 7);
    else if (bx < 15) gemm_h_body(g_hid, g_wk, kb, KN, D_, bm, (bx - 12) << 7);
    else              gemm_h_body(g_hid, g_wv, vb, VN, D_, bm, (bx - 15) << 7);
}

// O projection
__global__ void __launch_bounds__(256, 2) sgemm_o(float* __restrict__ C)
{
    gemm_h_body(g_ao, g_wo, C, D_, ON, blockIdx.y << 7, blockIdx.x << 7);
}

// ---------------------------------------------------------------------------
// Merged: RMSNorm+RoPE (fp16 out, Q scale folded) + V transpose->fp16
// ---------------------------------------------------------------------------
#define QROWS (TOK * H_)
#define KROWS (TOK * KV_)
#define NORM_BLKS ((QROWS + KROWS) / 4)
#define VT_BLKS   (B_ * KV_ * (VD_/32) * (S_/32))

__global__ void norm_vt_kernel(const float* __restrict__ qb,
                               const float* __restrict__ kb,
                               const float* __restrict__ qw,
                               const float* __restrict__ kw,
                               const int* __restrict__ pos_ids)
{
    if (blockIdx.x < NORM_BLKS) {
        __shared__ float sh[4][96];
        const int wid  = threadIdx.x >> 5;
        const int lane = threadIdx.x & 31;
        const int row  = blockIdx.x * 4 + wid;

        const bool isK = (row >= QROWS);
        const int  r   = isK ? row - QROWS : row;
        const int  token = isK ? (r / KV_) : (r / H_);
        const float* x = (isK ? kb : qb) + (size_t)r * 96;
        const float* w = isK ? kw : qw;
        __half* outp = (isK ? g_kh : g_qh) + (size_t)r * 96;
        const float oscale = isK ? 1.0f : (1.0f / sqrtf(96.0f));

        float v0 = x[lane], v1 = x[lane + 32], v2 = x[lane + 64];
        float ss = v0 * v0 + v1 * v1 + v2 * v2;
#pragma unroll
        for (int o = 16; o; o >>= 1) ss += __shfl_xor_sync(0xffffffffu, ss, o);
        float inv = rsqrtf(ss * (1.0f / 96.0f) + 1e-6f);

        sh[wid][lane]      = v0 * inv * w[lane];
        sh[wid][lane + 32] = v1 * inv * w[lane + 32];
        sh[wid][lane + 64] = v2 * inv * w[lane + 64];
        __syncwarp();

        const int pos = pos_ids[token];
        const float* ct = g_cos + pos * 48;
        const float* st = g_sin + pos * 48;
#pragma unroll
        for (int q3 = 0; q3 < 3; q3++) {
            int d = lane + q3 * 32;
            int f = (d < 48) ? d : d - 48;
            float rh = (d < 48) ? -sh[wid][d + 48] : sh[wid][d - 48];
            float val = sh[wid][d] * ct[f] + rh * st[f];
            outp[d] = __float2half_rn(val * oscale);
        }
    } else {
        __shared__ float tile[32][33];
        int bid = blockIdx.x - NORM_BLKS;
        const int stile = bid & 63;
        const int dtile = (bid >> 6) & 3;
        const int kv    = (bid >> 8) & 3;
        const int b     = bid >> 10;
        const int tx = threadIdx.x & 31;
        const int ty = threadIdx.x >> 5;
#pragma unroll
        for (int i = 0; i < 8; i++) {
            int sl = ty * 8 + i;
            tile[sl][tx] = g_v[(size_t)(b * S_ + stile * 32 + sl) * VN
                               + kv * VD_ + dtile * 32 + tx];
        }
        __syncthreads();
        __half* outbase = g_vT + ((size_t)(b * KV_ + kv) * VD_) * S_;
#pragma unroll
        for (int i = 0; i < 8; i++) {
            int dl = ty * 8 + i;
            outbase[(size_t)(dtile * 32 + dl) * S_ + stile * 32 + tx] =
                __float2half_rn(tile[tx][dl]);
        }
    }
}

// ---------------------------------------------------------------------------
// FP16 persistent flash attention — now 2 CTAs/SM (304 CTAs, 108.5KB smem).
// ---------------------------------------------------------------------------
#define QT128 128
#define KT64  64
#define AQSTR 52
#define AVSTR 36
#define APSTR 36
#define SM_QS   0
#define SM_KF   (128*AQSTR)
#define SM_VF   (SM_KF + 2*64*AQSTR)
#define SM_PS   (SM_VF + 2*128*AVSTR)
#define ATTN_WORDS (SM_PS + 8*16*APSTR)     // 27136 words = 108544 B
#define N_ITEMS (16 * H_ * B_)              // 512

__global__ void __launch_bounds__(256, 2) attn_tc_kernel()
{
    const int tid = threadIdx.x;
    const int w   = tid >> 5;
    const int lane = tid & 31;
    const int g   = lane >> 2;
    const int t   = lane & 3;
    const int wm  = w * 16;

    unsigned* Qs  = ds_dyn + SM_QS;
    unsigned* Psw = ds_dyn + SM_PS + w * 16 * APSTR;
    unsigned kf_s[2], vf_s[2];
    kf_s[0] = (unsigned)__cvta_generic_to_shared(ds_dyn + SM_KF);
    kf_s[1] = kf_s[0] + 64 * AQSTR * 4;
    vf_s[0] = (unsigned)__cvta_generic_to_shared(ds_dyn + SM_VF);
    vf_s[1] = vf_s[0] + 128 * AVSTR * 4;
    unsigned* Kf[2] = { ds_dyn + SM_KF, ds_dyn + SM_KF + 64 * AQSTR };
    unsigned* Vf[2] = { ds_dyn + SM_VF, ds_dyn + SM_VF + 128 * AVSTR };

    const unsigned qs_s = (unsigned)__cvta_generic_to_shared(Qs);
    __shared__ int s_item;

    for (;;) {
        if (tid == 0) s_item = atomicAdd(&g_ctr, 1);
        __syncthreads();
        const int item = s_item;
        if (item >= N_ITEMS) return;

        const int qt = 15 - (item >> 5);
        const int hb = item & 31;
        const int h  = hb & 15;
        const int b  = hb >> 4;
        const int kvh = h >> 2;

        const __half* kb0 = g_kh + (size_t)(b * S_) * KN + kvh * KQD_;
        const __half* vT0 = g_vT + ((size_t)(b * KV_ + kvh) * VD_) * S_;

        {
            for (int it = tid; it < 64 * 12; it += 256) {
                int r = it / 12, c = it % 12;
                cp_async16(kf_s[0] + (r * AQSTR + c * 4) * 4,
                           kb0 + (size_t)r * KN + c * 8);
            }
            for (int it = tid; it < 128 * 8; it += 256) {
                int d = it >> 3, c = it & 7;
                cp_async16(vf_s[0] + (d * AVSTR + c * 4) * 4,
                           vT0 + (size_t)d * S_ + c * 8);
            }
            const __half* qb0 = g_qh + (size_t)(b * S_ + qt * QT128) * QN + h * KQD_;
            for (int it = tid; it < 128 * 12; it += 256) {
                int r = it / 12, c = it % 12;
                cp_async16(qs_s + (r * AQSTR + c * 4) * 4,
                           qb0 + (size_t)r * QN + c * 8);
            }
            CP_COMMIT();
        }

        float o[16][4];
#pragma unroll
        for (int j = 0; j < 16; j++)
#pragma unroll
            for (int r = 0; r < 4; r++) o[j][r] = 0.f;
        float m0 = -INFINITY, m1 = -INFINITY, l0 = 0.f, l1 = 0.f;

        const int row0g = qt * QT128 + wm + g;
        const int row1g = row0g + 8;
        const int kt_max = 2 * qt + 1;

        for (int kt = 0; kt <= kt_max; kt++) {
            const int cur = kt & 1;
            if (kt < kt_max) {
                const int nb = (kt + 1) & 1;
                const __half* kbase = kb0 + (size_t)(kt + 1) * KT64 * KN;
                for (int it = tid; it < 64 * 12; it += 256) {
                    int r = it / 12, c = it % 12;
                    cp_async16(kf_s[nb] + (r * AQSTR + c * 4) * 4,
                               kbase + (size_t)r * KN + c * 8);
                }
                const __half* vbase = vT0 + (size_t)(kt + 1) * KT64;
                for (int it = tid; it < 128 * 8; it += 256) {
                    int d = it >> 3, c = it & 7;
                    cp_async16(vf_s[nb] + (d * AVSTR + c * 4) * 4,
                               vbase + (size_t)d * S_ + c * 8);
                }
            }
            CP_COMMIT();
            CP_WAIT1();
            __syncthreads();

            if (KT64 * kt <= qt * QT128 + wm + 15) {
                const unsigned* Kc = Kf[cur];
                const unsigned* Vc = Vf[cur];

                float s[8][4];
#pragma unroll
                for (int j = 0; j < 8; j++)
#pragma unroll
                    for (int r = 0; r < 4; r++) s[j][r] = 0.f;
#pragma unroll
                for (int kc = 0; kc < 6; kc++) {
                    const int kw = kc * 8;
                    unsigned af[4];
                    af[0] = Qs[(wm + g    ) * AQSTR + kw + t    ];
                    af[1] = Qs[(wm + g + 8) * AQSTR + kw + t    ];
                    af[2] = Qs[(wm + g    ) * AQSTR + kw + t + 4];
                    af[3] = Qs[(wm + g + 8) * AQSTR + kw + t + 4];
#pragma unroll
                    for (int j = 0; j < 8; j++) {
                        unsigned bf[2];
                        bf[0] = Kc[(8 * j + g) * AQSTR + kw + t    ];
                        bf[1] = Kc[(8 * j + g) * AQSTR + kw + t + 4];
                        mma_f16(s[j], af, bf);
                    }
                }

                if (kt >= 2 * qt) {
#pragma unroll
                    for (int j = 0; j < 8; j++) {
                        int c0 = kt * KT64 + 8 * j + 2 * t;
                        if (c0     > row0g) s[j][0] = -INFINITY;
                        if (c0 + 1 > row0g) s[j][1] = -INFINITY;
                        if (c0     > row1g) s[j][2] = -INFINITY;
                        if (c0 + 1 > row1g) s[j][3] = -INFINITY;
                    }
                }

                float ml0 = -INFINITY, ml1 = -INFINITY;
#pragma unroll
                for (int j = 0; j < 8; j++) {
                    ml0 = fmaxf(ml0, fmaxf(s[j][0], s[j][1]));
                    ml1 = fmaxf(ml1, fmaxf(s[j][2], s[j][3]));
                }
                ml0 = fmaxf(ml0, __shfl_xor_sync(0xffffffffu, ml0, 1));
                ml0 = fmaxf(ml0, __shfl_xor_sync(0xffffffffu, ml0, 2));
                ml1 = fmaxf(ml1, __shfl_xor_sync(0xffffffffu, ml1, 1));
                ml1 = fmaxf(ml1, __shfl_xor_sync(0xffffffffu, ml1, 2));
                float mn0 = fmaxf(m0, ml0), mn1 = fmaxf(m1, ml1);
                float al0 = __expf(m0 - mn0), al1 = __expf(m1 - mn1);
                m0 = mn0; m1 = mn1;
                float sum0 = 0.f, sum1 = 0.f;
#pragma unroll
                for (int j = 0; j < 8; j++) {
                    s[j][0] = __expf(s[j][0] - mn0); sum0 += s[j][0];
                    s[j][1] = __expf(s[j][1] - mn0); sum0 += s[j][1];
                    s[j][2] = __expf(s[j][2] - mn1); sum1 += s[j][2];
                    s[j][3] = __expf(s[j][3] - mn1); sum1 += s[j][3];
                }
                sum0 += __shfl_xor_sync(0xffffffffu, sum0, 1);
                sum0 += __shfl_xor_sync(0xffffffffu, sum0, 2);
                sum1 += __shfl_xor_sync(0xffffffffu, sum1, 1);
                sum1 += __shfl_xor_sync(0xffffffffu, sum1, 2);
                l0 = l0 * al0 + sum0;
                l1 = l1 * al1 + sum1;
#pragma unroll
                for (int j = 0; j < 16; j++) {
                    o[j][0] *= al0; o[j][1] *= al0;
                    o[j][2] *= al1; o[j][3] *= al1;
                }

#pragma unroll
                for (int j = 0; j < 8; j++) {
                    __half2 p0 = __floats2half2_rn(s[j][0], s[j][1]);
                    __half2 p1 = __floats2half2_rn(s[j][2], s[j][3]);
                    Psw[g * APSTR + 4 * j + t]       = *(unsigned*)&p0;
                    Psw[(g + 8) * APSTR + 4 * j + t] = *(unsigned*)&p1;
                }
                __syncwarp();

#pragma unroll
                for (int kc = 0; kc < 4; kc++) {
                    const int kw = kc * 8;
                    unsigned af[4];
                    af[0] = Psw[(g    ) * APSTR + kw + t    ];
                    af[1] = Psw[(g + 8) * APSTR + kw + t    ];
                    af[2] = Psw[(g    ) * APSTR + kw + t + 4];
                    af[3] = Psw[(g + 8) * APSTR + kw + t + 4];
#pragma unroll
                    for (int jn = 0; jn < 16; jn++) {
                        unsigned bf[2];
                        bf[0] = Vc[(8 * jn + g) * AVSTR + kw + t    ];
                        bf[1] = Vc[(8 * jn + g) * AVSTR + kw + t + 4];
                        mma_f16(o[jn], af, bf);
                    }
                }
            }
            __syncthreads();
        }

        float inv0 = 1.0f / l0, inv1 = 1.0f / l1;
        __half* ob = g_ao + ((size_t)(b * S_)) * ON + h * VD_;
        size_t r0 = (size_t)(qt * QT128 + wm + g);
        size_t r1 = r0 + 8;
#pragma unroll
        for (int jn = 0; jn < 16; jn++) {
            int col = 8 * jn + 2 * t;
            *(__half2*)&ob[r0 * ON + col] =
                __floats2half2_rn(o[jn][0] * inv0, o[jn][1] * inv0);
            *(__half2*)&ob[r1 * ON + col] =
                __floats2half2_rn(o[jn][2] * inv1, o[jn][3] * inv1);
        }

        CP_WAIT0();
        __syncthreads();
    }
}

// ---------------------------------------------------------------------------
extern "C" void kernel_launch(void* const* d_in, const int* in_sizes, int n_in,
                              void* d_out, int out_size)
{
    const float* hidden = (const float*)d_in[0];
    const int*   pos    = (const int*)  d_in[1];
    const float* Wq     = (const float*)d_in[2];
    const float* Wk     = (const float*)d_in[3];
    const float* Wv     = (const float*)d_in[4];
    const float* Wo     = (const float*)d_in[5];
    const float* qw     = (const float*)d_in[6];
    const float* kw     = (const float*)d_in[7];
    float* out = (float*)d_out;

    void *pq, *pk, *pv;
    cudaGetSymbolAddress(&pq, g_q);
    cudaGetSymbolAddress(&pk, g_k);
    cudaGetSymbolAddress(&pv, g_v);
    float* qb = (float*)pq;
    float* kb = (float*)pk;
    float* vb = (float*)pv;

    static double h_invf[48];
    static int init_done = 0;
    if (!init_done) {
        for (int j = 0; j < 48; j++) h_invf[j] = pow(10000.0, -(double)j / 48.0);
        cudaFuncSetAttribute(attn_tc_kernel,
                             cudaFuncAttributeMaxDynamicSharedMemorySize,
                             ATTN_WORDS * 4);
        cudaFuncSetAttribute(sgemm_qkv,
                             cudaFuncAttributeMaxDynamicSharedMemorySize,
                             GEMM_SMEM_BYTES);
        cudaFuncSetAttribute(sgemm_o,
                             cudaFuncAttributeMaxDynamicSharedMemorySize,
                             GEMM_SMEM_BYTES);
        init_done = 1;
    }
    cudaMemcpyToSymbolAsync(g_invf, h_invf, sizeof(h_invf), 0,
                            cudaMemcpyHostToDevice);

    // 1. Prologue
    prologue_kernel<<<(NPRE + 255) / 256, 256>>>(
        (const float4*)hidden, (const float4*)Wq, (const float4*)Wk,
        (const float4*)Wv, (const float4*)Wo);

    // 2. Fused QKV projection (ldmatrix fp16 MMA)
    sgemm_qkv<<<dim3(19, TOK / 128), 256, GEMM_SMEM_BYTES>>>(qb, kb, vb);

    // 3. RMSNorm+RoPE + V transpose
    norm_vt_kernel<<<NORM_BLKS + VT_BLKS, 128>>>(qb, kb, qw, kw, pos);

    // 4. FP16 persistent flash attention, 2 CTAs/SM — profiled slot
    attn_tc_kernel<<<304, 256, ATTN_WORDS * 4>>>();

    // 5. Output projection (ldmatrix fp16 MMA)
    sgemm_o<<<dim3(D_ / 128, TOK / 128), 256, GEMM_SMEM_BYTES>>>(out);
}